// round 2
// baseline (speedup 1.0000x reference)
#include <cuda_runtime.h>
#include <math.h>

#define Ntot 20000
#define IN_  256
#define Hh   128
#define HNh  4
#define Ss   5
#define Bb   1024
#define Mm   16
#define Dd   512
#define LALPHA 0.2f

__device__ __forceinline__ float lrelu(float z) { return z >= 0.f ? z : LALPHA * z; }

// scratch (static device globals; no runtime allocation)
__device__ float g_xsh[Ss * HNh * Bb * Hh];   // [S,HN,B,H]
__device__ float g_wh2[Ss * HNh * Bb * Hh];   // [S,HN,B,H]
__device__ float g_out[Ss * Bb * Dd];         // [S,B,D]  (head-concat, pre-semantic)

// ---------------------------------------------------------------------------
// Kernel 1: per (s,b) target chain: x_sh, qh, h2, wh2
// ---------------------------------------------------------------------------
__global__ __launch_bounds__(256) void k_target(
    const float* __restrict__ x, const int* __restrict__ tgt,
    const float* __restrict__ fc_w, const float* __restrict__ fc_b,
    const float* __restrict__ q_w, const float* __restrict__ q_b,
    const float* __restrict__ a2w, const float* __restrict__ a2b,
    const float* __restrict__ aW)
{
    __shared__ float s_tx[IN_];
    __shared__ float s_xsh[HNh * Hh];
    __shared__ float s_qh[HNh * Hh];
    __shared__ float s_h2[HNh * Hh];

    int sb = blockIdx.x;
    int s = sb / Bb, b = sb - s * Bb;
    int kk = (s >= 2) ? 1 : 0;
    int tid = threadIdx.x;

    int node = tgt[b];
    for (int i = tid; i < IN_; i += 256) s_tx[i] = x[(size_t)node * IN_ + i];
    __syncthreads();

    const float4* tx4 = (const float4*)s_tx;
    // fc -> lrelu -> x_sh
    #pragma unroll
    for (int pp = 0; pp < 2; ++pp) {
        int p = tid + pp * 256;
        int h = p >> 7, o = p & 127;
        int row = (s * HNh + h) * Hh + o;
        float acc = fc_b[row];
        const float4* w4 = (const float4*)(fc_w + (size_t)row * IN_);
        #pragma unroll 4
        for (int i = 0; i < IN_ / 4; ++i) {
            float4 w = w4[i]; float4 a = tx4[i];
            acc += w.x * a.x + w.y * a.y + w.z * a.z + w.w * a.w;
        }
        float v = lrelu(acc);
        s_xsh[p] = v;
        g_xsh[((s * HNh + h) * Bb + b) * Hh + o] = v;
    }
    __syncthreads();
    // qh = x_sh @ q_w^T + q_b   (no activation)
    #pragma unroll
    for (int pp = 0; pp < 2; ++pp) {
        int p = tid + pp * 256;
        int h = p >> 7, o = p & 127;
        int row = (s * HNh + h) * Hh + o;
        float acc = q_b[row];
        const float4* w4 = (const float4*)(q_w + (size_t)row * Hh);
        const float4* a4 = (const float4*)(s_xsh + h * Hh);
        #pragma unroll 4
        for (int j = 0; j < Hh / 4; ++j) {
            float4 w = w4[j]; float4 a = a4[j];
            acc += w.x * a.x + w.y * a.y + w.z * a.z + w.w * a.w;
        }
        s_qh[p] = acc;
    }
    __syncthreads();
    // h2 = lrelu(qh @ a2w^T + a2b)
    #pragma unroll
    for (int pp = 0; pp < 2; ++pp) {
        int p = tid + pp * 256;
        int h = p >> 7, o = p & 127;
        int row = (kk * HNh + h) * Hh + o;
        float acc = a2b[row];
        const float4* w4 = (const float4*)(a2w + (size_t)row * Hh);
        const float4* a4 = (const float4*)(s_qh + h * Hh);
        #pragma unroll 4
        for (int j = 0; j < Hh / 4; ++j) {
            float4 w = w4[j]; float4 a = a4[j];
            acc += w.x * a.x + w.y * a.y + w.z * a.z + w.w * a.w;
        }
        s_h2[p] = lrelu(acc);
    }
    __syncthreads();
    // wh2 = aW @ h2
    #pragma unroll
    for (int pp = 0; pp < 2; ++pp) {
        int p = tid + pp * 256;
        int h = p >> 7, o = p & 127;
        int row = (kk * HNh + h) * Hh + o;
        float acc = 0.f;
        const float4* w4 = (const float4*)(aW + (size_t)row * Hh);
        const float4* a4 = (const float4*)(s_h2 + h * Hh);
        #pragma unroll 4
        for (int j = 0; j < Hh / 4; ++j) {
            float4 w = w4[j]; float4 a = a4[j];
            acc += w.x * a.x + w.y * a.y + w.z * a.z + w.w * a.w;
        }
        g_wh2[((s * HNh + h) * Bb + b) * Hh + o] = acc;
    }
}

// ---------------------------------------------------------------------------
// Kernel 2: per (s,b) neighbor chain (all heads, all M), fused through softmax
// dynamic smem layout (floats):
//   [0)      ny    4096
//   [4096)   feat  8192   feat[(h*16+m)*128+o]
//   [12288)  kh    2048
//   [14336)  vh    2048
//   [16384)  hp    256
//   [16640)  red   64
//   [16704)  att   16
//   [16720)  e     16     -> total 16736 floats = 66944 B
// ---------------------------------------------------------------------------
__global__ __launch_bounds__(256) void k_neigh(
    const float* __restrict__ x, const int* __restrict__ nbr,
    const float* __restrict__ fc_w, const float* __restrict__ fc_b,
    const float* __restrict__ k_w, const float* __restrict__ k_b,
    const float* __restrict__ v_w, const float* __restrict__ v_b,
    const float* __restrict__ a1w, const float* __restrict__ a1b)
{
    extern __shared__ float sm[];
    float* s_ny   = sm;
    float* s_feat = sm + 4096;
    float* s_kh   = sm + 12288;
    float* s_vh   = sm + 14336;
    float* s_hp   = sm + 16384;
    float* s_red  = sm + 16640;
    float* s_att  = sm + 16704;
    float* s_e    = sm + 16720;

    int sb = blockIdx.x;
    int s = sb / Bb, b = sb - s * Bb;
    int kk = (s >= 2) ? 1 : 0;
    int tid = threadIdx.x;

    // gather 16 neighbor rows of x (float4)
    {
        const float4* x4 = (const float4*)x;
        float4* ny4 = (float4*)s_ny;
        for (int idx = tid; idx < Mm * (IN_ / 4); idx += 256) {
            int m = idx >> 6, i = idx & 63;
            int node = nbr[((size_t)s * Bb + b) * Mm + m];
            ny4[m * 64 + i] = x4[(size_t)node * 64 + i];
        }
    }
    __syncthreads();

    // fc for all heads / all m: 16-way m register blocking
    {
        const float4* ny4 = (const float4*)s_ny;
        #pragma unroll
        for (int pp = 0; pp < 2; ++pp) {
            int p = tid + pp * 256;
            int h = p >> 7, o = p & 127;
            int row = (s * HNh + h) * Hh + o;
            float bias = fc_b[row];
            float acc[Mm];
            #pragma unroll
            for (int m = 0; m < Mm; ++m) acc[m] = bias;
            const float4* w4 = (const float4*)(fc_w + (size_t)row * IN_);
            for (int i = 0; i < IN_ / 4; ++i) {
                float4 w = w4[i];
                #pragma unroll
                for (int m = 0; m < Mm; ++m) {
                    float4 a = ny4[m * 64 + i];
                    acc[m] += w.x * a.x + w.y * a.y + w.z * a.z + w.w * a.w;
                }
            }
            #pragma unroll
            for (int m = 0; m < Mm; ++m)
                s_feat[(h * Mm + m) * Hh + o] = lrelu(acc[m]);
        }
    }
    __syncthreads();

    int o    = tid & 127;
    int mh   = tid >> 7;    // m-half: 0 -> m 0..7, 1 -> m 8..15
    int lane = tid & 31;
    int warp = tid >> 5;

    for (int h = 0; h < HNh; ++h) {
        int row = (s * HNh + h) * Hh + o;
        // kh, vh (fused: share feat LDS)
        {
            float ak[8], av[8];
            float kb0 = k_b[row], vb0 = v_b[row];
            #pragma unroll
            for (int mi = 0; mi < 8; ++mi) { ak[mi] = kb0; av[mi] = vb0; }
            const float4* kw4 = (const float4*)(k_w + (size_t)row * Hh);
            const float4* vw4 = (const float4*)(v_w + (size_t)row * Hh);
            const float4* f4  = (const float4*)(s_feat + (h * Mm + mh * 8) * Hh);
            for (int j = 0; j < Hh / 4; ++j) {
                float4 wk = kw4[j], wv = vw4[j];
                #pragma unroll
                for (int mi = 0; mi < 8; ++mi) {
                    float4 a = f4[mi * 32 + j];
                    ak[mi] += wk.x * a.x + wk.y * a.y + wk.z * a.z + wk.w * a.w;
                    av[mi] += wv.x * a.x + wv.y * a.y + wv.z * a.z + wv.w * a.w;
                }
            }
            #pragma unroll
            for (int mi = 0; mi < 8; ++mi) {
                s_kh[(mh * 8 + mi) * Hh + o] = ak[mi];
                s_vh[(mh * 8 + mi) * Hh + o] = av[mi];
            }
        }
        __syncthreads();
        // h1 = lrelu(kh @ a1w^T + a1b); att[m] = sum_o h1[m][o]*wh2[o]
        {
            int arow = (kk * HNh + h) * Hh + o;
            float wh2o = g_wh2[((s * HNh + h) * Bb + b) * Hh + o];
            float bias = a1b[arow];
            float acc[8];
            #pragma unroll
            for (int mi = 0; mi < 8; ++mi) acc[mi] = bias;
            const float4* aw4 = (const float4*)(a1w + (size_t)arow * Hh);
            const float4* k4  = (const float4*)(s_kh + mh * 8 * Hh);
            for (int j = 0; j < Hh / 4; ++j) {
                float4 w = aw4[j];
                #pragma unroll
                for (int mi = 0; mi < 8; ++mi) {
                    float4 a = k4[mi * 32 + j];
                    acc[mi] += w.x * a.x + w.y * a.y + w.z * a.z + w.w * a.w;
                }
            }
            float attc[8];
            #pragma unroll
            for (int mi = 0; mi < 8; ++mi) attc[mi] = lrelu(acc[mi]) * wh2o;
            #pragma unroll
            for (int off = 16; off > 0; off >>= 1) {
                #pragma unroll
                for (int mi = 0; mi < 8; ++mi)
                    attc[mi] += __shfl_down_sync(0xffffffffu, attc[mi], off);
            }
            if (lane == 0) {
                #pragma unroll
                for (int mi = 0; mi < 8; ++mi)
                    s_red[(mh * 8 + mi) * 4 + (warp & 3)] = attc[mi];
            }
        }
        __syncthreads();
        if (tid < Mm)
            s_att[tid] = s_red[tid * 4] + s_red[tid * 4 + 1] + s_red[tid * 4 + 2] + s_red[tid * 4 + 3];
        __syncthreads();
        if (tid == 0) {
            float mx = s_att[0];
            #pragma unroll
            for (int m = 1; m < Mm; ++m) mx = fmaxf(mx, s_att[m]);
            float ee[Mm];
            float sum = 0.f;
            #pragma unroll
            for (int m = 0; m < Mm; ++m) { ee[m] = expf(s_att[m] - mx); sum += ee[m]; }
            float inv = 1.f / sum;
            #pragma unroll
            for (int m = 0; m < Mm; ++m) s_e[m] = ee[m] * inv;
        }
        __syncthreads();
        // h[o] = sum_m lrelu(vh*e) ; out = (x_sh + h)*0.5 -> g_out[s][b][h*H+o]
        {
            float hp = 0.f;
            #pragma unroll
            for (int mi = 0; mi < 8; ++mi) {
                int m = mh * 8 + mi;
                hp += lrelu(s_vh[m * Hh + o] * s_e[m]);
            }
            s_hp[mh * Hh + o] = hp;
        }
        __syncthreads();
        if (tid < Hh) {
            float hsum = s_hp[tid] + s_hp[Hh + tid];
            float xs = g_xsh[((s * HNh + h) * Bb + b) * Hh + tid];
            g_out[(size_t)(s * Bb + b) * Dd + h * Hh + tid] = 0.5f * (xs + hsum);
        }
        __syncthreads();  // before next head reuses s_kh/s_vh
    }
}

// ---------------------------------------------------------------------------
// Kernel 3: per-b semantic attention (inner per metapath, then between)
// ---------------------------------------------------------------------------
__global__ __launch_bounds__(256) void k_sem(
    const float* __restrict__ ip1w, const float* __restrict__ ip1b,
    const float* __restrict__ ip2w,
    const float* __restrict__ bp1w, const float* __restrict__ bp1b,
    const float* __restrict__ bp2w,
    float* __restrict__ out)
{
    __shared__ float s_z[Dd];
    __shared__ float s_tmp[256];
    __shared__ float s_w[Hh];
    __shared__ float s_mp[2 * Dd];
    __shared__ float s_sc[4];
    __shared__ float s_beta[4];

    int b = blockIdx.x;
    int tid = threadIdx.x;
    int h = tid & 127, half = tid >> 7;

    for (int ki = 0; ki < 2; ++ki) {
        int s0 = (ki == 0) ? 0 : 2;
        int P  = (ki == 0) ? 2 : 3;
        for (int p = 0; p < P; ++p) {
            for (int i = tid; i < Dd; i += 256)
                s_z[i] = g_out[(size_t)((s0 + p) * Bb + b) * Dd + i];
            __syncthreads();
            float acc = 0.f;
            {
                const float4* w4 = (const float4*)(ip1w + (size_t)(ki * Hh + h) * Dd) + half * 64;
                const float4* z4 = (const float4*)s_z + half * 64;
                #pragma unroll 4
                for (int j = 0; j < 64; ++j) {
                    float4 w = w4[j]; float4 a = z4[j];
                    acc += w.x * a.x + w.y * a.y + w.z * a.z + w.w * a.w;
                }
            }
            s_tmp[tid] = acc;
            __syncthreads();
            if (tid < Hh) {
                float wv = tanhf(s_tmp[tid] + s_tmp[tid + 128] + ip1b[ki * Hh + tid]);
                s_w[tid] = wv * ip2w[ki * Hh + tid];
            }
            __syncthreads();
            if (tid < 32) {
                float v = s_w[tid] + s_w[tid + 32] + s_w[tid + 64] + s_w[tid + 96];
                #pragma unroll
                for (int off = 16; off > 0; off >>= 1)
                    v += __shfl_down_sync(0xffffffffu, v, off);
                if (tid == 0) s_sc[p] = v;
            }
            __syncthreads();
        }
        if (tid == 0) {
            float mx = s_sc[0];
            for (int p = 1; p < P; ++p) mx = fmaxf(mx, s_sc[p]);
            float sum = 0.f, ee[4];
            for (int p = 0; p < P; ++p) { ee[p] = expf(s_sc[p] - mx); sum += ee[p]; }
            for (int p = 0; p < P; ++p) s_beta[p] = ee[p] / sum;
        }
        __syncthreads();
        for (int d = tid; d < Dd; d += 256) {
            float a = 0.f;
            for (int p = 0; p < P; ++p)
                a += s_beta[p] * g_out[(size_t)((s0 + p) * Bb + b) * Dd + d];
            s_mp[ki * Dd + d] = a;
        }
        __syncthreads();
    }

    // between-metapath attention over K=2 rows of s_mp
    for (int k2 = 0; k2 < 2; ++k2) {
        float acc = 0.f;
        {
            const float4* w4 = (const float4*)(bp1w + (size_t)h * Dd) + half * 64;
            const float4* z4 = (const float4*)(s_mp + k2 * Dd) + half * 64;
            #pragma unroll 4
            for (int j = 0; j < 64; ++j) {
                float4 w = w4[j]; float4 a = z4[j];
                acc += w.x * a.x + w.y * a.y + w.z * a.z + w.w * a.w;
            }
        }
        s_tmp[tid] = acc;
        __syncthreads();
        if (tid < Hh)
            s_w[tid] = tanhf(s_tmp[tid] + s_tmp[tid + 128] + bp1b[tid]) * bp2w[tid];
        __syncthreads();
        if (tid < 32) {
            float v = s_w[tid] + s_w[tid + 32] + s_w[tid + 64] + s_w[tid + 96];
            #pragma unroll
            for (int off = 16; off > 0; off >>= 1)
                v += __shfl_down_sync(0xffffffffu, v, off);
            if (tid == 0) s_sc[k2] = v;
        }
        __syncthreads();
    }
    if (tid == 0) {
        float mx = fmaxf(s_sc[0], s_sc[1]);
        float e0 = expf(s_sc[0] - mx), e1 = expf(s_sc[1] - mx);
        float inv = 1.f / (e0 + e1);
        s_beta[0] = e0 * inv; s_beta[1] = e1 * inv;
    }
    __syncthreads();
    for (int d = tid; d < Dd; d += 256)
        out[(size_t)b * Dd + d] = s_beta[0] * s_mp[d] + s_beta[1] * s_mp[Dd + d];
}

// ---------------------------------------------------------------------------
extern "C" void kernel_launch(void* const* d_in, const int* in_sizes, int n_in,
                              void* d_out, int out_size)
{
    const float* x    = (const float*)d_in[0];
    const int*   tgt  = (const int*)d_in[1];
    const int*   nbr  = (const int*)d_in[2];
    const float* fc_w = (const float*)d_in[3];
    const float* fc_b = (const float*)d_in[4];
    const float* q_w  = (const float*)d_in[5];
    const float* q_b  = (const float*)d_in[6];
    const float* k_w  = (const float*)d_in[7];
    const float* k_b  = (const float*)d_in[8];
    const float* v_w  = (const float*)d_in[9];
    const float* v_b  = (const float*)d_in[10];
    const float* aW   = (const float*)d_in[11];
    const float* a1w  = (const float*)d_in[12];
    const float* a1b  = (const float*)d_in[13];
    const float* a2w  = (const float*)d_in[14];
    const float* a2b  = (const float*)d_in[15];
    const float* ip1w = (const float*)d_in[16];
    const float* ip1b = (const float*)d_in[17];
    const float* ip2w = (const float*)d_in[18];
    const float* bp1w = (const float*)d_in[19];
    const float* bp1b = (const float*)d_in[20];
    const float* bp2w = (const float*)d_in[21];
    float* out = (float*)d_out;

    (void)in_sizes; (void)n_in; (void)out_size;

    cudaFuncSetAttribute(k_neigh, cudaFuncAttributeMaxDynamicSharedMemorySize, 16736 * 4);

    k_target<<<Ss * Bb, 256>>>(x, tgt, fc_w, fc_b, q_w, q_b, a2w, a2b, aW);
    k_neigh<<<Ss * Bb, 256, 16736 * 4>>>(x, nbr, fc_w, fc_b, k_w, k_b, v_w, v_b, a1w, a1b);
    k_sem<<<Bb, 256>>>(ip1w, ip1b, ip2w, bp1w, bp1b, bp2w, out);
}

// round 3
// speedup vs baseline: 1.4973x; 1.4973x over previous
#include <cuda_runtime.h>
#include <math.h>

#define Ntot 20000
#define IN_  256
#define Hh   128
#define HNh  4
#define Ss   5
#define Bb   1024
#define Mm   16
#define Dd   512
#define RR   16384          // rows per s = B*M
#define LALPHA 0.2f

__device__ __forceinline__ float lrelu(float z) { return z >= 0.f ? z : LALPHA * z; }

// scratch (static device globals; no runtime allocation)
__device__ float g_xsh[Ss * HNh * Bb * Hh];   // [S,HN,B,H]
__device__ float g_wh2[Ss * HNh * Bb * Hh];   // [S,HN,B,H]
__device__ float g_out[Ss * Bb * Dd];         // [S,B,D]
__device__ float g_feat[(size_t)Ss * RR * Dd]; // [S, B*M, HN*H] = lrelu(fc(x[nbr]))

// ---------------------------------------------------------------------------
// Kernel 1: target chain per (s,b): x_sh, qh, h2, wh2   (unchanged, small)
// ---------------------------------------------------------------------------
__global__ __launch_bounds__(256) void k_target(
    const float* __restrict__ x, const int* __restrict__ tgt,
    const float* __restrict__ fc_w, const float* __restrict__ fc_b,
    const float* __restrict__ q_w, const float* __restrict__ q_b,
    const float* __restrict__ a2w, const float* __restrict__ a2b,
    const float* __restrict__ aW)
{
    __shared__ float s_tx[IN_];
    __shared__ float s_xsh[HNh * Hh];
    __shared__ float s_qh[HNh * Hh];
    __shared__ float s_h2[HNh * Hh];

    int sb = blockIdx.x;
    int s = sb / Bb, b = sb - s * Bb;
    int kk = (s >= 2) ? 1 : 0;
    int tid = threadIdx.x;

    int node = tgt[b];
    for (int i = tid; i < IN_; i += 256) s_tx[i] = x[(size_t)node * IN_ + i];
    __syncthreads();

    const float4* tx4 = (const float4*)s_tx;
    #pragma unroll
    for (int pp = 0; pp < 2; ++pp) {
        int p = tid + pp * 256;
        int h = p >> 7, o = p & 127;
        int row = (s * HNh + h) * Hh + o;
        float acc = fc_b[row];
        const float4* w4 = (const float4*)(fc_w + (size_t)row * IN_);
        #pragma unroll 4
        for (int i = 0; i < IN_ / 4; ++i) {
            float4 w = w4[i]; float4 a = tx4[i];
            acc += w.x * a.x + w.y * a.y + w.z * a.z + w.w * a.w;
        }
        float v = lrelu(acc);
        s_xsh[p] = v;
        g_xsh[((s * HNh + h) * Bb + b) * Hh + o] = v;
    }
    __syncthreads();
    #pragma unroll
    for (int pp = 0; pp < 2; ++pp) {
        int p = tid + pp * 256;
        int h = p >> 7, o = p & 127;
        int row = (s * HNh + h) * Hh + o;
        float acc = q_b[row];
        const float4* w4 = (const float4*)(q_w + (size_t)row * Hh);
        const float4* a4 = (const float4*)(s_xsh + h * Hh);
        #pragma unroll 4
        for (int j = 0; j < Hh / 4; ++j) {
            float4 w = w4[j]; float4 a = a4[j];
            acc += w.x * a.x + w.y * a.y + w.z * a.z + w.w * a.w;
        }
        s_qh[p] = acc;
    }
    __syncthreads();
    #pragma unroll
    for (int pp = 0; pp < 2; ++pp) {
        int p = tid + pp * 256;
        int h = p >> 7, o = p & 127;
        int row = (kk * HNh + h) * Hh + o;
        float acc = a2b[row];
        const float4* w4 = (const float4*)(a2w + (size_t)row * Hh);
        const float4* a4 = (const float4*)(s_qh + h * Hh);
        #pragma unroll 4
        for (int j = 0; j < Hh / 4; ++j) {
            float4 w = w4[j]; float4 a = a4[j];
            acc += w.x * a.x + w.y * a.y + w.z * a.z + w.w * a.w;
        }
        s_h2[p] = lrelu(acc);
    }
    __syncthreads();
    #pragma unroll
    for (int pp = 0; pp < 2; ++pp) {
        int p = tid + pp * 256;
        int h = p >> 7, o = p & 127;
        int row = (kk * HNh + h) * Hh + o;
        float acc = 0.f;
        const float4* w4 = (const float4*)(aW + (size_t)row * Hh);
        const float4* a4 = (const float4*)(s_h2 + h * Hh);
        #pragma unroll 4
        for (int j = 0; j < Hh / 4; ++j) {
            float4 w = w4[j]; float4 a = a4[j];
            acc += w.x * a.x + w.y * a.y + w.z * a.z + w.w * a.w;
        }
        g_wh2[((s * HNh + h) * Bb + b) * Hh + o] = acc;
    }
}

// ---------------------------------------------------------------------------
// Kernel 2: feat GEMM. C[s][r][n] = lrelu( x[nbr[s][r]] . fc_w[s][n] + b )
// tile 128x128, 256 threads, 8x8 per thread, BK=16
// ---------------------------------------------------------------------------
#define SA_STR 20
#define SW_STR 132

__global__ __launch_bounds__(256) void k_feat(
    const float* __restrict__ x, const int* __restrict__ nbr,
    const float* __restrict__ fc_w, const float* __restrict__ fc_b)
{
    __shared__ float sA[128 * SA_STR];   // [row][k] row-major chunk
    __shared__ float sW[16 * SW_STR];    // [k][n] transposed chunk
    __shared__ int   sIdx[128];

    int m0 = blockIdx.x * 128;
    int n0 = blockIdx.y * 128;
    int s  = blockIdx.z;
    int tid = threadIdx.x;
    int tx = tid & 15, ty = tid >> 4;

    if (tid < 128) sIdx[tid] = nbr[s * RR + m0 + tid];
    __syncthreads();

    float acc[8][8];
    #pragma unroll
    for (int i = 0; i < 8; ++i)
        #pragma unroll
        for (int j = 0; j < 8; ++j) acc[i][j] = 0.f;

    const float* wbase = fc_w + (size_t)s * 512 * IN_;

    for (int k0 = 0; k0 < IN_; k0 += 16) {
        // stage A (gathered rows, row-major)
        #pragma unroll
        for (int i = 0; i < 2; ++i) {
            int lid = tid + i * 256;
            int row = lid >> 2, kc = (lid & 3) << 2;
            float4 v = *(const float4*)(x + (size_t)sIdx[row] * IN_ + k0 + kc);
            *(float4*)(sA + row * SA_STR + kc) = v;
        }
        // stage W (transposed)
        #pragma unroll
        for (int i = 0; i < 2; ++i) {
            int lid = tid + i * 256;
            int n = lid >> 2, kc = (lid & 3) << 2;
            float4 v = *(const float4*)(wbase + (size_t)(n0 + n) * IN_ + k0 + kc);
            sW[(kc + 0) * SW_STR + n] = v.x;
            sW[(kc + 1) * SW_STR + n] = v.y;
            sW[(kc + 2) * SW_STR + n] = v.z;
            sW[(kc + 3) * SW_STR + n] = v.w;
        }
        __syncthreads();
        #pragma unroll
        for (int kk = 0; kk < 16; ++kk) {
            float a[8], w[8];
            #pragma unroll
            for (int ri = 0; ri < 8; ++ri) a[ri] = sA[(ty * 8 + ri) * SA_STR + kk];
            float4 w0 = *(const float4*)(sW + kk * SW_STR + tx * 8);
            float4 w1 = *(const float4*)(sW + kk * SW_STR + tx * 8 + 4);
            w[0] = w0.x; w[1] = w0.y; w[2] = w0.z; w[3] = w0.w;
            w[4] = w1.x; w[5] = w1.y; w[6] = w1.z; w[7] = w1.w;
            #pragma unroll
            for (int ri = 0; ri < 8; ++ri)
                #pragma unroll
                for (int ci = 0; ci < 8; ++ci)
                    acc[ri][ci] += a[ri] * w[ci];
        }
        __syncthreads();
    }

    // epilogue: bias + lrelu + store
    float bias[8];
    #pragma unroll
    for (int ci = 0; ci < 8; ++ci) bias[ci] = fc_b[s * 512 + n0 + tx * 8 + ci];
    #pragma unroll
    for (int ri = 0; ri < 8; ++ri) {
        int r = m0 + ty * 8 + ri;
        float* dst = g_feat + ((size_t)s * RR + r) * Dd + n0 + tx * 8;
        float4 v0, v1;
        v0.x = lrelu(acc[ri][0] + bias[0]); v0.y = lrelu(acc[ri][1] + bias[1]);
        v0.z = lrelu(acc[ri][2] + bias[2]); v0.w = lrelu(acc[ri][3] + bias[3]);
        v1.x = lrelu(acc[ri][4] + bias[4]); v1.y = lrelu(acc[ri][5] + bias[5]);
        v1.z = lrelu(acc[ri][6] + bias[6]); v1.w = lrelu(acc[ri][7] + bias[7]);
        *(float4*)(dst) = v0;
        *(float4*)(dst + 4) = v1;
    }
}

// ---------------------------------------------------------------------------
// Kernel 3: fused attention per (s,h, 64-row tile)
// 3 chained 64x128x128 GEMMs (kh, vh, h1) + bilinear att + softmax + vsum
// ---------------------------------------------------------------------------
#define T_STR 132
#define SMEM_ATTN_FLOATS (3 * 64 * T_STR + 16 * T_STR + 512 + 64 + 64)

// one GEMM pass: acc[4][8] += sIn(64x128 row-major) @ Wg^T, W streamed via sW
__device__ __forceinline__ void gemm_pass(
    const float* __restrict__ sIn, const float* __restrict__ Wg,
    float* __restrict__ sW, float acc[4][8], int tid, int tx, int ty)
{
    #pragma unroll
    for (int ri = 0; ri < 4; ++ri)
        #pragma unroll
        for (int ci = 0; ci < 8; ++ci) acc[ri][ci] = 0.f;

    for (int k0 = 0; k0 < Hh; k0 += 16) {
        #pragma unroll
        for (int i = 0; i < 2; ++i) {
            int lid = tid + i * 256;
            int n = lid >> 2, kc = (lid & 3) << 2;
            float4 v = *(const float4*)(Wg + (size_t)n * Hh + k0 + kc);
            sW[(kc + 0) * T_STR + n] = v.x;
            sW[(kc + 1) * T_STR + n] = v.y;
            sW[(kc + 2) * T_STR + n] = v.z;
            sW[(kc + 3) * T_STR + n] = v.w;
        }
        __syncthreads();
        #pragma unroll
        for (int kk = 0; kk < 16; ++kk) {
            float a[4], w[8];
            #pragma unroll
            for (int ri = 0; ri < 4; ++ri) a[ri] = sIn[(ty * 4 + ri) * T_STR + k0 + kk];
            float4 w0 = *(const float4*)(sW + kk * T_STR + tx * 8);
            float4 w1 = *(const float4*)(sW + kk * T_STR + tx * 8 + 4);
            w[0] = w0.x; w[1] = w0.y; w[2] = w0.z; w[3] = w0.w;
            w[4] = w1.x; w[5] = w1.y; w[6] = w1.z; w[7] = w1.w;
            #pragma unroll
            for (int ri = 0; ri < 4; ++ri)
                #pragma unroll
                for (int ci = 0; ci < 8; ++ci)
                    acc[ri][ci] += a[ri] * w[ci];
        }
        __syncthreads();
    }
}

__global__ __launch_bounds__(256) void k_attn(
    const float* __restrict__ k_w, const float* __restrict__ k_b,
    const float* __restrict__ v_w, const float* __restrict__ v_b,
    const float* __restrict__ a1w, const float* __restrict__ a1b)
{
    extern __shared__ float sm[];
    float* sF   = sm;                     // 64 x T_STR  (feat tile)
    float* sKH  = sm + 64 * T_STR;        // 64 x T_STR
    float* sVH  = sm + 2 * 64 * T_STR;    // 64 x T_STR
    float* sW   = sm + 3 * 64 * T_STR;    // 16 x T_STR  (weight chunk / att parts)
    float* sW2  = sW + 16 * T_STR;        // 4 x 128 (wh2 for 4 b's)
    float* sAtt = sW2 + 512;              // 64
    float* sE   = sAtt + 64;              // 64

    int sh = blockIdx.y;             // 0..19
    int s = sh >> 2, h = sh & 3;
    int km = (s >= 2) ? 1 : 0;
    int r0 = blockIdx.x * 64;
    int b0 = r0 >> 4;
    int tid = threadIdx.x;
    int tx = tid & 15, ty = tid >> 4;

    // stage feat tile [64 x 128] and wh2 [4 x 128]
    #pragma unroll
    for (int i = 0; i < 8; ++i) {
        int lid = tid + i * 256;
        int row = lid >> 5, c4 = (lid & 31) << 2;
        float4 v = *(const float4*)(g_feat + ((size_t)s * RR + r0 + row) * Dd + h * Hh + c4);
        *(float4*)(sF + row * T_STR + c4) = v;
    }
    #pragma unroll
    for (int i = 0; i < 2; ++i) {
        int lid = tid + i * 256;
        int bg = lid >> 7, o = lid & 127;
        sW2[lid] = g_wh2[((s * HNh + h) * Bb + b0 + bg) * Hh + o];
    }
    __syncthreads();

    float acc[4][8];
    int who = (s * HNh + h) * Hh;         // per-(s,h) weight row base /128
    int aho = (km * HNh + h) * Hh;

    // PASS 1: kh = feat @ k_w^T + k_b  -> sKH (row-major)
    gemm_pass(sF, k_w + (size_t)who * Hh, sW, acc, tid, tx, ty);
    {
        float4 b0v = *(const float4*)(k_b + who + tx * 8);
        float4 b1v = *(const float4*)(k_b + who + tx * 8 + 4);
        float bb[8] = {b0v.x, b0v.y, b0v.z, b0v.w, b1v.x, b1v.y, b1v.z, b1v.w};
        #pragma unroll
        for (int ri = 0; ri < 4; ++ri) {
            float4 v0, v1;
            v0.x = acc[ri][0] + bb[0]; v0.y = acc[ri][1] + bb[1];
            v0.z = acc[ri][2] + bb[2]; v0.w = acc[ri][3] + bb[3];
            v1.x = acc[ri][4] + bb[4]; v1.y = acc[ri][5] + bb[5];
            v1.z = acc[ri][6] + bb[6]; v1.w = acc[ri][7] + bb[7];
            *(float4*)(sKH + (ty * 4 + ri) * T_STR + tx * 8) = v0;
            *(float4*)(sKH + (ty * 4 + ri) * T_STR + tx * 8 + 4) = v1;
        }
    }

    // PASS 2: vh = feat @ v_w^T + v_b -> sVH
    gemm_pass(sF, v_w + (size_t)who * Hh, sW, acc, tid, tx, ty);
    {
        float4 b0v = *(const float4*)(v_b + who + tx * 8);
        float4 b1v = *(const float4*)(v_b + who + tx * 8 + 4);
        float bb[8] = {b0v.x, b0v.y, b0v.z, b0v.w, b1v.x, b1v.y, b1v.z, b1v.w};
        #pragma unroll
        for (int ri = 0; ri < 4; ++ri) {
            float4 v0, v1;
            v0.x = acc[ri][0] + bb[0]; v0.y = acc[ri][1] + bb[1];
            v0.z = acc[ri][2] + bb[2]; v0.w = acc[ri][3] + bb[3];
            v1.x = acc[ri][4] + bb[4]; v1.y = acc[ri][5] + bb[5];
            v1.z = acc[ri][6] + bb[6]; v1.w = acc[ri][7] + bb[7];
            *(float4*)(sVH + (ty * 4 + ri) * T_STR + tx * 8) = v0;
            *(float4*)(sVH + (ty * 4 + ri) * T_STR + tx * 8 + 4) = v1;
        }
    }
    __syncthreads();   // sKH complete before PASS 3 reads it

    // PASS 3: h1 = lrelu(kh @ a1w^T + a1b); att partials vs wh2
    gemm_pass(sKH, a1w + (size_t)aho * Hh, sW, acc, tid, tx, ty);
    float part[4];
    {
        float4 b0v = *(const float4*)(a1b + aho + tx * 8);
        float4 b1v = *(const float4*)(a1b + aho + tx * 8 + 4);
        float bb[8] = {b0v.x, b0v.y, b0v.z, b0v.w, b1v.x, b1v.y, b1v.z, b1v.w};
        int bg = ty >> 2;
        #pragma unroll
        for (int ri = 0; ri < 4; ++ri) {
            float p = 0.f;
            #pragma unroll
            for (int ci = 0; ci < 8; ++ci) {
                float h1 = lrelu(acc[ri][ci] + bb[ci]);
                p += h1 * sW2[bg * 128 + tx * 8 + ci];
            }
            part[ri] = p;
        }
    }
    __syncthreads();   // done reading sW as weights; reuse as att scratch
    float* sPart = sW;  // 64 x 16
    #pragma unroll
    for (int ri = 0; ri < 4; ++ri) sPart[(ty * 4 + ri) * 16 + tx] = part[ri];
    __syncthreads();
    if (tid < 64) {
        float a = 0.f;
        #pragma unroll
        for (int j = 0; j < 16; ++j) a += sPart[tid * 16 + j];
        sAtt[tid] = a;
    }
    __syncthreads();
    if (tid < 4) {
        float mx = -1e30f;
        #pragma unroll
        for (int m = 0; m < Mm; ++m) mx = fmaxf(mx, sAtt[tid * 16 + m]);
        float sum = 0.f, ee[Mm];
        #pragma unroll
        for (int m = 0; m < Mm; ++m) { ee[m] = expf(sAtt[tid * 16 + m] - mx); sum += ee[m]; }
        float inv = 1.f / sum;
        #pragma unroll
        for (int m = 0; m < Mm; ++m) sE[tid * 16 + m] = ee[m] * inv;
    }
    __syncthreads();

    // h = sum_m lrelu(vh * e); out = 0.5*(xsh + h)
    #pragma unroll
    for (int i = 0; i < 2; ++i) {
        int lid = tid + i * 256;
        int bg = lid >> 7, o = lid & 127;
        float hsum = 0.f;
        #pragma unroll
        for (int m = 0; m < Mm; ++m)
            hsum += lrelu(sVH[(bg * 16 + m) * T_STR + o] * sE[bg * 16 + m]);
        float xs = g_xsh[((s * HNh + h) * Bb + b0 + bg) * Hh + o];
        g_out[((size_t)s * Bb + b0 + bg) * Dd + h * Hh + o] = 0.5f * (xs + hsum);
    }
}

// ---------------------------------------------------------------------------
// Kernel 4: per-b semantic attention (unchanged)
// ---------------------------------------------------------------------------
__global__ __launch_bounds__(256) void k_sem(
    const float* __restrict__ ip1w, const float* __restrict__ ip1b,
    const float* __restrict__ ip2w,
    const float* __restrict__ bp1w, const float* __restrict__ bp1b,
    const float* __restrict__ bp2w,
    float* __restrict__ out)
{
    __shared__ float s_z[Dd];
    __shared__ float s_tmp[256];
    __shared__ float s_w[Hh];
    __shared__ float s_mp[2 * Dd];
    __shared__ float s_sc[4];
    __shared__ float s_beta[4];

    int b = blockIdx.x;
    int tid = threadIdx.x;
    int h = tid & 127, half = tid >> 7;

    for (int ki = 0; ki < 2; ++ki) {
        int s0 = (ki == 0) ? 0 : 2;
        int P  = (ki == 0) ? 2 : 3;
        for (int p = 0; p < P; ++p) {
            for (int i = tid; i < Dd; i += 256)
                s_z[i] = g_out[(size_t)((s0 + p) * Bb + b) * Dd + i];
            __syncthreads();
            float acc = 0.f;
            {
                const float4* w4 = (const float4*)(ip1w + (size_t)(ki * Hh + h) * Dd) + half * 64;
                const float4* z4 = (const float4*)s_z + half * 64;
                #pragma unroll 4
                for (int j = 0; j < 64; ++j) {
                    float4 w = w4[j]; float4 a = z4[j];
                    acc += w.x * a.x + w.y * a.y + w.z * a.z + w.w * a.w;
                }
            }
            s_tmp[tid] = acc;
            __syncthreads();
            if (tid < Hh) {
                float wv = tanhf(s_tmp[tid] + s_tmp[tid + 128] + ip1b[ki * Hh + tid]);
                s_w[tid] = wv * ip2w[ki * Hh + tid];
            }
            __syncthreads();
            if (tid < 32) {
                float v = s_w[tid] + s_w[tid + 32] + s_w[tid + 64] + s_w[tid + 96];
                #pragma unroll
                for (int off = 16; off > 0; off >>= 1)
                    v += __shfl_down_sync(0xffffffffu, v, off);
                if (tid == 0) s_sc[p] = v;
            }
            __syncthreads();
        }
        if (tid == 0) {
            float mx = s_sc[0];
            for (int p = 1; p < P; ++p) mx = fmaxf(mx, s_sc[p]);
            float sum = 0.f, ee[4];
            for (int p = 0; p < P; ++p) { ee[p] = expf(s_sc[p] - mx); sum += ee[p]; }
            for (int p = 0; p < P; ++p) s_beta[p] = ee[p] / sum;
        }
        __syncthreads();
        for (int d = tid; d < Dd; d += 256) {
            float a = 0.f;
            for (int p = 0; p < P; ++p)
                a += s_beta[p] * g_out[(size_t)((s0 + p) * Bb + b) * Dd + d];
            s_mp[ki * Dd + d] = a;
        }
        __syncthreads();
    }

    for (int k2 = 0; k2 < 2; ++k2) {
        float acc = 0.f;
        {
            const float4* w4 = (const float4*)(bp1w + (size_t)h * Dd) + half * 64;
            const float4* z4 = (const float4*)(s_mp + k2 * Dd) + half * 64;
            #pragma unroll 4
            for (int j = 0; j < 64; ++j) {
                float4 w = w4[j]; float4 a = z4[j];
                acc += w.x * a.x + w.y * a.y + w.z * a.z + w.w * a.w;
            }
        }
        s_tmp[tid] = acc;
        __syncthreads();
        if (tid < Hh)
            s_w[tid] = tanhf(s_tmp[tid] + s_tmp[tid + 128] + bp1b[tid]) * bp2w[tid];
        __syncthreads();
        if (tid < 32) {
            float v = s_w[tid] + s_w[tid + 32] + s_w[tid + 64] + s_w[tid + 96];
            #pragma unroll
            for (int off = 16; off > 0; off >>= 1)
                v += __shfl_down_sync(0xffffffffu, v, off);
            if (tid == 0) s_sc[k2] = v;
        }
        __syncthreads();
    }
    if (tid == 0) {
        float mx = fmaxf(s_sc[0], s_sc[1]);
        float e0 = expf(s_sc[0] - mx), e1 = expf(s_sc[1] - mx);
        float inv = 1.f / (e0 + e1);
        s_beta[0] = e0 * inv; s_beta[1] = e1 * inv;
    }
    __syncthreads();
    for (int d = tid; d < Dd; d += 256)
        out[(size_t)b * Dd + d] = s_beta[0] * s_mp[d] + s_beta[1] * s_mp[Dd + d];
}

// ---------------------------------------------------------------------------
extern "C" void kernel_launch(void* const* d_in, const int* in_sizes, int n_in,
                              void* d_out, int out_size)
{
    const float* x    = (const float*)d_in[0];
    const int*   tgt  = (const int*)d_in[1];
    const int*   nbr  = (const int*)d_in[2];
    const float* fc_w = (const float*)d_in[3];
    const float* fc_b = (const float*)d_in[4];
    const float* q_w  = (const float*)d_in[5];
    const float* q_b  = (const float*)d_in[6];
    const float* k_w  = (const float*)d_in[7];
    const float* k_b  = (const float*)d_in[8];
    const float* v_w  = (const float*)d_in[9];
    const float* v_b  = (const float*)d_in[10];
    const float* aW   = (const float*)d_in[11];
    const float* a1w  = (const float*)d_in[12];
    const float* a1b  = (const float*)d_in[13];
    const float* a2w  = (const float*)d_in[14];
    const float* a2b  = (const float*)d_in[15];
    const float* ip1w = (const float*)d_in[16];
    const float* ip1b = (const float*)d_in[17];
    const float* ip2w = (const float*)d_in[18];
    const float* bp1w = (const float*)d_in[19];
    const float* bp1b = (const float*)d_in[20];
    const float* bp2w = (const float*)d_in[21];
    float* out = (float*)d_out;

    (void)in_sizes; (void)n_in; (void)out_size;

    static int configured = 0;
    if (!configured) {
        cudaFuncSetAttribute(k_attn, cudaFuncAttributeMaxDynamicSharedMemorySize,
                             SMEM_ATTN_FLOATS * 4);
        configured = 1;
    }

    k_target<<<Ss * Bb, 256>>>(x, tgt, fc_w, fc_b, q_w, q_b, a2w, a2b, aW);
    k_feat<<<dim3(RR / 128, 4, Ss), 256>>>(x, nbr, fc_w, fc_b);
    k_attn<<<dim3(RR / 64, Ss * HNh), 256, SMEM_ATTN_FLOATS * 4>>>(k_w, k_b, v_w, v_b, a1w, a1b);
    k_sem<<<Bb, 256>>>(ip1w, ip1b, ip2w, bp1w, bp1b, bp2w, out);
}

// round 4
// speedup vs baseline: 1.7915x; 1.1965x over previous
#include <cuda_runtime.h>
#include <math.h>

#define Ntot 20000
#define IN_  256
#define Hh   128
#define HNh  4
#define Ss   5
#define Bb   1024
#define Mm   16
#define Dd   512
#define RR   16384
#define LALPHA 0.2f

__device__ __forceinline__ float lrelu(float z) { return z >= 0.f ? z : LALPHA * z; }

// scratch
__device__ float g_xsh[Ss * HNh * Bb * Hh];
__device__ float g_wh2[Ss * HNh * Bb * Hh];
__device__ float g_out[Ss * Bb * Dd];
__device__ float g_feat[(size_t)Ss * RR * Dd];
__device__ float g_mp[Bb * 2 * Dd];
__device__ float g_sc1[Ss * Bb];
__device__ float g_sc2[2 * Bb];

// ---------------------------------------------------------------------------
// Kernel 1: target chain per (s,b)
// ---------------------------------------------------------------------------
__global__ __launch_bounds__(256) void k_target(
    const float* __restrict__ x, const int* __restrict__ tgt,
    const float* __restrict__ fc_w, const float* __restrict__ fc_b,
    const float* __restrict__ q_w, const float* __restrict__ q_b,
    const float* __restrict__ a2w, const float* __restrict__ a2b,
    const float* __restrict__ aW)
{
    __shared__ float s_tx[IN_];
    __shared__ float s_xsh[HNh * Hh];
    __shared__ float s_qh[HNh * Hh];
    __shared__ float s_h2[HNh * Hh];

    int sb = blockIdx.x;
    int s = sb / Bb, b = sb - s * Bb;
    int kk = (s >= 2) ? 1 : 0;
    int tid = threadIdx.x;

    int node = tgt[b];
    for (int i = tid; i < IN_; i += 256) s_tx[i] = x[(size_t)node * IN_ + i];
    __syncthreads();

    const float4* tx4 = (const float4*)s_tx;
    #pragma unroll
    for (int pp = 0; pp < 2; ++pp) {
        int p = tid + pp * 256;
        int h = p >> 7, o = p & 127;
        int row = (s * HNh + h) * Hh + o;
        float acc = fc_b[row];
        const float4* w4 = (const float4*)(fc_w + (size_t)row * IN_);
        #pragma unroll 4
        for (int i = 0; i < IN_ / 4; ++i) {
            float4 w = w4[i]; float4 a = tx4[i];
            acc += w.x * a.x + w.y * a.y + w.z * a.z + w.w * a.w;
        }
        float v = lrelu(acc);
        s_xsh[p] = v;
        g_xsh[((s * HNh + h) * Bb + b) * Hh + o] = v;
    }
    __syncthreads();
    #pragma unroll
    for (int pp = 0; pp < 2; ++pp) {
        int p = tid + pp * 256;
        int h = p >> 7, o = p & 127;
        int row = (s * HNh + h) * Hh + o;
        float acc = q_b[row];
        const float4* w4 = (const float4*)(q_w + (size_t)row * Hh);
        const float4* a4 = (const float4*)(s_xsh + h * Hh);
        #pragma unroll 4
        for (int j = 0; j < Hh / 4; ++j) {
            float4 w = w4[j]; float4 a = a4[j];
            acc += w.x * a.x + w.y * a.y + w.z * a.z + w.w * a.w;
        }
        s_qh[p] = acc;
    }
    __syncthreads();
    #pragma unroll
    for (int pp = 0; pp < 2; ++pp) {
        int p = tid + pp * 256;
        int h = p >> 7, o = p & 127;
        int row = (kk * HNh + h) * Hh + o;
        float acc = a2b[row];
        const float4* w4 = (const float4*)(a2w + (size_t)row * Hh);
        const float4* a4 = (const float4*)(s_qh + h * Hh);
        #pragma unroll 4
        for (int j = 0; j < Hh / 4; ++j) {
            float4 w = w4[j]; float4 a = a4[j];
            acc += w.x * a.x + w.y * a.y + w.z * a.z + w.w * a.w;
        }
        s_h2[p] = lrelu(acc);
    }
    __syncthreads();
    #pragma unroll
    for (int pp = 0; pp < 2; ++pp) {
        int p = tid + pp * 256;
        int h = p >> 7, o = p & 127;
        int row = (kk * HNh + h) * Hh + o;
        float acc = 0.f;
        const float4* w4 = (const float4*)(aW + (size_t)row * Hh);
        const float4* a4 = (const float4*)(s_h2 + h * Hh);
        #pragma unroll 4
        for (int j = 0; j < Hh / 4; ++j) {
            float4 w = w4[j]; float4 a = a4[j];
            acc += w.x * a.x + w.y * a.y + w.z * a.z + w.w * a.w;
        }
        g_wh2[((s * HNh + h) * Bb + b) * Hh + o] = acc;
    }
}

// ---------------------------------------------------------------------------
// Kernel 2: feat GEMM with register-prefetch double buffering
// ---------------------------------------------------------------------------
#define SA_STR 20
#define SW_STR 132

__global__ __launch_bounds__(256, 2) void k_feat(
    const float* __restrict__ x, const int* __restrict__ nbr,
    const float* __restrict__ fc_w, const float* __restrict__ fc_b)
{
    __shared__ float sA[128 * SA_STR];
    __shared__ float sW[16 * SW_STR];
    __shared__ int   sIdx[128];

    int m0 = blockIdx.x * 128;
    int n0 = blockIdx.y * 128;
    int s  = blockIdx.z;
    int tid = threadIdx.x;
    int tx = tid & 15, ty = tid >> 4;

    if (tid < 128) sIdx[tid] = nbr[s * RR + m0 + tid];
    __syncthreads();

    float acc[8][8];
    #pragma unroll
    for (int i = 0; i < 8; ++i)
        #pragma unroll
        for (int j = 0; j < 8; ++j) acc[i][j] = 0.f;

    const float* wbase = fc_w + (size_t)s * 512 * IN_;

    int kcp = (tid & 3) << 2;
    int rA0 = tid >> 2, rA1 = rA0 + 64;        // A rows
    int nA0 = tid >> 2, nA1 = nA0 + 64;        // W rows

    float4 pa0, pa1, pw0, pw1;
    pa0 = *(const float4*)(x + (size_t)sIdx[rA0] * IN_ + kcp);
    pa1 = *(const float4*)(x + (size_t)sIdx[rA1] * IN_ + kcp);
    pw0 = *(const float4*)(wbase + (size_t)(n0 + nA0) * IN_ + kcp);
    pw1 = *(const float4*)(wbase + (size_t)(n0 + nA1) * IN_ + kcp);

    for (int c = 0; c < 16; ++c) {
        __syncthreads();
        *(float4*)(sA + rA0 * SA_STR + kcp) = pa0;
        *(float4*)(sA + rA1 * SA_STR + kcp) = pa1;
        sW[(kcp + 0) * SW_STR + nA0] = pw0.x;
        sW[(kcp + 1) * SW_STR + nA0] = pw0.y;
        sW[(kcp + 2) * SW_STR + nA0] = pw0.z;
        sW[(kcp + 3) * SW_STR + nA0] = pw0.w;
        sW[(kcp + 0) * SW_STR + nA1] = pw1.x;
        sW[(kcp + 1) * SW_STR + nA1] = pw1.y;
        sW[(kcp + 2) * SW_STR + nA1] = pw1.z;
        sW[(kcp + 3) * SW_STR + nA1] = pw1.w;
        __syncthreads();
        if (c < 15) {
            int k0n = (c + 1) * 16 + kcp;
            pa0 = *(const float4*)(x + (size_t)sIdx[rA0] * IN_ + k0n);
            pa1 = *(const float4*)(x + (size_t)sIdx[rA1] * IN_ + k0n);
            pw0 = *(const float4*)(wbase + (size_t)(n0 + nA0) * IN_ + k0n);
            pw1 = *(const float4*)(wbase + (size_t)(n0 + nA1) * IN_ + k0n);
        }
        #pragma unroll
        for (int kk = 0; kk < 16; ++kk) {
            float a[8], w[8];
            #pragma unroll
            for (int ri = 0; ri < 8; ++ri) a[ri] = sA[(ty * 8 + ri) * SA_STR + kk];
            float4 w0 = *(const float4*)(sW + kk * SW_STR + tx * 8);
            float4 w1 = *(const float4*)(sW + kk * SW_STR + tx * 8 + 4);
            w[0] = w0.x; w[1] = w0.y; w[2] = w0.z; w[3] = w0.w;
            w[4] = w1.x; w[5] = w1.y; w[6] = w1.z; w[7] = w1.w;
            #pragma unroll
            for (int ri = 0; ri < 8; ++ri)
                #pragma unroll
                for (int ci = 0; ci < 8; ++ci)
                    acc[ri][ci] += a[ri] * w[ci];
        }
    }

    float bias[8];
    #pragma unroll
    for (int ci = 0; ci < 8; ++ci) bias[ci] = fc_b[s * 512 + n0 + tx * 8 + ci];
    #pragma unroll
    for (int ri = 0; ri < 8; ++ri) {
        int r = m0 + ty * 8 + ri;
        float* dst = g_feat + ((size_t)s * RR + r) * Dd + n0 + tx * 8;
        float4 v0, v1;
        v0.x = lrelu(acc[ri][0] + bias[0]); v0.y = lrelu(acc[ri][1] + bias[1]);
        v0.z = lrelu(acc[ri][2] + bias[2]); v0.w = lrelu(acc[ri][3] + bias[3]);
        v1.x = lrelu(acc[ri][4] + bias[4]); v1.y = lrelu(acc[ri][5] + bias[5]);
        v1.z = lrelu(acc[ri][6] + bias[6]); v1.w = lrelu(acc[ri][7] + bias[7]);
        *(float4*)(dst) = v0;
        *(float4*)(dst + 4) = v1;
    }
}

// ---------------------------------------------------------------------------
// Kernel 3: fused attention. Merged kh+vh pass (vh stays in regs),
// register-prefetched weight chunks, h1+att+softmax+vsum epilogue.
// smem floats: sF 8448 | sKH 8448 | sWk 2112 | sWv 2112 | sW2 512 | sHp 2112
//              sAtt 64 | sE 64  => 23872 floats = 95488 B
// ---------------------------------------------------------------------------
#define T_STR 132
#define SM_ATTN 23872

__global__ __launch_bounds__(256, 2) void k_attn(
    const float* __restrict__ k_w, const float* __restrict__ k_b,
    const float* __restrict__ v_w, const float* __restrict__ v_b,
    const float* __restrict__ a1w, const float* __restrict__ a1b)
{
    extern __shared__ float sm[];
    float* sF   = sm;
    float* sKH  = sm + 8448;
    float* sWk  = sm + 16896;
    float* sWv  = sm + 19008;
    float* sW2  = sm + 21120;
    float* sHp  = sm + 21632;
    float* sAtt = sm + 23744;
    float* sE   = sm + 23808;

    int sh = blockIdx.y;
    int s = sh >> 2, h = sh & 3;
    int km = (s >= 2) ? 1 : 0;
    int r0 = blockIdx.x * 64;
    int b0 = r0 >> 4;
    int tid = threadIdx.x;
    int tx = tid & 15, ty = tid >> 4;

    // stage feat tile + wh2
    #pragma unroll
    for (int i = 0; i < 8; ++i) {
        int lid = tid + i * 256;
        int row = lid >> 5, c4 = (lid & 31) << 2;
        float4 v = *(const float4*)(g_feat + ((size_t)s * RR + r0 + row) * Dd + h * Hh + c4);
        *(float4*)(sF + row * T_STR + c4) = v;
    }
    #pragma unroll
    for (int i = 0; i < 2; ++i) {
        int lid = tid + i * 256;
        int bg = lid >> 7, o = lid & 127;
        sW2[lid] = g_wh2[((s * HNh + h) * Bb + b0 + bg) * Hh + o];
    }

    int who = (s * HNh + h) * Hh;
    int aho = (km * HNh + h) * Hh;
    const float* Wk = k_w + (size_t)who * Hh;
    const float* Wv = v_w + (size_t)who * Hh;
    const float* Wa = a1w + (size_t)aho * Hh;

    int kcp = (tid & 3) << 2;
    int nA = tid >> 2, nB = nA + 64;

    float ak[4][8], av[4][8];
    #pragma unroll
    for (int ri = 0; ri < 4; ++ri)
        #pragma unroll
        for (int ci = 0; ci < 8; ++ci) { ak[ri][ci] = 0.f; av[ri][ci] = 0.f; }

    float4 pk0 = *(const float4*)(Wk + nA * Hh + kcp);
    float4 pk1 = *(const float4*)(Wk + nB * Hh + kcp);
    float4 pv0 = *(const float4*)(Wv + nA * Hh + kcp);
    float4 pv1 = *(const float4*)(Wv + nB * Hh + kcp);

    // PASS A: kh and vh together
    for (int c = 0; c < 8; ++c) {
        __syncthreads();
        sWk[(kcp + 0) * T_STR + nA] = pk0.x; sWk[(kcp + 1) * T_STR + nA] = pk0.y;
        sWk[(kcp + 2) * T_STR + nA] = pk0.z; sWk[(kcp + 3) * T_STR + nA] = pk0.w;
        sWk[(kcp + 0) * T_STR + nB] = pk1.x; sWk[(kcp + 1) * T_STR + nB] = pk1.y;
        sWk[(kcp + 2) * T_STR + nB] = pk1.z; sWk[(kcp + 3) * T_STR + nB] = pk1.w;
        sWv[(kcp + 0) * T_STR + nA] = pv0.x; sWv[(kcp + 1) * T_STR + nA] = pv0.y;
        sWv[(kcp + 2) * T_STR + nA] = pv0.z; sWv[(kcp + 3) * T_STR + nA] = pv0.w;
        sWv[(kcp + 0) * T_STR + nB] = pv1.x; sWv[(kcp + 1) * T_STR + nB] = pv1.y;
        sWv[(kcp + 2) * T_STR + nB] = pv1.z; sWv[(kcp + 3) * T_STR + nB] = pv1.w;
        __syncthreads();
        if (c < 7) {
            int k0n = (c + 1) * 16 + kcp;
            pk0 = *(const float4*)(Wk + nA * Hh + k0n);
            pk1 = *(const float4*)(Wk + nB * Hh + k0n);
            pv0 = *(const float4*)(Wv + nA * Hh + k0n);
            pv1 = *(const float4*)(Wv + nB * Hh + k0n);
        }
        int k0 = c * 16;
        #pragma unroll
        for (int kk = 0; kk < 16; ++kk) {
            float a[4];
            #pragma unroll
            for (int ri = 0; ri < 4; ++ri) a[ri] = sF[(ty * 4 + ri) * T_STR + k0 + kk];
            float4 wk0 = *(const float4*)(sWk + kk * T_STR + tx * 8);
            float4 wk1 = *(const float4*)(sWk + kk * T_STR + tx * 8 + 4);
            float4 wv0 = *(const float4*)(sWv + kk * T_STR + tx * 8);
            float4 wv1 = *(const float4*)(sWv + kk * T_STR + tx * 8 + 4);
            float wkk[8] = {wk0.x, wk0.y, wk0.z, wk0.w, wk1.x, wk1.y, wk1.z, wk1.w};
            float wvv[8] = {wv0.x, wv0.y, wv0.z, wv0.w, wv1.x, wv1.y, wv1.z, wv1.w};
            #pragma unroll
            for (int ri = 0; ri < 4; ++ri)
                #pragma unroll
                for (int ci = 0; ci < 8; ++ci) {
                    ak[ri][ci] += a[ri] * wkk[ci];
                    av[ri][ci] += a[ri] * wvv[ci];
                }
        }
    }

    // epilogue A: kh -> sKH; vh stays in regs (+bias)
    {
        float4 b0v = *(const float4*)(k_b + who + tx * 8);
        float4 b1v = *(const float4*)(k_b + who + tx * 8 + 4);
        float bb[8] = {b0v.x, b0v.y, b0v.z, b0v.w, b1v.x, b1v.y, b1v.z, b1v.w};
        #pragma unroll
        for (int ri = 0; ri < 4; ++ri) {
            float4 v0, v1;
            v0.x = ak[ri][0] + bb[0]; v0.y = ak[ri][1] + bb[1];
            v0.z = ak[ri][2] + bb[2]; v0.w = ak[ri][3] + bb[3];
            v1.x = ak[ri][4] + bb[4]; v1.y = ak[ri][5] + bb[5];
            v1.z = ak[ri][6] + bb[6]; v1.w = ak[ri][7] + bb[7];
            *(float4*)(sKH + (ty * 4 + ri) * T_STR + tx * 8) = v0;
            *(float4*)(sKH + (ty * 4 + ri) * T_STR + tx * 8 + 4) = v1;
        }
        float4 c0v = *(const float4*)(v_b + who + tx * 8);
        float4 c1v = *(const float4*)(v_b + who + tx * 8 + 4);
        float cc[8] = {c0v.x, c0v.y, c0v.z, c0v.w, c1v.x, c1v.y, c1v.z, c1v.w};
        #pragma unroll
        for (int ri = 0; ri < 4; ++ri)
            #pragma unroll
            for (int ci = 0; ci < 8; ++ci) av[ri][ci] += cc[ci];
    }

    // PASS 3: h1 gemm on sKH vs a1w
    float ac3[4][8];
    #pragma unroll
    for (int ri = 0; ri < 4; ++ri)
        #pragma unroll
        for (int ci = 0; ci < 8; ++ci) ac3[ri][ci] = 0.f;

    pk0 = *(const float4*)(Wa + nA * Hh + kcp);
    pk1 = *(const float4*)(Wa + nB * Hh + kcp);
    for (int c = 0; c < 8; ++c) {
        __syncthreads();
        sWk[(kcp + 0) * T_STR + nA] = pk0.x; sWk[(kcp + 1) * T_STR + nA] = pk0.y;
        sWk[(kcp + 2) * T_STR + nA] = pk0.z; sWk[(kcp + 3) * T_STR + nA] = pk0.w;
        sWk[(kcp + 0) * T_STR + nB] = pk1.x; sWk[(kcp + 1) * T_STR + nB] = pk1.y;
        sWk[(kcp + 2) * T_STR + nB] = pk1.z; sWk[(kcp + 3) * T_STR + nB] = pk1.w;
        __syncthreads();
        if (c < 7) {
            int k0n = (c + 1) * 16 + kcp;
            pk0 = *(const float4*)(Wa + nA * Hh + k0n);
            pk1 = *(const float4*)(Wa + nB * Hh + k0n);
        }
        int k0 = c * 16;
        #pragma unroll
        for (int kk = 0; kk < 16; ++kk) {
            float a[4];
            #pragma unroll
            for (int ri = 0; ri < 4; ++ri) a[ri] = sKH[(ty * 4 + ri) * T_STR + k0 + kk];
            float4 w0 = *(const float4*)(sWk + kk * T_STR + tx * 8);
            float4 w1 = *(const float4*)(sWk + kk * T_STR + tx * 8 + 4);
            float ww[8] = {w0.x, w0.y, w0.z, w0.w, w1.x, w1.y, w1.z, w1.w};
            #pragma unroll
            for (int ri = 0; ri < 4; ++ri)
                #pragma unroll
                for (int ci = 0; ci < 8; ++ci)
                    ac3[ri][ci] += a[ri] * ww[ci];
        }
    }

    // att partials
    {
        float4 b0v = *(const float4*)(a1b + aho + tx * 8);
        float4 b1v = *(const float4*)(a1b + aho + tx * 8 + 4);
        float bb[8] = {b0v.x, b0v.y, b0v.z, b0v.w, b1v.x, b1v.y, b1v.z, b1v.w};
        int bg = ty >> 2;
        #pragma unroll
        for (int ri = 0; ri < 4; ++ri) {
            float p = 0.f;
            #pragma unroll
            for (int ci = 0; ci < 8; ++ci) {
                float h1 = lrelu(ac3[ri][ci] + bb[ci]);
                p += h1 * sW2[bg * 128 + tx * 8 + ci];
            }
            sHp[(ty * 4 + ri) * 16 + tx] = p;
        }
    }
    __syncthreads();
    if (tid < 64) {
        float a = 0.f;
        #pragma unroll
        for (int j = 0; j < 16; ++j) a += sHp[tid * 16 + j];
        sAtt[tid] = a;
    }
    __syncthreads();
    if (tid < 4) {
        float mx = -1e30f;
        #pragma unroll
        for (int m = 0; m < Mm; ++m) mx = fmaxf(mx, sAtt[tid * 16 + m]);
        float sum = 0.f, ee[Mm];
        #pragma unroll
        for (int m = 0; m < Mm; ++m) { ee[m] = expf(sAtt[tid * 16 + m] - mx); sum += ee[m]; }
        float inv = 1.f / sum;
        #pragma unroll
        for (int m = 0; m < Mm; ++m) sE[tid * 16 + m] = ee[m] * inv;
    }
    __syncthreads();

    // h partials from register vh
    {
        int bg = ty >> 2;
        float hp[8];
        #pragma unroll
        for (int ci = 0; ci < 8; ++ci) hp[ci] = 0.f;
        #pragma unroll
        for (int ri = 0; ri < 4; ++ri) {
            int m = (ty * 4 + ri) & 15;
            float e = sE[bg * 16 + m];
            #pragma unroll
            for (int ci = 0; ci < 8; ++ci)
                hp[ci] += lrelu(av[ri][ci] * e);
        }
        #pragma unroll
        for (int ci = 0; ci < 8; ++ci)
            sHp[ty * T_STR + tx * 8 + ci] = hp[ci];
    }
    __syncthreads();
    #pragma unroll
    for (int i = 0; i < 2; ++i) {
        int lid = tid + i * 256;
        int bg = lid >> 7, o = lid & 127;
        float hsum = sHp[(bg * 4 + 0) * T_STR + o] + sHp[(bg * 4 + 1) * T_STR + o]
                   + sHp[(bg * 4 + 2) * T_STR + o] + sHp[(bg * 4 + 3) * T_STR + o];
        float xs = g_xsh[((s * HNh + h) * Bb + b0 + bg) * Hh + o];
        g_out[((size_t)s * Bb + b0 + bg) * Dd + h * Hh + o] = 0.5f * (xs + hsum);
    }
}

// ---------------------------------------------------------------------------
// Semantic attention as flat GEMMs
// ---------------------------------------------------------------------------
#define SZ_STR 20

// scores1[s][b] = sum_h tanh(g_out[s][b] . p1w[ki][h] + b1) * p2w[ki][h]
__global__ __launch_bounds__(256) void k_sem_score(
    const float* __restrict__ zbase,   // rows: [(rowsel)*Dd]
    const float* __restrict__ p1w, const float* __restrict__ p1b,
    const float* __restrict__ p2w,
    float* __restrict__ sc,
    int mode)   // 0: inner (grid.y = s), 1: between (grid.y = k2)
{
    __shared__ float sZ[64 * SZ_STR];
    __shared__ float sW[16 * SW_STR];
    __shared__ float sPart[64 * 16];

    int gy = blockIdx.y;
    int b0 = blockIdx.x * 64;
    int tid = threadIdx.x;
    int tx = tid & 15, ty = tid >> 4;

    int wsel, outbase;
    const float* zrow0;
    size_t zstride;
    if (mode == 0) {
        int s = gy;
        wsel = (s >= 2) ? 1 : 0;
        zrow0 = zbase + ((size_t)s * Bb + b0) * Dd;
        zstride = Dd;
        outbase = s * Bb + b0;
    } else {
        int k2 = gy;
        wsel = 0;
        zrow0 = zbase + ((size_t)b0 * 2 + k2) * Dd;
        zstride = 2 * Dd;
        outbase = k2 * Bb + b0;
    }
    const float* Wp = p1w + (size_t)wsel * Hh * Dd;
    const float* bp = p1b + wsel * Hh;
    const float* p2 = p2w + wsel * Hh;

    int kcp = (tid & 3) << 2;
    int rZ = tid >> 2;            // 0..63
    int nA = tid >> 2, nB = nA + 64;

    float acc[4][8];
    #pragma unroll
    for (int ri = 0; ri < 4; ++ri)
        #pragma unroll
        for (int ci = 0; ci < 8; ++ci) acc[ri][ci] = 0.f;

    float4 pz = *(const float4*)(zrow0 + (size_t)rZ * zstride + kcp);
    float4 pw0 = *(const float4*)(Wp + (size_t)nA * Dd + kcp);
    float4 pw1 = *(const float4*)(Wp + (size_t)nB * Dd + kcp);

    for (int c = 0; c < 32; ++c) {
        __syncthreads();
        *(float4*)(sZ + rZ * SZ_STR + kcp) = pz;
        sW[(kcp + 0) * SW_STR + nA] = pw0.x; sW[(kcp + 1) * SW_STR + nA] = pw0.y;
        sW[(kcp + 2) * SW_STR + nA] = pw0.z; sW[(kcp + 3) * SW_STR + nA] = pw0.w;
        sW[(kcp + 0) * SW_STR + nB] = pw1.x; sW[(kcp + 1) * SW_STR + nB] = pw1.y;
        sW[(kcp + 2) * SW_STR + nB] = pw1.z; sW[(kcp + 3) * SW_STR + nB] = pw1.w;
        __syncthreads();
        if (c < 31) {
            int k0n = (c + 1) * 16 + kcp;
            pz = *(const float4*)(zrow0 + (size_t)rZ * zstride + k0n);
            pw0 = *(const float4*)(Wp + (size_t)nA * Dd + k0n);
            pw1 = *(const float4*)(Wp + (size_t)nB * Dd + k0n);
        }
        #pragma unroll
        for (int kk = 0; kk < 16; ++kk) {
            float a[4];
            #pragma unroll
            for (int ri = 0; ri < 4; ++ri) a[ri] = sZ[(ty * 4 + ri) * SZ_STR + kk];
            float4 w0 = *(const float4*)(sW + kk * SW_STR + tx * 8);
            float4 w1 = *(const float4*)(sW + kk * SW_STR + tx * 8 + 4);
            float ww[8] = {w0.x, w0.y, w0.z, w0.w, w1.x, w1.y, w1.z, w1.w};
            #pragma unroll
            for (int ri = 0; ri < 4; ++ri)
                #pragma unroll
                for (int ci = 0; ci < 8; ++ci)
                    acc[ri][ci] += a[ri] * ww[ci];
        }
    }
    // epilogue: tanh + dot with p2w, reduce over cols
    {
        float bb[8], pp[8];
        #pragma unroll
        for (int ci = 0; ci < 8; ++ci) {
            bb[ci] = bp[tx * 8 + ci];
            pp[ci] = p2[tx * 8 + ci];
        }
        #pragma unroll
        for (int ri = 0; ri < 4; ++ri) {
            float p = 0.f;
            #pragma unroll
            for (int ci = 0; ci < 8; ++ci)
                p += tanhf(acc[ri][ci] + bb[ci]) * pp[ci];
            sPart[(ty * 4 + ri) * 16 + tx] = p;
        }
    }
    __syncthreads();
    if (tid < 64) {
        float a = 0.f;
        #pragma unroll
        for (int j = 0; j < 16; ++j) a += sPart[tid * 16 + j];
        sc[outbase + tid] = a;
    }
}

// inner combine: softmax over splits, z2 -> g_mp
__global__ __launch_bounds__(256) void k_sem_comb1()
{
    int b = blockIdx.x;
    int tid = threadIdx.x;
    float s0 = g_sc1[0 * Bb + b], s1 = g_sc1[1 * Bb + b];
    float s2 = g_sc1[2 * Bb + b], s3 = g_sc1[3 * Bb + b], s4 = g_sc1[4 * Bb + b];
    float mx0 = fmaxf(s0, s1);
    float e0 = expf(s0 - mx0), e1 = expf(s1 - mx0);
    float i0 = 1.f / (e0 + e1);
    float b00 = e0 * i0, b01 = e1 * i0;
    float mx1 = fmaxf(fmaxf(s2, s3), s4);
    float f0 = expf(s2 - mx1), f1 = expf(s3 - mx1), f2 = expf(s4 - mx1);
    float i1 = 1.f / (f0 + f1 + f2);
    float b10 = f0 * i1, b11 = f1 * i1, b12 = f2 * i1;
    for (int d = tid; d < Dd; d += 256) {
        float z0 = b00 * g_out[(0 * Bb + b) * Dd + d] + b01 * g_out[(1 * Bb + b) * Dd + d];
        float z1 = b10 * g_out[(2 * Bb + b) * Dd + d] + b11 * g_out[(3 * Bb + b) * Dd + d]
                 + b12 * g_out[(4 * Bb + b) * Dd + d];
        g_mp[(b * 2 + 0) * Dd + d] = z0;
        g_mp[(b * 2 + 1) * Dd + d] = z1;
    }
}

// final combine
__global__ __launch_bounds__(256) void k_sem_comb2(float* __restrict__ out)
{
    int b = blockIdx.x;
    int tid = threadIdx.x;
    float s0 = g_sc2[b], s1 = g_sc2[Bb + b];
    float mx = fmaxf(s0, s1);
    float e0 = expf(s0 - mx), e1 = expf(s1 - mx);
    float inv = 1.f / (e0 + e1);
    float be0 = e0 * inv, be1 = e1 * inv;
    for (int d = tid; d < Dd; d += 256)
        out[(size_t)b * Dd + d] = be0 * g_mp[(b * 2 + 0) * Dd + d]
                                + be1 * g_mp[(b * 2 + 1) * Dd + d];
}

// ---------------------------------------------------------------------------
extern "C" void kernel_launch(void* const* d_in, const int* in_sizes, int n_in,
                              void* d_out, int out_size)
{
    const float* x    = (const float*)d_in[0];
    const int*   tgt  = (const int*)d_in[1];
    const int*   nbr  = (const int*)d_in[2];
    const float* fc_w = (const float*)d_in[3];
    const float* fc_b = (const float*)d_in[4];
    const float* q_w  = (const float*)d_in[5];
    const float* q_b  = (const float*)d_in[6];
    const float* k_w  = (const float*)d_in[7];
    const float* k_b  = (const float*)d_in[8];
    const float* v_w  = (const float*)d_in[9];
    const float* v_b  = (const float*)d_in[10];
    const float* aW   = (const float*)d_in[11];
    const float* a1w  = (const float*)d_in[12];
    const float* a1b  = (const float*)d_in[13];
    const float* a2w  = (const float*)d_in[14];
    const float* a2b  = (const float*)d_in[15];
    const float* ip1w = (const float*)d_in[16];
    const float* ip1b = (const float*)d_in[17];
    const float* ip2w = (const float*)d_in[18];
    const float* bp1w = (const float*)d_in[19];
    const float* bp1b = (const float*)d_in[20];
    const float* bp2w = (const float*)d_in[21];
    float* out = (float*)d_out;

    (void)in_sizes; (void)n_in; (void)out_size;

    static int configured = 0;
    if (!configured) {
        cudaFuncSetAttribute(k_attn, cudaFuncAttributeMaxDynamicSharedMemorySize,
                             SM_ATTN * 4);
        configured = 1;
    }

    float* d_gout;  cudaGetSymbolAddress((void**)&d_gout, g_out);
    float* d_gmp;   cudaGetSymbolAddress((void**)&d_gmp, g_mp);
    float* d_sc1;   cudaGetSymbolAddress((void**)&d_sc1, g_sc1);
    float* d_sc2;   cudaGetSymbolAddress((void**)&d_sc2, g_sc2);

    k_target<<<Ss * Bb, 256>>>(x, tgt, fc_w, fc_b, q_w, q_b, a2w, a2b, aW);
    k_feat<<<dim3(RR / 128, 4, Ss), 256>>>(x, nbr, fc_w, fc_b);
    k_attn<<<dim3(RR / 64, Ss * HNh), 256, SM_ATTN * 4>>>(k_w, k_b, v_w, v_b, a1w, a1b);
    k_sem_score<<<dim3(Bb / 64, Ss), 256>>>(d_gout, ip1w, ip1b, ip2w, d_sc1, 0);
    k_sem_comb1<<<Bb, 256>>>();
    k_sem_score<<<dim3(Bb / 64, 2), 256>>>(d_gmp, bp1w, bp1b, bp2w, d_sc2, 1);
    k_sem_comb2<<<Bb, 256>>>(out);
}

// round 5
// speedup vs baseline: 3.1476x; 1.7570x over previous
#include <cuda_runtime.h>
#include <math.h>

#define Ntot 20000
#define IN_  256
#define Hh   128
#define HNh  4
#define Ss   5
#define Bb   1024
#define Mm   16
#define Dd   512
#define RR   16384
#define RTOT (RR + Bb)      // neighbor rows + target rows
#define LALPHA 0.2f

__device__ __forceinline__ float lrelu(float z) { return z >= 0.f ? z : LALPHA * z; }

// scratch
__device__ float g_xsh[Ss * HNh * Bb * Hh];
__device__ float g_wh2[Ss * HNh * Bb * Hh];
__device__ float g_out[Ss * Bb * Dd];
__device__ float g_feat[(size_t)Ss * RR * Dd];
__device__ float g_mp[Bb * 2 * Dd];
__device__ float g_sc1[Ss * Bb];
__device__ float g_sc2[2 * Bb];

// ---------------------------------------------------------------------------
// Kernel 1: feat GEMM (neighbors + target rows folded in)
// rows 0..16383 -> g_feat ; rows 16384..17407 -> g_xsh
// ---------------------------------------------------------------------------
#define SA_STR 20
#define SW_STR 132

__global__ __launch_bounds__(256, 2) void k_feat(
    const float* __restrict__ x, const int* __restrict__ nbr,
    const int* __restrict__ tgt,
    const float* __restrict__ fc_w, const float* __restrict__ fc_b)
{
    __shared__ float sA[128 * SA_STR];
    __shared__ float sW[16 * SW_STR];
    __shared__ int   sIdx[128];

    int m0 = blockIdx.x * 128;
    int n0 = blockIdx.y * 128;
    int s  = blockIdx.z;
    int tid = threadIdx.x;
    int tx = tid & 15, ty = tid >> 4;

    if (tid < 128) {
        int r = m0 + tid;
        sIdx[tid] = (r < RR) ? nbr[s * RR + r] : tgt[r - RR];
    }
    __syncthreads();

    float acc[8][8];
    #pragma unroll
    for (int i = 0; i < 8; ++i)
        #pragma unroll
        for (int j = 0; j < 8; ++j) acc[i][j] = 0.f;

    const float* wbase = fc_w + (size_t)s * 512 * IN_;

    int kcp = (tid & 3) << 2;
    int rA0 = tid >> 2, rA1 = rA0 + 64;
    int nA0 = tid >> 2, nA1 = nA0 + 64;

    float4 pa0, pa1, pw0, pw1;
    pa0 = *(const float4*)(x + (size_t)sIdx[rA0] * IN_ + kcp);
    pa1 = *(const float4*)(x + (size_t)sIdx[rA1] * IN_ + kcp);
    pw0 = *(const float4*)(wbase + (size_t)(n0 + nA0) * IN_ + kcp);
    pw1 = *(const float4*)(wbase + (size_t)(n0 + nA1) * IN_ + kcp);

    for (int c = 0; c < 16; ++c) {
        __syncthreads();
        *(float4*)(sA + rA0 * SA_STR + kcp) = pa0;
        *(float4*)(sA + rA1 * SA_STR + kcp) = pa1;
        sW[(kcp + 0) * SW_STR + nA0] = pw0.x;
        sW[(kcp + 1) * SW_STR + nA0] = pw0.y;
        sW[(kcp + 2) * SW_STR + nA0] = pw0.z;
        sW[(kcp + 3) * SW_STR + nA0] = pw0.w;
        sW[(kcp + 0) * SW_STR + nA1] = pw1.x;
        sW[(kcp + 1) * SW_STR + nA1] = pw1.y;
        sW[(kcp + 2) * SW_STR + nA1] = pw1.z;
        sW[(kcp + 3) * SW_STR + nA1] = pw1.w;
        __syncthreads();
        if (c < 15) {
            int k0n = (c + 1) * 16 + kcp;
            pa0 = *(const float4*)(x + (size_t)sIdx[rA0] * IN_ + k0n);
            pa1 = *(const float4*)(x + (size_t)sIdx[rA1] * IN_ + k0n);
            pw0 = *(const float4*)(wbase + (size_t)(n0 + nA0) * IN_ + k0n);
            pw1 = *(const float4*)(wbase + (size_t)(n0 + nA1) * IN_ + k0n);
        }
        #pragma unroll
        for (int kk = 0; kk < 16; ++kk) {
            float a[8], w[8];
            #pragma unroll
            for (int ri = 0; ri < 8; ++ri) a[ri] = sA[(ty * 8 + ri) * SA_STR + kk];
            float4 w0 = *(const float4*)(sW + kk * SW_STR + tx * 8);
            float4 w1 = *(const float4*)(sW + kk * SW_STR + tx * 8 + 4);
            w[0] = w0.x; w[1] = w0.y; w[2] = w0.z; w[3] = w0.w;
            w[4] = w1.x; w[5] = w1.y; w[6] = w1.z; w[7] = w1.w;
            #pragma unroll
            for (int ri = 0; ri < 8; ++ri)
                #pragma unroll
                for (int ci = 0; ci < 8; ++ci)
                    acc[ri][ci] += a[ri] * w[ci];
        }
    }

    float bias[8];
    #pragma unroll
    for (int ci = 0; ci < 8; ++ci) bias[ci] = fc_b[s * 512 + n0 + tx * 8 + ci];

    if (m0 < RR) {
        #pragma unroll
        for (int ri = 0; ri < 8; ++ri) {
            int r = m0 + ty * 8 + ri;
            float* dst = g_feat + ((size_t)s * RR + r) * Dd + n0 + tx * 8;
            float4 v0, v1;
            v0.x = lrelu(acc[ri][0] + bias[0]); v0.y = lrelu(acc[ri][1] + bias[1]);
            v0.z = lrelu(acc[ri][2] + bias[2]); v0.w = lrelu(acc[ri][3] + bias[3]);
            v1.x = lrelu(acc[ri][4] + bias[4]); v1.y = lrelu(acc[ri][5] + bias[5]);
            v1.z = lrelu(acc[ri][6] + bias[6]); v1.w = lrelu(acc[ri][7] + bias[7]);
            *(float4*)(dst) = v0;
            *(float4*)(dst + 4) = v1;
        }
    } else {
        int h = n0 >> 7;
        #pragma unroll
        for (int ri = 0; ri < 8; ++ri) {
            int b = m0 - RR + ty * 8 + ri;
            float* dst = g_xsh + ((size_t)(s * HNh + h) * Bb + b) * Hh + tx * 8;
            float4 v0, v1;
            v0.x = lrelu(acc[ri][0] + bias[0]); v0.y = lrelu(acc[ri][1] + bias[1]);
            v0.z = lrelu(acc[ri][2] + bias[2]); v0.w = lrelu(acc[ri][3] + bias[3]);
            v1.x = lrelu(acc[ri][4] + bias[4]); v1.y = lrelu(acc[ri][5] + bias[5]);
            v1.z = lrelu(acc[ri][6] + bias[6]); v1.w = lrelu(acc[ri][7] + bias[7]);
            *(float4*)(dst) = v0;
            *(float4*)(dst + 4) = v1;
        }
    }
}

// ---------------------------------------------------------------------------
// Kernel 2: qkv chain per (s,h, 64-row tile): qh -> h2 -> wh2
// smem floats: sA 8448 | sQ 8448 | sW 2112 = 19008 floats = 76032 B
// ---------------------------------------------------------------------------
#define T_STR 132
#define SM_QKV 19008

__global__ __launch_bounds__(256, 2) void k_qkv(
    const float* __restrict__ q_w, const float* __restrict__ q_b,
    const float* __restrict__ a2w, const float* __restrict__ a2b,
    const float* __restrict__ aW)
{
    extern __shared__ float sm[];
    float* sA = sm;            // xsh tile, later h2 tile
    float* sQ = sm + 8448;     // qh tile
    float* sW = sm + 16896;

    int sh = blockIdx.y;
    int s = sh >> 2, h = sh & 3;
    int km = (s >= 2) ? 1 : 0;
    int b0 = blockIdx.x * 64;
    int tid = threadIdx.x;
    int tx = tid & 15, ty = tid >> 4;

    int who = (s * HNh + h) * Hh;
    int aho = (km * HNh + h) * Hh;
    const float* Wq = q_w + (size_t)who * Hh;
    const float* W2 = a2w + (size_t)aho * Hh;
    const float* Ww = aW + (size_t)aho * Hh;

    // stage xsh tile [64 x 128]
    #pragma unroll
    for (int i = 0; i < 8; ++i) {
        int lid = tid + i * 256;
        int row = lid >> 5, c4 = (lid & 31) << 2;
        float4 v = *(const float4*)(g_xsh + ((size_t)(s * HNh + h) * Bb + b0 + row) * Hh + c4);
        *(float4*)(sA + row * T_STR + c4) = v;
    }

    int kcp = (tid & 3) << 2;
    int nA = tid >> 2, nB = nA + 64;

    float acc[4][8];

    // ---- GEMM1: qh = xsh @ q_w^T + q_b -> sQ ----
    #pragma unroll
    for (int ri = 0; ri < 4; ++ri)
        #pragma unroll
        for (int ci = 0; ci < 8; ++ci) acc[ri][ci] = 0.f;
    float4 p0 = *(const float4*)(Wq + nA * Hh + kcp);
    float4 p1 = *(const float4*)(Wq + nB * Hh + kcp);
    for (int c = 0; c < 8; ++c) {
        __syncthreads();
        sW[(kcp + 0) * T_STR + nA] = p0.x; sW[(kcp + 1) * T_STR + nA] = p0.y;
        sW[(kcp + 2) * T_STR + nA] = p0.z; sW[(kcp + 3) * T_STR + nA] = p0.w;
        sW[(kcp + 0) * T_STR + nB] = p1.x; sW[(kcp + 1) * T_STR + nB] = p1.y;
        sW[(kcp + 2) * T_STR + nB] = p1.z; sW[(kcp + 3) * T_STR + nB] = p1.w;
        __syncthreads();
        if (c < 7) {
            int k0n = (c + 1) * 16 + kcp;
            p0 = *(const float4*)(Wq + nA * Hh + k0n);
            p1 = *(const float4*)(Wq + nB * Hh + k0n);
        }
        int k0 = c * 16;
        #pragma unroll
        for (int kk = 0; kk < 16; ++kk) {
            float a[4];
            #pragma unroll
            for (int ri = 0; ri < 4; ++ri) a[ri] = sA[(ty * 4 + ri) * T_STR + k0 + kk];
            float4 w0 = *(const float4*)(sW + kk * T_STR + tx * 8);
            float4 w1 = *(const float4*)(sW + kk * T_STR + tx * 8 + 4);
            float ww[8] = {w0.x, w0.y, w0.z, w0.w, w1.x, w1.y, w1.z, w1.w};
            #pragma unroll
            for (int ri = 0; ri < 4; ++ri)
                #pragma unroll
                for (int ci = 0; ci < 8; ++ci)
                    acc[ri][ci] += a[ri] * ww[ci];
        }
    }
    {
        float4 b0v = *(const float4*)(q_b + who + tx * 8);
        float4 b1v = *(const float4*)(q_b + who + tx * 8 + 4);
        float bb[8] = {b0v.x, b0v.y, b0v.z, b0v.w, b1v.x, b1v.y, b1v.z, b1v.w};
        #pragma unroll
        for (int ri = 0; ri < 4; ++ri) {
            float4 v0, v1;
            v0.x = acc[ri][0] + bb[0]; v0.y = acc[ri][1] + bb[1];
            v0.z = acc[ri][2] + bb[2]; v0.w = acc[ri][3] + bb[3];
            v1.x = acc[ri][4] + bb[4]; v1.y = acc[ri][5] + bb[5];
            v1.z = acc[ri][6] + bb[6]; v1.w = acc[ri][7] + bb[7];
            *(float4*)(sQ + (ty * 4 + ri) * T_STR + tx * 8) = v0;
            *(float4*)(sQ + (ty * 4 + ri) * T_STR + tx * 8 + 4) = v1;
        }
    }

    // ---- GEMM2: h2 = lrelu(qh @ a2w^T + a2b) -> sA (reuse) ----
    #pragma unroll
    for (int ri = 0; ri < 4; ++ri)
        #pragma unroll
        for (int ci = 0; ci < 8; ++ci) acc[ri][ci] = 0.f;
    p0 = *(const float4*)(W2 + nA * Hh + kcp);
    p1 = *(const float4*)(W2 + nB * Hh + kcp);
    for (int c = 0; c < 8; ++c) {
        __syncthreads();
        sW[(kcp + 0) * T_STR + nA] = p0.x; sW[(kcp + 1) * T_STR + nA] = p0.y;
        sW[(kcp + 2) * T_STR + nA] = p0.z; sW[(kcp + 3) * T_STR + nA] = p0.w;
        sW[(kcp + 0) * T_STR + nB] = p1.x; sW[(kcp + 1) * T_STR + nB] = p1.y;
        sW[(kcp + 2) * T_STR + nB] = p1.z; sW[(kcp + 3) * T_STR + nB] = p1.w;
        __syncthreads();
        if (c < 7) {
            int k0n = (c + 1) * 16 + kcp;
            p0 = *(const float4*)(W2 + nA * Hh + k0n);
            p1 = *(const float4*)(W2 + nB * Hh + k0n);
        }
        int k0 = c * 16;
        #pragma unroll
        for (int kk = 0; kk < 16; ++kk) {
            float a[4];
            #pragma unroll
            for (int ri = 0; ri < 4; ++ri) a[ri] = sQ[(ty * 4 + ri) * T_STR + k0 + kk];
            float4 w0 = *(const float4*)(sW + kk * T_STR + tx * 8);
            float4 w1 = *(const float4*)(sW + kk * T_STR + tx * 8 + 4);
            float ww[8] = {w0.x, w0.y, w0.z, w0.w, w1.x, w1.y, w1.z, w1.w};
            #pragma unroll
            for (int ri = 0; ri < 4; ++ri)
                #pragma unroll
                for (int ci = 0; ci < 8; ++ci)
                    acc[ri][ci] += a[ri] * ww[ci];
        }
    }
    __syncthreads();   // everyone done reading sA(GEMM1 src gone) & writing
    {
        float4 b0v = *(const float4*)(a2b + aho + tx * 8);
        float4 b1v = *(const float4*)(a2b + aho + tx * 8 + 4);
        float bb[8] = {b0v.x, b0v.y, b0v.z, b0v.w, b1v.x, b1v.y, b1v.z, b1v.w};
        #pragma unroll
        for (int ri = 0; ri < 4; ++ri) {
            float4 v0, v1;
            v0.x = lrelu(acc[ri][0] + bb[0]); v0.y = lrelu(acc[ri][1] + bb[1]);
            v0.z = lrelu(acc[ri][2] + bb[2]); v0.w = lrelu(acc[ri][3] + bb[3]);
            v1.x = lrelu(acc[ri][4] + bb[4]); v1.y = lrelu(acc[ri][5] + bb[5]);
            v1.z = lrelu(acc[ri][6] + bb[6]); v1.w = lrelu(acc[ri][7] + bb[7]);
            *(float4*)(sA + (ty * 4 + ri) * T_STR + tx * 8) = v0;
            *(float4*)(sA + (ty * 4 + ri) * T_STR + tx * 8 + 4) = v1;
        }
    }

    // ---- GEMM3: wh2 = h2 @ aW^T -> g_wh2 ----
    #pragma unroll
    for (int ri = 0; ri < 4; ++ri)
        #pragma unroll
        for (int ci = 0; ci < 8; ++ci) acc[ri][ci] = 0.f;
    p0 = *(const float4*)(Ww + nA * Hh + kcp);
    p1 = *(const float4*)(Ww + nB * Hh + kcp);
    for (int c = 0; c < 8; ++c) {
        __syncthreads();
        sW[(kcp + 0) * T_STR + nA] = p0.x; sW[(kcp + 1) * T_STR + nA] = p0.y;
        sW[(kcp + 2) * T_STR + nA] = p0.z; sW[(kcp + 3) * T_STR + nA] = p0.w;
        sW[(kcp + 0) * T_STR + nB] = p1.x; sW[(kcp + 1) * T_STR + nB] = p1.y;
        sW[(kcp + 2) * T_STR + nB] = p1.z; sW[(kcp + 3) * T_STR + nB] = p1.w;
        __syncthreads();
        if (c < 7) {
            int k0n = (c + 1) * 16 + kcp;
            p0 = *(const float4*)(Ww + nA * Hh + k0n);
            p1 = *(const float4*)(Ww + nB * Hh + k0n);
        }
        int k0 = c * 16;
        #pragma unroll
        for (int kk = 0; kk < 16; ++kk) {
            float a[4];
            #pragma unroll
            for (int ri = 0; ri < 4; ++ri) a[ri] = sA[(ty * 4 + ri) * T_STR + k0 + kk];
            float4 w0 = *(const float4*)(sW + kk * T_STR + tx * 8);
            float4 w1 = *(const float4*)(sW + kk * T_STR + tx * 8 + 4);
            float ww[8] = {w0.x, w0.y, w0.z, w0.w, w1.x, w1.y, w1.z, w1.w};
            #pragma unroll
            for (int ri = 0; ri < 4; ++ri)
                #pragma unroll
                for (int ci = 0; ci < 8; ++ci)
                    acc[ri][ci] += a[ri] * ww[ci];
        }
    }
    #pragma unroll
    for (int ri = 0; ri < 4; ++ri) {
        int b = b0 + ty * 4 + ri;
        float* dst = g_wh2 + ((size_t)(s * HNh + h) * Bb + b) * Hh + tx * 8;
        float4 v0, v1;
        v0.x = acc[ri][0]; v0.y = acc[ri][1]; v0.z = acc[ri][2]; v0.w = acc[ri][3];
        v1.x = acc[ri][4]; v1.y = acc[ri][5]; v1.z = acc[ri][6]; v1.w = acc[ri][7];
        *(float4*)(dst) = v0;
        *(float4*)(dst + 4) = v1;
    }
}

// ---------------------------------------------------------------------------
// Kernel 3: fused attention (unchanged from round 4)
// ---------------------------------------------------------------------------
#define SM_ATTN 23872

__global__ __launch_bounds__(256, 2) void k_attn(
    const float* __restrict__ k_w, const float* __restrict__ k_b,
    const float* __restrict__ v_w, const float* __restrict__ v_b,
    const float* __restrict__ a1w, const float* __restrict__ a1b)
{
    extern __shared__ float sm[];
    float* sF   = sm;
    float* sKH  = sm + 8448;
    float* sWk  = sm + 16896;
    float* sWv  = sm + 19008;
    float* sW2  = sm + 21120;
    float* sHp  = sm + 21632;
    float* sAtt = sm + 23744;
    float* sE   = sm + 23808;

    int sh = blockIdx.y;
    int s = sh >> 2, h = sh & 3;
    int km = (s >= 2) ? 1 : 0;
    int r0 = blockIdx.x * 64;
    int b0 = r0 >> 4;
    int tid = threadIdx.x;
    int tx = tid & 15, ty = tid >> 4;

    #pragma unroll
    for (int i = 0; i < 8; ++i) {
        int lid = tid + i * 256;
        int row = lid >> 5, c4 = (lid & 31) << 2;
        float4 v = *(const float4*)(g_feat + ((size_t)s * RR + r0 + row) * Dd + h * Hh + c4);
        *(float4*)(sF + row * T_STR + c4) = v;
    }
    #pragma unroll
    for (int i = 0; i < 2; ++i) {
        int lid = tid + i * 256;
        int bg = lid >> 7, o = lid & 127;
        sW2[lid] = g_wh2[((s * HNh + h) * Bb + b0 + bg) * Hh + o];
    }

    int who = (s * HNh + h) * Hh;
    int aho = (km * HNh + h) * Hh;
    const float* Wk = k_w + (size_t)who * Hh;
    const float* Wv = v_w + (size_t)who * Hh;
    const float* Wa = a1w + (size_t)aho * Hh;

    int kcp = (tid & 3) << 2;
    int nA = tid >> 2, nB = nA + 64;

    float ak[4][8], av[4][8];
    #pragma unroll
    for (int ri = 0; ri < 4; ++ri)
        #pragma unroll
        for (int ci = 0; ci < 8; ++ci) { ak[ri][ci] = 0.f; av[ri][ci] = 0.f; }

    float4 pk0 = *(const float4*)(Wk + nA * Hh + kcp);
    float4 pk1 = *(const float4*)(Wk + nB * Hh + kcp);
    float4 pv0 = *(const float4*)(Wv + nA * Hh + kcp);
    float4 pv1 = *(const float4*)(Wv + nB * Hh + kcp);

    for (int c = 0; c < 8; ++c) {
        __syncthreads();
        sWk[(kcp + 0) * T_STR + nA] = pk0.x; sWk[(kcp + 1) * T_STR + nA] = pk0.y;
        sWk[(kcp + 2) * T_STR + nA] = pk0.z; sWk[(kcp + 3) * T_STR + nA] = pk0.w;
        sWk[(kcp + 0) * T_STR + nB] = pk1.x; sWk[(kcp + 1) * T_STR + nB] = pk1.y;
        sWk[(kcp + 2) * T_STR + nB] = pk1.z; sWk[(kcp + 3) * T_STR + nB] = pk1.w;
        sWv[(kcp + 0) * T_STR + nA] = pv0.x; sWv[(kcp + 1) * T_STR + nA] = pv0.y;
        sWv[(kcp + 2) * T_STR + nA] = pv0.z; sWv[(kcp + 3) * T_STR + nA] = pv0.w;
        sWv[(kcp + 0) * T_STR + nB] = pv1.x; sWv[(kcp + 1) * T_STR + nB] = pv1.y;
        sWv[(kcp + 2) * T_STR + nB] = pv1.z; sWv[(kcp + 3) * T_STR + nB] = pv1.w;
        __syncthreads();
        if (c < 7) {
            int k0n = (c + 1) * 16 + kcp;
            pk0 = *(const float4*)(Wk + nA * Hh + k0n);
            pk1 = *(const float4*)(Wk + nB * Hh + k0n);
            pv0 = *(const float4*)(Wv + nA * Hh + k0n);
            pv1 = *(const float4*)(Wv + nB * Hh + k0n);
        }
        int k0 = c * 16;
        #pragma unroll
        for (int kk = 0; kk < 16; ++kk) {
            float a[4];
            #pragma unroll
            for (int ri = 0; ri < 4; ++ri) a[ri] = sF[(ty * 4 + ri) * T_STR + k0 + kk];
            float4 wk0 = *(const float4*)(sWk + kk * T_STR + tx * 8);
            float4 wk1 = *(const float4*)(sWk + kk * T_STR + tx * 8 + 4);
            float4 wv0 = *(const float4*)(sWv + kk * T_STR + tx * 8);
            float4 wv1 = *(const float4*)(sWv + kk * T_STR + tx * 8 + 4);
            float wkk[8] = {wk0.x, wk0.y, wk0.z, wk0.w, wk1.x, wk1.y, wk1.z, wk1.w};
            float wvv[8] = {wv0.x, wv0.y, wv0.z, wv0.w, wv1.x, wv1.y, wv1.z, wv1.w};
            #pragma unroll
            for (int ri = 0; ri < 4; ++ri)
                #pragma unroll
                for (int ci = 0; ci < 8; ++ci) {
                    ak[ri][ci] += a[ri] * wkk[ci];
                    av[ri][ci] += a[ri] * wvv[ci];
                }
        }
    }

    {
        float4 b0v = *(const float4*)(k_b + who + tx * 8);
        float4 b1v = *(const float4*)(k_b + who + tx * 8 + 4);
        float bb[8] = {b0v.x, b0v.y, b0v.z, b0v.w, b1v.x, b1v.y, b1v.z, b1v.w};
        #pragma unroll
        for (int ri = 0; ri < 4; ++ri) {
            float4 v0, v1;
            v0.x = ak[ri][0] + bb[0]; v0.y = ak[ri][1] + bb[1];
            v0.z = ak[ri][2] + bb[2]; v0.w = ak[ri][3] + bb[3];
            v1.x = ak[ri][4] + bb[4]; v1.y = ak[ri][5] + bb[5];
            v1.z = ak[ri][6] + bb[6]; v1.w = ak[ri][7] + bb[7];
            *(float4*)(sKH + (ty * 4 + ri) * T_STR + tx * 8) = v0;
            *(float4*)(sKH + (ty * 4 + ri) * T_STR + tx * 8 + 4) = v1;
        }
        float4 c0v = *(const float4*)(v_b + who + tx * 8);
        float4 c1v = *(const float4*)(v_b + who + tx * 8 + 4);
        float cc[8] = {c0v.x, c0v.y, c0v.z, c0v.w, c1v.x, c1v.y, c1v.z, c1v.w};
        #pragma unroll
        for (int ri = 0; ri < 4; ++ri)
            #pragma unroll
            for (int ci = 0; ci < 8; ++ci) av[ri][ci] += cc[ci];
    }

    float ac3[4][8];
    #pragma unroll
    for (int ri = 0; ri < 4; ++ri)
        #pragma unroll
        for (int ci = 0; ci < 8; ++ci) ac3[ri][ci] = 0.f;

    pk0 = *(const float4*)(Wa + nA * Hh + kcp);
    pk1 = *(const float4*)(Wa + nB * Hh + kcp);
    for (int c = 0; c < 8; ++c) {
        __syncthreads();
        sWk[(kcp + 0) * T_STR + nA] = pk0.x; sWk[(kcp + 1) * T_STR + nA] = pk0.y;
        sWk[(kcp + 2) * T_STR + nA] = pk0.z; sWk[(kcp + 3) * T_STR + nA] = pk0.w;
        sWk[(kcp + 0) * T_STR + nB] = pk1.x; sWk[(kcp + 1) * T_STR + nB] = pk1.y;
        sWk[(kcp + 2) * T_STR + nB] = pk1.z; sWk[(kcp + 3) * T_STR + nB] = pk1.w;
        __syncthreads();
        if (c < 7) {
            int k0n = (c + 1) * 16 + kcp;
            pk0 = *(const float4*)(Wa + nA * Hh + k0n);
            pk1 = *(const float4*)(Wa + nB * Hh + k0n);
        }
        int k0 = c * 16;
        #pragma unroll
        for (int kk = 0; kk < 16; ++kk) {
            float a[4];
            #pragma unroll
            for (int ri = 0; ri < 4; ++ri) a[ri] = sKH[(ty * 4 + ri) * T_STR + k0 + kk];
            float4 w0 = *(const float4*)(sWk + kk * T_STR + tx * 8);
            float4 w1 = *(const float4*)(sWk + kk * T_STR + tx * 8 + 4);
            float ww[8] = {w0.x, w0.y, w0.z, w0.w, w1.x, w1.y, w1.z, w1.w};
            #pragma unroll
            for (int ri = 0; ri < 4; ++ri)
                #pragma unroll
                for (int ci = 0; ci < 8; ++ci)
                    ac3[ri][ci] += a[ri] * ww[ci];
        }
    }

    {
        float4 b0v = *(const float4*)(a1b + aho + tx * 8);
        float4 b1v = *(const float4*)(a1b + aho + tx * 8 + 4);
        float bb[8] = {b0v.x, b0v.y, b0v.z, b0v.w, b1v.x, b1v.y, b1v.z, b1v.w};
        int bg = ty >> 2;
        #pragma unroll
        for (int ri = 0; ri < 4; ++ri) {
            float p = 0.f;
            #pragma unroll
            for (int ci = 0; ci < 8; ++ci) {
                float h1 = lrelu(ac3[ri][ci] + bb[ci]);
                p += h1 * sW2[bg * 128 + tx * 8 + ci];
            }
            sHp[(ty * 4 + ri) * 16 + tx] = p;
        }
    }
    __syncthreads();
    if (tid < 64) {
        float a = 0.f;
        #pragma unroll
        for (int j = 0; j < 16; ++j) a += sHp[tid * 16 + j];
        sAtt[tid] = a;
    }
    __syncthreads();
    if (tid < 4) {
        float mx = -1e30f;
        #pragma unroll
        for (int m = 0; m < Mm; ++m) mx = fmaxf(mx, sAtt[tid * 16 + m]);
        float sum = 0.f, ee[Mm];
        #pragma unroll
        for (int m = 0; m < Mm; ++m) { ee[m] = expf(sAtt[tid * 16 + m] - mx); sum += ee[m]; }
        float inv = 1.f / sum;
        #pragma unroll
        for (int m = 0; m < Mm; ++m) sE[tid * 16 + m] = ee[m] * inv;
    }
    __syncthreads();

    {
        int bg = ty >> 2;
        float hp[8];
        #pragma unroll
        for (int ci = 0; ci < 8; ++ci) hp[ci] = 0.f;
        #pragma unroll
        for (int ri = 0; ri < 4; ++ri) {
            int m = (ty * 4 + ri) & 15;
            float e = sE[bg * 16 + m];
            #pragma unroll
            for (int ci = 0; ci < 8; ++ci)
                hp[ci] += lrelu(av[ri][ci] * e);
        }
        #pragma unroll
        for (int ci = 0; ci < 8; ++ci)
            sHp[ty * T_STR + tx * 8 + ci] = hp[ci];
    }
    __syncthreads();
    #pragma unroll
    for (int i = 0; i < 2; ++i) {
        int lid = tid + i * 256;
        int bg = lid >> 7, o = lid & 127;
        float hsum = sHp[(bg * 4 + 0) * T_STR + o] + sHp[(bg * 4 + 1) * T_STR + o]
                   + sHp[(bg * 4 + 2) * T_STR + o] + sHp[(bg * 4 + 3) * T_STR + o];
        float xs = g_xsh[((s * HNh + h) * Bb + b0 + bg) * Hh + o];
        g_out[((size_t)s * Bb + b0 + bg) * Dd + h * Hh + o] = 0.5f * (xs + hsum);
    }
}

// ---------------------------------------------------------------------------
// Semantic attention (unchanged)
// ---------------------------------------------------------------------------
#define SZ_STR 20

__global__ __launch_bounds__(256) void k_sem_score(
    const float* __restrict__ zbase,
    const float* __restrict__ p1w, const float* __restrict__ p1b,
    const float* __restrict__ p2w,
    float* __restrict__ sc,
    int mode)
{
    __shared__ float sZ[64 * SZ_STR];
    __shared__ float sW[16 * SW_STR];
    __shared__ float sPart[64 * 16];

    int gy = blockIdx.y;
    int b0 = blockIdx.x * 64;
    int tid = threadIdx.x;
    int tx = tid & 15, ty = tid >> 4;

    int wsel, outbase;
    const float* zrow0;
    size_t zstride;
    if (mode == 0) {
        int s = gy;
        wsel = (s >= 2) ? 1 : 0;
        zrow0 = zbase + ((size_t)s * Bb + b0) * Dd;
        zstride = Dd;
        outbase = s * Bb + b0;
    } else {
        int k2 = gy;
        wsel = 0;
        zrow0 = zbase + ((size_t)b0 * 2 + k2) * Dd;
        zstride = 2 * Dd;
        outbase = k2 * Bb + b0;
    }
    const float* Wp = p1w + (size_t)wsel * Hh * Dd;
    const float* bp = p1b + wsel * Hh;
    const float* p2 = p2w + wsel * Hh;

    int kcp = (tid & 3) << 2;
    int rZ = tid >> 2;
    int nA = tid >> 2, nB = nA + 64;

    float acc[4][8];
    #pragma unroll
    for (int ri = 0; ri < 4; ++ri)
        #pragma unroll
        for (int ci = 0; ci < 8; ++ci) acc[ri][ci] = 0.f;

    float4 pz = *(const float4*)(zrow0 + (size_t)rZ * zstride + kcp);
    float4 pw0 = *(const float4*)(Wp + (size_t)nA * Dd + kcp);
    float4 pw1 = *(const float4*)(Wp + (size_t)nB * Dd + kcp);

    for (int c = 0; c < 32; ++c) {
        __syncthreads();
        *(float4*)(sZ + rZ * SZ_STR + kcp) = pz;
        sW[(kcp + 0) * SW_STR + nA] = pw0.x; sW[(kcp + 1) * SW_STR + nA] = pw0.y;
        sW[(kcp + 2) * SW_STR + nA] = pw0.z; sW[(kcp + 3) * SW_STR + nA] = pw0.w;
        sW[(kcp + 0) * SW_STR + nB] = pw1.x; sW[(kcp + 1) * SW_STR + nB] = pw1.y;
        sW[(kcp + 2) * SW_STR + nB] = pw1.z; sW[(kcp + 3) * SW_STR + nB] = pw1.w;
        __syncthreads();
        if (c < 31) {
            int k0n = (c + 1) * 16 + kcp;
            pz = *(const float4*)(zrow0 + (size_t)rZ * zstride + k0n);
            pw0 = *(const float4*)(Wp + (size_t)nA * Dd + k0n);
            pw1 = *(const float4*)(Wp + (size_t)nB * Dd + k0n);
        }
        #pragma unroll
        for (int kk = 0; kk < 16; ++kk) {
            float a[4];
            #pragma unroll
            for (int ri = 0; ri < 4; ++ri) a[ri] = sZ[(ty * 4 + ri) * SZ_STR + kk];
            float4 w0 = *(const float4*)(sW + kk * SW_STR + tx * 8);
            float4 w1 = *(const float4*)(sW + kk * SW_STR + tx * 8 + 4);
            float ww[8] = {w0.x, w0.y, w0.z, w0.w, w1.x, w1.y, w1.z, w1.w};
            #pragma unroll
            for (int ri = 0; ri < 4; ++ri)
                #pragma unroll
                for (int ci = 0; ci < 8; ++ci)
                    acc[ri][ci] += a[ri] * ww[ci];
        }
    }
    {
        float bb[8], pp[8];
        #pragma unroll
        for (int ci = 0; ci < 8; ++ci) {
            bb[ci] = bp[tx * 8 + ci];
            pp[ci] = p2[tx * 8 + ci];
        }
        #pragma unroll
        for (int ri = 0; ri < 4; ++ri) {
            float p = 0.f;
            #pragma unroll
            for (int ci = 0; ci < 8; ++ci)
                p += tanhf(acc[ri][ci] + bb[ci]) * pp[ci];
            sPart[(ty * 4 + ri) * 16 + tx] = p;
        }
    }
    __syncthreads();
    if (tid < 64) {
        float a = 0.f;
        #pragma unroll
        for (int j = 0; j < 16; ++j) a += sPart[tid * 16 + j];
        sc[outbase + tid] = a;
    }
}

__global__ __launch_bounds__(256) void k_sem_comb1()
{
    int b = blockIdx.x;
    int tid = threadIdx.x;
    float s0 = g_sc1[0 * Bb + b], s1 = g_sc1[1 * Bb + b];
    float s2 = g_sc1[2 * Bb + b], s3 = g_sc1[3 * Bb + b], s4 = g_sc1[4 * Bb + b];
    float mx0 = fmaxf(s0, s1);
    float e0 = expf(s0 - mx0), e1 = expf(s1 - mx0);
    float i0 = 1.f / (e0 + e1);
    float b00 = e0 * i0, b01 = e1 * i0;
    float mx1 = fmaxf(fmaxf(s2, s3), s4);
    float f0 = expf(s2 - mx1), f1 = expf(s3 - mx1), f2 = expf(s4 - mx1);
    float i1 = 1.f / (f0 + f1 + f2);
    float b10 = f0 * i1, b11 = f1 * i1, b12 = f2 * i1;
    for (int d = tid; d < Dd; d += 256) {
        float z0 = b00 * g_out[(0 * Bb + b) * Dd + d] + b01 * g_out[(1 * Bb + b) * Dd + d];
        float z1 = b10 * g_out[(2 * Bb + b) * Dd + d] + b11 * g_out[(3 * Bb + b) * Dd + d]
                 + b12 * g_out[(4 * Bb + b) * Dd + d];
        g_mp[(b * 2 + 0) * Dd + d] = z0;
        g_mp[(b * 2 + 1) * Dd + d] = z1;
    }
}

__global__ __launch_bounds__(256) void k_sem_comb2(float* __restrict__ out)
{
    int b = blockIdx.x;
    int tid = threadIdx.x;
    float s0 = g_sc2[b], s1 = g_sc2[Bb + b];
    float mx = fmaxf(s0, s1);
    float e0 = expf(s0 - mx), e1 = expf(s1 - mx);
    float inv = 1.f / (e0 + e1);
    float be0 = e0 * inv, be1 = e1 * inv;
    for (int d = tid; d < Dd; d += 256)
        out[(size_t)b * Dd + d] = be0 * g_mp[(b * 2 + 0) * Dd + d]
                                + be1 * g_mp[(b * 2 + 1) * Dd + d];
}

// ---------------------------------------------------------------------------
extern "C" void kernel_launch(void* const* d_in, const int* in_sizes, int n_in,
                              void* d_out, int out_size)
{
    const float* x    = (const float*)d_in[0];
    const int*   tgt  = (const int*)d_in[1];
    const int*   nbr  = (const int*)d_in[2];
    const float* fc_w = (const float*)d_in[3];
    const float* fc_b = (const float*)d_in[4];
    const float* q_w  = (const float*)d_in[5];
    const float* q_b  = (const float*)d_in[6];
    const float* k_w  = (const float*)d_in[7];
    const float* k_b  = (const float*)d_in[8];
    const float* v_w  = (const float*)d_in[9];
    const float* v_b  = (const float*)d_in[10];
    const float* aW   = (const float*)d_in[11];
    const float* a1w  = (const float*)d_in[12];
    const float* a1b  = (const float*)d_in[13];
    const float* a2w  = (const float*)d_in[14];
    const float* a2b  = (const float*)d_in[15];
    const float* ip1w = (const float*)d_in[16];
    const float* ip1b = (const float*)d_in[17];
    const float* ip2w = (const float*)d_in[18];
    const float* bp1w = (const float*)d_in[19];
    const float* bp1b = (const float*)d_in[20];
    const float* bp2w = (const float*)d_in[21];
    float* out = (float*)d_out;

    (void)in_sizes; (void)n_in; (void)out_size;

    static int configured = 0;
    if (!configured) {
        cudaFuncSetAttribute(k_attn, cudaFuncAttributeMaxDynamicSharedMemorySize,
                             SM_ATTN * 4);
        cudaFuncSetAttribute(k_qkv, cudaFuncAttributeMaxDynamicSharedMemorySize,
                             SM_QKV * 4);
        configured = 1;
    }

    float* d_gout;  cudaGetSymbolAddress((void**)&d_gout, g_out);
    float* d_gmp;   cudaGetSymbolAddress((void**)&d_gmp, g_mp);
    float* d_sc1;   cudaGetSymbolAddress((void**)&d_sc1, g_sc1);
    float* d_sc2;   cudaGetSymbolAddress((void**)&d_sc2, g_sc2);

    k_feat<<<dim3(RTOT / 128, 4, Ss), 256>>>(x, nbr, tgt, fc_w, fc_b);
    k_qkv<<<dim3(Bb / 64, Ss * HNh), 256, SM_QKV * 4>>>(q_w, q_b, a2w, a2b, aW);
    k_attn<<<dim3(RR / 64, Ss * HNh), 256, SM_ATTN * 4>>>(k_w, k_b, v_w, v_b, a1w, a1b);
    k_sem_score<<<dim3(Bb / 64, Ss), 256>>>(d_gout, ip1w, ip1b, ip2w, d_sc1, 0);
    k_sem_comb1<<<Bb, 256>>>();
    k_sem_score<<<dim3(Bb / 64, 2), 256>>>(d_gmp, bp1w, bp1b, bp2w, d_sc2, 1);
    k_sem_comb2<<<Bb, 256>>>(out);
}

// round 6
// speedup vs baseline: 3.2069x; 1.0189x over previous
#include <cuda_runtime.h>
#include <math.h>

#define Ntot 20000
#define IN_  256
#define Hh   128
#define HNh  4
#define Ss   5
#define Bb   1024
#define Mm   16
#define Dd   512
#define RR   16384
#define RTOT (RR + Bb)
#define LALPHA 0.2f

typedef unsigned long long ull;

__device__ __forceinline__ float lrelu(float z) { return z >= 0.f ? z : LALPHA * z; }

__device__ __forceinline__ ull pack2b(float a) {          // broadcast pack {a,a}
    ull r;
    asm("mov.b64 %0, {%1, %1};" : "=l"(r) : "f"(a));
    return r;
}
__device__ __forceinline__ void ffma2(ull& d, ull a, ull b) {
    asm("fma.rn.f32x2 %0, %1, %2, %0;" : "+l"(d) : "l"(a), "l"(b));
}
__device__ __forceinline__ float2 unpack2(ull v) {
    float2 r;
    asm("mov.b64 {%0, %1}, %2;" : "=f"(r.x), "=f"(r.y) : "l"(v));
    return r;
}

// scratch
__device__ float g_xsh[Ss * HNh * Bb * Hh];
__device__ float g_wh2[Ss * HNh * Bb * Hh];
__device__ float g_out[Ss * Bb * Dd];
__device__ float g_feat[(size_t)Ss * RR * Dd];
__device__ float g_mp[Bb * 2 * Dd];
__device__ float g_sc1[Ss * Bb];
__device__ float g_sc2[2 * Bb];

// ---------------------------------------------------------------------------
// Kernel 1: feat GEMM (neighbors + target rows folded in), FFMA2 core
// ---------------------------------------------------------------------------
#define SA_STR 20
#define SW_STR 132

__global__ __launch_bounds__(256, 2) void k_feat(
    const float* __restrict__ x, const int* __restrict__ nbr,
    const int* __restrict__ tgt,
    const float* __restrict__ fc_w, const float* __restrict__ fc_b)
{
    __shared__ __align__(16) float sA[128 * SA_STR];
    __shared__ __align__(16) float sW[16 * SW_STR];
    __shared__ int sIdx[128];

    int m0 = blockIdx.x * 128;
    int n0 = blockIdx.y * 128;
    int s  = blockIdx.z;
    int tid = threadIdx.x;
    int tx = tid & 15, ty = tid >> 4;

    if (tid < 128) {
        int r = m0 + tid;
        sIdx[tid] = (r < RR) ? nbr[s * RR + r] : tgt[r - RR];
    }
    __syncthreads();

    ull acc2[8][4];
    #pragma unroll
    for (int i = 0; i < 8; ++i)
        #pragma unroll
        for (int j = 0; j < 4; ++j) acc2[i][j] = 0ull;

    const float* wbase = fc_w + (size_t)s * 512 * IN_;

    int kcp = (tid & 3) << 2;
    int rA0 = tid >> 2, rA1 = rA0 + 64;
    int nA0 = tid >> 2, nA1 = nA0 + 64;

    float4 pa0, pa1, pw0, pw1;
    pa0 = *(const float4*)(x + (size_t)sIdx[rA0] * IN_ + kcp);
    pa1 = *(const float4*)(x + (size_t)sIdx[rA1] * IN_ + kcp);
    pw0 = *(const float4*)(wbase + (size_t)(n0 + nA0) * IN_ + kcp);
    pw1 = *(const float4*)(wbase + (size_t)(n0 + nA1) * IN_ + kcp);

    for (int c = 0; c < 16; ++c) {
        __syncthreads();
        *(float4*)(sA + rA0 * SA_STR + kcp) = pa0;
        *(float4*)(sA + rA1 * SA_STR + kcp) = pa1;
        sW[(kcp + 0) * SW_STR + nA0] = pw0.x;
        sW[(kcp + 1) * SW_STR + nA0] = pw0.y;
        sW[(kcp + 2) * SW_STR + nA0] = pw0.z;
        sW[(kcp + 3) * SW_STR + nA0] = pw0.w;
        sW[(kcp + 0) * SW_STR + nA1] = pw1.x;
        sW[(kcp + 1) * SW_STR + nA1] = pw1.y;
        sW[(kcp + 2) * SW_STR + nA1] = pw1.z;
        sW[(kcp + 3) * SW_STR + nA1] = pw1.w;
        __syncthreads();
        if (c < 15) {
            int k0n = (c + 1) * 16 + kcp;
            pa0 = *(const float4*)(x + (size_t)sIdx[rA0] * IN_ + k0n);
            pa1 = *(const float4*)(x + (size_t)sIdx[rA1] * IN_ + k0n);
            pw0 = *(const float4*)(wbase + (size_t)(n0 + nA0) * IN_ + k0n);
            pw1 = *(const float4*)(wbase + (size_t)(n0 + nA1) * IN_ + k0n);
        }
        #pragma unroll
        for (int kk = 0; kk < 16; ++kk) {
            ull a2[8], w2[4];
            #pragma unroll
            for (int ri = 0; ri < 8; ++ri)
                a2[ri] = pack2b(sA[(ty * 8 + ri) * SA_STR + kk]);
            #pragma unroll
            for (int j = 0; j < 4; ++j)
                w2[j] = *(const ull*)(sW + kk * SW_STR + tx * 8 + 2 * j);
            #pragma unroll
            for (int ri = 0; ri < 8; ++ri)
                #pragma unroll
                for (int j = 0; j < 4; ++j)
                    ffma2(acc2[ri][j], a2[ri], w2[j]);
        }
    }

    float bias[8];
    #pragma unroll
    for (int ci = 0; ci < 8; ++ci) bias[ci] = fc_b[s * 512 + n0 + tx * 8 + ci];

    #pragma unroll
    for (int ri = 0; ri < 8; ++ri) {
        float vv[8];
        #pragma unroll
        for (int j = 0; j < 4; ++j) {
            float2 t = unpack2(acc2[ri][j]);
            vv[2 * j] = lrelu(t.x + bias[2 * j]);
            vv[2 * j + 1] = lrelu(t.y + bias[2 * j + 1]);
        }
        float4 v0 = {vv[0], vv[1], vv[2], vv[3]};
        float4 v1 = {vv[4], vv[5], vv[6], vv[7]};
        float* dst;
        if (m0 < RR) {
            int r = m0 + ty * 8 + ri;
            dst = g_feat + ((size_t)s * RR + r) * Dd + n0 + tx * 8;
        } else {
            int h = n0 >> 7;
            int b = m0 - RR + ty * 8 + ri;
            dst = g_xsh + ((size_t)(s * HNh + h) * Bb + b) * Hh + tx * 8;
        }
        *(float4*)(dst) = v0;
        *(float4*)(dst + 4) = v1;
    }
}

// ---------------------------------------------------------------------------
// shared FFMA2 64x128x128 micro-kernel pieces (T_STR layout)
// ---------------------------------------------------------------------------
#define T_STR 132
#define SM_QKV 19008
#define SM_ATTN 23872

// One 8-chunk (k=128) single-W GEMM: acc2[4][4] += sIn @ W^T, stream via sWbuf
__device__ __forceinline__ void gemm128_f2(
    const float* __restrict__ sIn, const float* __restrict__ Wg,
    float* __restrict__ sWbuf, ull acc2[4][4],
    int tid, int tx, int ty)
{
    int kcp = (tid & 3) << 2;
    int nA = tid >> 2, nB = nA + 64;
    #pragma unroll
    for (int ri = 0; ri < 4; ++ri)
        #pragma unroll
        for (int j = 0; j < 4; ++j) acc2[ri][j] = 0ull;

    float4 p0 = *(const float4*)(Wg + nA * Hh + kcp);
    float4 p1 = *(const float4*)(Wg + nB * Hh + kcp);
    for (int c = 0; c < 8; ++c) {
        __syncthreads();
        sWbuf[(kcp + 0) * T_STR + nA] = p0.x; sWbuf[(kcp + 1) * T_STR + nA] = p0.y;
        sWbuf[(kcp + 2) * T_STR + nA] = p0.z; sWbuf[(kcp + 3) * T_STR + nA] = p0.w;
        sWbuf[(kcp + 0) * T_STR + nB] = p1.x; sWbuf[(kcp + 1) * T_STR + nB] = p1.y;
        sWbuf[(kcp + 2) * T_STR + nB] = p1.z; sWbuf[(kcp + 3) * T_STR + nB] = p1.w;
        __syncthreads();
        if (c < 7) {
            int k0n = (c + 1) * 16 + kcp;
            p0 = *(const float4*)(Wg + nA * Hh + k0n);
            p1 = *(const float4*)(Wg + nB * Hh + k0n);
        }
        int k0 = c * 16;
        #pragma unroll
        for (int kk = 0; kk < 16; ++kk) {
            ull a2[4], w2[4];
            #pragma unroll
            for (int ri = 0; ri < 4; ++ri)
                a2[ri] = pack2b(sIn[(ty * 4 + ri) * T_STR + k0 + kk]);
            #pragma unroll
            for (int j = 0; j < 4; ++j)
                w2[j] = *(const ull*)(sWbuf + kk * T_STR + tx * 8 + 2 * j);
            #pragma unroll
            for (int ri = 0; ri < 4; ++ri)
                #pragma unroll
                for (int j = 0; j < 4; ++j)
                    ffma2(acc2[ri][j], a2[ri], w2[j]);
        }
    }
}

// ---------------------------------------------------------------------------
// Kernel 2: qkv chain per (s,h, 64-row tile)
// ---------------------------------------------------------------------------
__global__ __launch_bounds__(256, 2) void k_qkv(
    const float* __restrict__ q_w, const float* __restrict__ q_b,
    const float* __restrict__ a2w, const float* __restrict__ a2b,
    const float* __restrict__ aW)
{
    extern __shared__ __align__(16) float sm[];
    float* sA = sm;
    float* sQ = sm + 8448;
    float* sW = sm + 16896;

    int sh = blockIdx.y;
    int s = sh >> 2, h = sh & 3;
    int km = (s >= 2) ? 1 : 0;
    int b0 = blockIdx.x * 64;
    int tid = threadIdx.x;
    int tx = tid & 15, ty = tid >> 4;

    int who = (s * HNh + h) * Hh;
    int aho = (km * HNh + h) * Hh;
    const float* Wq = q_w + (size_t)who * Hh;
    const float* W2 = a2w + (size_t)aho * Hh;
    const float* Ww = aW + (size_t)aho * Hh;

    #pragma unroll
    for (int i = 0; i < 8; ++i) {
        int lid = tid + i * 256;
        int row = lid >> 5, c4 = (lid & 31) << 2;
        float4 v = *(const float4*)(g_xsh + ((size_t)(s * HNh + h) * Bb + b0 + row) * Hh + c4);
        *(float4*)(sA + row * T_STR + c4) = v;
    }

    ull acc2[4][4];

    // GEMM1: qh -> sQ
    gemm128_f2(sA, Wq, sW, acc2, tid, tx, ty);
    {
        float4 b0v = *(const float4*)(q_b + who + tx * 8);
        float4 b1v = *(const float4*)(q_b + who + tx * 8 + 4);
        float bb[8] = {b0v.x, b0v.y, b0v.z, b0v.w, b1v.x, b1v.y, b1v.z, b1v.w};
        #pragma unroll
        for (int ri = 0; ri < 4; ++ri) {
            float vv[8];
            #pragma unroll
            for (int j = 0; j < 4; ++j) {
                float2 t = unpack2(acc2[ri][j]);
                vv[2 * j] = t.x + bb[2 * j];
                vv[2 * j + 1] = t.y + bb[2 * j + 1];
            }
            float4 v0 = {vv[0], vv[1], vv[2], vv[3]};
            float4 v1 = {vv[4], vv[5], vv[6], vv[7]};
            *(float4*)(sQ + (ty * 4 + ri) * T_STR + tx * 8) = v0;
            *(float4*)(sQ + (ty * 4 + ri) * T_STR + tx * 8 + 4) = v1;
        }
    }

    // GEMM2: h2 -> sA
    gemm128_f2(sQ, W2, sW, acc2, tid, tx, ty);
    __syncthreads();
    {
        float4 b0v = *(const float4*)(a2b + aho + tx * 8);
        float4 b1v = *(const float4*)(a2b + aho + tx * 8 + 4);
        float bb[8] = {b0v.x, b0v.y, b0v.z, b0v.w, b1v.x, b1v.y, b1v.z, b1v.w};
        #pragma unroll
        for (int ri = 0; ri < 4; ++ri) {
            float vv[8];
            #pragma unroll
            for (int j = 0; j < 4; ++j) {
                float2 t = unpack2(acc2[ri][j]);
                vv[2 * j] = lrelu(t.x + bb[2 * j]);
                vv[2 * j + 1] = lrelu(t.y + bb[2 * j + 1]);
            }
            float4 v0 = {vv[0], vv[1], vv[2], vv[3]};
            float4 v1 = {vv[4], vv[5], vv[6], vv[7]};
            *(float4*)(sA + (ty * 4 + ri) * T_STR + tx * 8) = v0;
            *(float4*)(sA + (ty * 4 + ri) * T_STR + tx * 8 + 4) = v1;
        }
    }

    // GEMM3: wh2 -> g_wh2
    gemm128_f2(sA, Ww, sW, acc2, tid, tx, ty);
    #pragma unroll
    for (int ri = 0; ri < 4; ++ri) {
        int b = b0 + ty * 4 + ri;
        float* dst = g_wh2 + ((size_t)(s * HNh + h) * Bb + b) * Hh + tx * 8;
        float vv[8];
        #pragma unroll
        for (int j = 0; j < 4; ++j) {
            float2 t = unpack2(acc2[ri][j]);
            vv[2 * j] = t.x; vv[2 * j + 1] = t.y;
        }
        float4 v0 = {vv[0], vv[1], vv[2], vv[3]};
        float4 v1 = {vv[4], vv[5], vv[6], vv[7]};
        *(float4*)(dst) = v0;
        *(float4*)(dst + 4) = v1;
    }
}

// ---------------------------------------------------------------------------
// Kernel 3: fused attention, FFMA2 core
// ---------------------------------------------------------------------------
__global__ __launch_bounds__(256, 2) void k_attn(
    const float* __restrict__ k_w, const float* __restrict__ k_b,
    const float* __restrict__ v_w, const float* __restrict__ v_b,
    const float* __restrict__ a1w, const float* __restrict__ a1b)
{
    extern __shared__ __align__(16) float sm[];
    float* sF   = sm;
    float* sKH  = sm + 8448;
    float* sWk  = sm + 16896;
    float* sWv  = sm + 19008;
    float* sW2  = sm + 21120;
    float* sHp  = sm + 21632;
    float* sAtt = sm + 23744;
    float* sE   = sm + 23808;

    int sh = blockIdx.y;
    int s = sh >> 2, h = sh & 3;
    int km = (s >= 2) ? 1 : 0;
    int r0 = blockIdx.x * 64;
    int b0 = r0 >> 4;
    int tid = threadIdx.x;
    int tx = tid & 15, ty = tid >> 4;

    #pragma unroll
    for (int i = 0; i < 8; ++i) {
        int lid = tid + i * 256;
        int row = lid >> 5, c4 = (lid & 31) << 2;
        float4 v = *(const float4*)(g_feat + ((size_t)s * RR + r0 + row) * Dd + h * Hh + c4);
        *(float4*)(sF + row * T_STR + c4) = v;
    }
    #pragma unroll
    for (int i = 0; i < 2; ++i) {
        int lid = tid + i * 256;
        int bg = lid >> 7, o = lid & 127;
        sW2[lid] = g_wh2[((s * HNh + h) * Bb + b0 + bg) * Hh + o];
    }

    int who = (s * HNh + h) * Hh;
    int aho = (km * HNh + h) * Hh;
    const float* Wk = k_w + (size_t)who * Hh;
    const float* Wv = v_w + (size_t)who * Hh;
    const float* Wa = a1w + (size_t)aho * Hh;

    int kcp = (tid & 3) << 2;
    int nA = tid >> 2, nB = nA + 64;

    ull ak2[4][4], av2[4][4];
    #pragma unroll
    for (int ri = 0; ri < 4; ++ri)
        #pragma unroll
        for (int j = 0; j < 4; ++j) { ak2[ri][j] = 0ull; av2[ri][j] = 0ull; }

    float4 pk0 = *(const float4*)(Wk + nA * Hh + kcp);
    float4 pk1 = *(const float4*)(Wk + nB * Hh + kcp);
    float4 pv0 = *(const float4*)(Wv + nA * Hh + kcp);
    float4 pv1 = *(const float4*)(Wv + nB * Hh + kcp);

    // PASS A: kh + vh
    for (int c = 0; c < 8; ++c) {
        __syncthreads();
        sWk[(kcp + 0) * T_STR + nA] = pk0.x; sWk[(kcp + 1) * T_STR + nA] = pk0.y;
        sWk[(kcp + 2) * T_STR + nA] = pk0.z; sWk[(kcp + 3) * T_STR + nA] = pk0.w;
        sWk[(kcp + 0) * T_STR + nB] = pk1.x; sWk[(kcp + 1) * T_STR + nB] = pk1.y;
        sWk[(kcp + 2) * T_STR + nB] = pk1.z; sWk[(kcp + 3) * T_STR + nB] = pk1.w;
        sWv[(kcp + 0) * T_STR + nA] = pv0.x; sWv[(kcp + 1) * T_STR + nA] = pv0.y;
        sWv[(kcp + 2) * T_STR + nA] = pv0.z; sWv[(kcp + 3) * T_STR + nA] = pv0.w;
        sWv[(kcp + 0) * T_STR + nB] = pv1.x; sWv[(kcp + 1) * T_STR + nB] = pv1.y;
        sWv[(kcp + 2) * T_STR + nB] = pv1.z; sWv[(kcp + 3) * T_STR + nB] = pv1.w;
        __syncthreads();
        if (c < 7) {
            int k0n = (c + 1) * 16 + kcp;
            pk0 = *(const float4*)(Wk + nA * Hh + k0n);
            pk1 = *(const float4*)(Wk + nB * Hh + k0n);
            pv0 = *(const float4*)(Wv + nA * Hh + k0n);
            pv1 = *(const float4*)(Wv + nB * Hh + k0n);
        }
        int k0 = c * 16;
        #pragma unroll
        for (int kk = 0; kk < 16; ++kk) {
            ull a2[4], wk2[4], wv2[4];
            #pragma unroll
            for (int ri = 0; ri < 4; ++ri)
                a2[ri] = pack2b(sF[(ty * 4 + ri) * T_STR + k0 + kk]);
            #pragma unroll
            for (int j = 0; j < 4; ++j) {
                wk2[j] = *(const ull*)(sWk + kk * T_STR + tx * 8 + 2 * j);
                wv2[j] = *(const ull*)(sWv + kk * T_STR + tx * 8 + 2 * j);
            }
            #pragma unroll
            for (int ri = 0; ri < 4; ++ri)
                #pragma unroll
                for (int j = 0; j < 4; ++j) {
                    ffma2(ak2[ri][j], a2[ri], wk2[j]);
                    ffma2(av2[ri][j], a2[ri], wv2[j]);
                }
        }
    }

    float av[4][8];
    {
        float4 b0v = *(const float4*)(k_b + who + tx * 8);
        float4 b1v = *(const float4*)(k_b + who + tx * 8 + 4);
        float bb[8] = {b0v.x, b0v.y, b0v.z, b0v.w, b1v.x, b1v.y, b1v.z, b1v.w};
        #pragma unroll
        for (int ri = 0; ri < 4; ++ri) {
            float vv[8];
            #pragma unroll
            for (int j = 0; j < 4; ++j) {
                float2 t = unpack2(ak2[ri][j]);
                vv[2 * j] = t.x + bb[2 * j];
                vv[2 * j + 1] = t.y + bb[2 * j + 1];
            }
            float4 v0 = {vv[0], vv[1], vv[2], vv[3]};
            float4 v1 = {vv[4], vv[5], vv[6], vv[7]};
            *(float4*)(sKH + (ty * 4 + ri) * T_STR + tx * 8) = v0;
            *(float4*)(sKH + (ty * 4 + ri) * T_STR + tx * 8 + 4) = v1;
        }
        float4 c0v = *(const float4*)(v_b + who + tx * 8);
        float4 c1v = *(const float4*)(v_b + who + tx * 8 + 4);
        float cc[8] = {c0v.x, c0v.y, c0v.z, c0v.w, c1v.x, c1v.y, c1v.z, c1v.w};
        #pragma unroll
        for (int ri = 0; ri < 4; ++ri)
            #pragma unroll
            for (int j = 0; j < 4; ++j) {
                float2 t = unpack2(av2[ri][j]);
                av[ri][2 * j] = t.x + cc[2 * j];
                av[ri][2 * j + 1] = t.y + cc[2 * j + 1];
            }
    }

    // PASS 3: h1 gemm on sKH vs a1w
    ull ac32[4][4];
    #pragma unroll
    for (int ri = 0; ri < 4; ++ri)
        #pragma unroll
        for (int j = 0; j < 4; ++j) ac32[ri][j] = 0ull;

    pk0 = *(const float4*)(Wa + nA * Hh + kcp);
    pk1 = *(const float4*)(Wa + nB * Hh + kcp);
    for (int c = 0; c < 8; ++c) {
        __syncthreads();
        sWk[(kcp + 0) * T_STR + nA] = pk0.x; sWk[(kcp + 1) * T_STR + nA] = pk0.y;
        sWk[(kcp + 2) * T_STR + nA] = pk0.z; sWk[(kcp + 3) * T_STR + nA] = pk0.w;
        sWk[(kcp + 0) * T_STR + nB] = pk1.x; sWk[(kcp + 1) * T_STR + nB] = pk1.y;
        sWk[(kcp + 2) * T_STR + nB] = pk1.z; sWk[(kcp + 3) * T_STR + nB] = pk1.w;
        __syncthreads();
        if (c < 7) {
            int k0n = (c + 1) * 16 + kcp;
            pk0 = *(const float4*)(Wa + nA * Hh + k0n);
            pk1 = *(const float4*)(Wa + nB * Hh + k0n);
        }
        int k0 = c * 16;
        #pragma unroll
        for (int kk = 0; kk < 16; ++kk) {
            ull a2[4], w2[4];
            #pragma unroll
            for (int ri = 0; ri < 4; ++ri)
                a2[ri] = pack2b(sKH[(ty * 4 + ri) * T_STR + k0 + kk]);
            #pragma unroll
            for (int j = 0; j < 4; ++j)
                w2[j] = *(const ull*)(sWk + kk * T_STR + tx * 8 + 2 * j);
            #pragma unroll
            for (int ri = 0; ri < 4; ++ri)
                #pragma unroll
                for (int j = 0; j < 4; ++j)
                    ffma2(ac32[ri][j], a2[ri], w2[j]);
        }
    }

    {
        float4 b0v = *(const float4*)(a1b + aho + tx * 8);
        float4 b1v = *(const float4*)(a1b + aho + tx * 8 + 4);
        float bb[8] = {b0v.x, b0v.y, b0v.z, b0v.w, b1v.x, b1v.y, b1v.z, b1v.w};
        int bg = ty >> 2;
        #pragma unroll
        for (int ri = 0; ri < 4; ++ri) {
            float p = 0.f;
            #pragma unroll
            for (int j = 0; j < 4; ++j) {
                float2 t = unpack2(ac32[ri][j]);
                p += lrelu(t.x + bb[2 * j]) * sW2[bg * 128 + tx * 8 + 2 * j];
                p += lrelu(t.y + bb[2 * j + 1]) * sW2[bg * 128 + tx * 8 + 2 * j + 1];
            }
            sHp[(ty * 4 + ri) * 16 + tx] = p;
        }
    }
    __syncthreads();
    if (tid < 64) {
        float a = 0.f;
        #pragma unroll
        for (int j = 0; j < 16; ++j) a += sHp[tid * 16 + j];
        sAtt[tid] = a;
    }
    __syncthreads();
    if (tid < 4) {
        float mx = -1e30f;
        #pragma unroll
        for (int m = 0; m < Mm; ++m) mx = fmaxf(mx, sAtt[tid * 16 + m]);
        float sum = 0.f, ee[Mm];
        #pragma unroll
        for (int m = 0; m < Mm; ++m) { ee[m] = expf(sAtt[tid * 16 + m] - mx); sum += ee[m]; }
        float inv = 1.f / sum;
        #pragma unroll
        for (int m = 0; m < Mm; ++m) sE[tid * 16 + m] = ee[m] * inv;
    }
    __syncthreads();

    {
        int bg = ty >> 2;
        float hp[8];
        #pragma unroll
        for (int ci = 0; ci < 8; ++ci) hp[ci] = 0.f;
        #pragma unroll
        for (int ri = 0; ri < 4; ++ri) {
            int m = (ty * 4 + ri) & 15;
            float e = sE[bg * 16 + m];
            #pragma unroll
            for (int ci = 0; ci < 8; ++ci)
                hp[ci] += lrelu(av[ri][ci] * e);
        }
        #pragma unroll
        for (int ci = 0; ci < 8; ++ci)
            sHp[ty * T_STR + tx * 8 + ci] = hp[ci];
    }
    __syncthreads();
    #pragma unroll
    for (int i = 0; i < 2; ++i) {
        int lid = tid + i * 256;
        int bg = lid >> 7, o = lid & 127;
        float hsum = sHp[(bg * 4 + 0) * T_STR + o] + sHp[(bg * 4 + 1) * T_STR + o]
                   + sHp[(bg * 4 + 2) * T_STR + o] + sHp[(bg * 4 + 3) * T_STR + o];
        float xs = g_xsh[((s * HNh + h) * Bb + b0 + bg) * Hh + o];
        g_out[((size_t)s * Bb + b0 + bg) * Dd + h * Hh + o] = 0.5f * (xs + hsum);
    }
}

// ---------------------------------------------------------------------------
// Semantic attention, FFMA2 core
// ---------------------------------------------------------------------------
#define SZ_STR 20

__global__ __launch_bounds__(256) void k_sem_score(
    const float* __restrict__ zbase,
    const float* __restrict__ p1w, const float* __restrict__ p1b,
    const float* __restrict__ p2w,
    float* __restrict__ sc,
    int mode)
{
    __shared__ __align__(16) float sZ[64 * SZ_STR];
    __shared__ __align__(16) float sW[16 * SW_STR];
    __shared__ float sPart[64 * 16];

    int gy = blockIdx.y;
    int b0 = blockIdx.x * 64;
    int tid = threadIdx.x;
    int tx = tid & 15, ty = tid >> 4;

    int wsel, outbase;
    const float* zrow0;
    size_t zstride;
    if (mode == 0) {
        int s = gy;
        wsel = (s >= 2) ? 1 : 0;
        zrow0 = zbase + ((size_t)s * Bb + b0) * Dd;
        zstride = Dd;
        outbase = s * Bb + b0;
    } else {
        int k2 = gy;
        wsel = 0;
        zrow0 = zbase + ((size_t)b0 * 2 + k2) * Dd;
        zstride = 2 * Dd;
        outbase = k2 * Bb + b0;
    }
    const float* Wp = p1w + (size_t)wsel * Hh * Dd;
    const float* bp = p1b + wsel * Hh;
    const float* p2 = p2w + wsel * Hh;

    int kcp = (tid & 3) << 2;
    int rZ = tid >> 2;
    int nA = tid >> 2, nB = nA + 64;

    ull acc2[4][4];
    #pragma unroll
    for (int ri = 0; ri < 4; ++ri)
        #pragma unroll
        for (int j = 0; j < 4; ++j) acc2[ri][j] = 0ull;

    float4 pz = *(const float4*)(zrow0 + (size_t)rZ * zstride + kcp);
    float4 pw0 = *(const float4*)(Wp + (size_t)nA * Dd + kcp);
    float4 pw1 = *(const float4*)(Wp + (size_t)nB * Dd + kcp);

    for (int c = 0; c < 32; ++c) {
        __syncthreads();
        *(float4*)(sZ + rZ * SZ_STR + kcp) = pz;
        sW[(kcp + 0) * SW_STR + nA] = pw0.x; sW[(kcp + 1) * SW_STR + nA] = pw0.y;
        sW[(kcp + 2) * SW_STR + nA] = pw0.z; sW[(kcp + 3) * SW_STR + nA] = pw0.w;
        sW[(kcp + 0) * SW_STR + nB] = pw1.x; sW[(kcp + 1) * SW_STR + nB] = pw1.y;
        sW[(kcp + 2) * SW_STR + nB] = pw1.z; sW[(kcp + 3) * SW_STR + nB] = pw1.w;
        __syncthreads();
        if (c < 31) {
            int k0n = (c + 1) * 16 + kcp;
            pz = *(const float4*)(zrow0 + (size_t)rZ * zstride + k0n);
            pw0 = *(const float4*)(Wp + (size_t)nA * Dd + k0n);
            pw1 = *(const float4*)(Wp + (size_t)nB * Dd + k0n);
        }
        #pragma unroll
        for (int kk = 0; kk < 16; ++kk) {
            ull a2[4], w2[4];
            #pragma unroll
            for (int ri = 0; ri < 4; ++ri)
                a2[ri] = pack2b(sZ[(ty * 4 + ri) * SZ_STR + kk]);
            #pragma unroll
            for (int j = 0; j < 4; ++j)
                w2[j] = *(const ull*)(sW + kk * SW_STR + tx * 8 + 2 * j);
            #pragma unroll
            for (int ri = 0; ri < 4; ++ri)
                #pragma unroll
                for (int j = 0; j < 4; ++j)
                    ffma2(acc2[ri][j], a2[ri], w2[j]);
        }
    }
    {
        float bb[8], pp[8];
        #pragma unroll
        for (int ci = 0; ci < 8; ++ci) {
            bb[ci] = bp[tx * 8 + ci];
            pp[ci] = p2[tx * 8 + ci];
        }
        #pragma unroll
        for (int ri = 0; ri < 4; ++ri) {
            float p = 0.f;
            #pragma unroll
            for (int j = 0; j < 4; ++j) {
                float2 t = unpack2(acc2[ri][j]);
                p += tanhf(t.x + bb[2 * j]) * pp[2 * j];
                p += tanhf(t.y + bb[2 * j + 1]) * pp[2 * j + 1];
            }
            sPart[(ty * 4 + ri) * 16 + tx] = p;
        }
    }
    __syncthreads();
    if (tid < 64) {
        float a = 0.f;
        #pragma unroll
        for (int j = 0; j < 16; ++j) a += sPart[tid * 16 + j];
        sc[outbase + tid] = a;
    }
}

__global__ __launch_bounds__(256) void k_sem_comb1()
{
    int b = blockIdx.x;
    int tid = threadIdx.x;
    float s0 = g_sc1[0 * Bb + b], s1 = g_sc1[1 * Bb + b];
    float s2 = g_sc1[2 * Bb + b], s3 = g_sc1[3 * Bb + b], s4 = g_sc1[4 * Bb + b];
    float mx0 = fmaxf(s0, s1);
    float e0 = expf(s0 - mx0), e1 = expf(s1 - mx0);
    float i0 = 1.f / (e0 + e1);
    float b00 = e0 * i0, b01 = e1 * i0;
    float mx1 = fmaxf(fmaxf(s2, s3), s4);
    float f0 = expf(s2 - mx1), f1 = expf(s3 - mx1), f2 = expf(s4 - mx1);
    float i1 = 1.f / (f0 + f1 + f2);
    float b10 = f0 * i1, b11 = f1 * i1, b12 = f2 * i1;
    for (int d = tid; d < Dd; d += 256) {
        float z0 = b00 * g_out[(0 * Bb + b) * Dd + d] + b01 * g_out[(1 * Bb + b) * Dd + d];
        float z1 = b10 * g_out[(2 * Bb + b) * Dd + d] + b11 * g_out[(3 * Bb + b) * Dd + d]
                 + b12 * g_out[(4 * Bb + b) * Dd + d];
        g_mp[(b * 2 + 0) * Dd + d] = z0;
        g_mp[(b * 2 + 1) * Dd + d] = z1;
    }
}

__global__ __launch_bounds__(256) void k_sem_comb2(float* __restrict__ out)
{
    int b = blockIdx.x;
    int tid = threadIdx.x;
    float s0 = g_sc2[b], s1 = g_sc2[Bb + b];
    float mx = fmaxf(s0, s1);
    float e0 = expf(s0 - mx), e1 = expf(s1 - mx);
    float inv = 1.f / (e0 + e1);
    float be0 = e0 * inv, be1 = e1 * inv;
    for (int d = tid; d < Dd; d += 256)
        out[(size_t)b * Dd + d] = be0 * g_mp[(b * 2 + 0) * Dd + d]
                                + be1 * g_mp[(b * 2 + 1) * Dd + d];
}

// ---------------------------------------------------------------------------
extern "C" void kernel_launch(void* const* d_in, const int* in_sizes, int n_in,
                              void* d_out, int out_size)
{
    const float* x    = (const float*)d_in[0];
    const int*   tgt  = (const int*)d_in[1];
    const int*   nbr  = (const int*)d_in[2];
    const float* fc_w = (const float*)d_in[3];
    const float* fc_b = (const float*)d_in[4];
    const float* q_w  = (const float*)d_in[5];
    const float* q_b  = (const float*)d_in[6];
    const float* k_w  = (const float*)d_in[7];
    const float* k_b  = (const float*)d_in[8];
    const float* v_w  = (const float*)d_in[9];
    const float* v_b  = (const float*)d_in[10];
    const float* aW   = (const float*)d_in[11];
    const float* a1w  = (const float*)d_in[12];
    const float* a1b  = (const float*)d_in[13];
    const float* a2w  = (const float*)d_in[14];
    const float* a2b  = (const float*)d_in[15];
    const float* ip1w = (const float*)d_in[16];
    const float* ip1b = (const float*)d_in[17];
    const float* ip2w = (const float*)d_in[18];
    const float* bp1w = (const float*)d_in[19];
    const float* bp1b = (const float*)d_in[20];
    const float* bp2w = (const float*)d_in[21];
    float* out = (float*)d_out;

    (void)in_sizes; (void)n_in; (void)out_size;

    static int configured = 0;
    if (!configured) {
        cudaFuncSetAttribute(k_attn, cudaFuncAttributeMaxDynamicSharedMemorySize,
                             SM_ATTN * 4);
        cudaFuncSetAttribute(k_qkv, cudaFuncAttributeMaxDynamicSharedMemorySize,
                             SM_QKV * 4);
        configured = 1;
    }

    float* d_gout;  cudaGetSymbolAddress((void**)&d_gout, g_out);
    float* d_gmp;   cudaGetSymbolAddress((void**)&d_gmp, g_mp);
    float* d_sc1;   cudaGetSymbolAddress((void**)&d_sc1, g_sc1);
    float* d_sc2;   cudaGetSymbolAddress((void**)&d_sc2, g_sc2);

    k_feat<<<dim3(RTOT / 128, 4, Ss), 256>>>(x, nbr, tgt, fc_w, fc_b);
    k_qkv<<<dim3(Bb / 64, Ss * HNh), 256, SM_QKV * 4>>>(q_w, q_b, a2w, a2b, aW);
    k_attn<<<dim3(RR / 64, Ss * HNh), 256, SM_ATTN * 4>>>(k_w, k_b, v_w, v_b, a1w, a1b);
    k_sem_score<<<dim3(Bb / 64, Ss), 256>>>(d_gout, ip1w, ip1b, ip2w, d_sc1, 0);
    k_sem_comb1<<<Bb, 256>>>();
    k_sem_score<<<dim3(Bb / 64, 2), 256>>>(d_gmp, bp1w, bp1b, bp2w, d_sc2, 1);
    k_sem_comb2<<<Bb, 256>>>(out);
}

// round 7
// speedup vs baseline: 3.2856x; 1.0245x over previous
#include <cuda_runtime.h>
#include <math.h>

#define Ntot 20000
#define IN_  256
#define Hh   128
#define HNh  4
#define Ss   5
#define Bb   1024
#define Mm   16
#define Dd   512
#define RR   16384
#define RTOT (RR + Bb)
#define LALPHA 0.2f

typedef unsigned long long ull;
typedef unsigned int uint;

__device__ __forceinline__ float lrelu(float z) { return z >= 0.f ? z : LALPHA * z; }

__device__ __forceinline__ ull pack2b(float a) {
    ull r;
    asm("mov.b64 %0, {%1, %1};" : "=l"(r) : "f"(a));
    return r;
}
__device__ __forceinline__ void ffma2(ull& d, ull a, ull b) {
    asm("fma.rn.f32x2 %0, %1, %2, %0;" : "+l"(d) : "l"(a), "l"(b));
}
__device__ __forceinline__ float2 unpack2(ull v) {
    float2 r;
    asm("mov.b64 {%0, %1}, %2;" : "=f"(r.x), "=f"(r.y) : "l"(v));
    return r;
}
__device__ __forceinline__ float cvt_tf32(float x) {
    uint r;
    asm("cvt.rna.tf32.f32 %0, %1;" : "=r"(r) : "f"(x));
    return __uint_as_float(r);
}
__device__ __forceinline__ void mma_tf32(float c[4], const uint a[4], uint b0, uint b1) {
    asm("mma.sync.aligned.m16n8k8.row.col.f32.tf32.tf32.f32 "
        "{%0,%1,%2,%3}, {%4,%5,%6,%7}, {%8,%9}, {%0,%1,%2,%3};"
        : "+f"(c[0]), "+f"(c[1]), "+f"(c[2]), "+f"(c[3])
        : "r"(a[0]), "r"(a[1]), "r"(a[2]), "r"(a[3]), "r"(b0), "r"(b1));
}

// scratch
__device__ float g_xsh[Ss * HNh * Bb * Hh];
__device__ float g_wh2[Ss * HNh * Bb * Hh];
__device__ float g_out[Ss * Bb * Dd];
__device__ float g_feat[(size_t)Ss * RR * Dd];
__device__ float g_mp[Bb * 2 * Dd];
__device__ float g_sc1[Ss * Bb];
__device__ float g_sc2[2 * Bb];
__device__ float g_xhi[(size_t)Ntot * IN_];
__device__ float g_xlo[(size_t)Ntot * IN_];
__device__ float g_wfrag[Ss * 32 * 64 * 32 * 4];   // [s][k8][j][lane][4]={b0h,b1h,b0l,b1l}

// ---------------------------------------------------------------------------
// Pre-kernels: tf32 hi/lo decomposition
// ---------------------------------------------------------------------------
__global__ __launch_bounds__(256) void k_xconv(const float* __restrict__ x)
{
    size_t i = (size_t)blockIdx.x * 256 + threadIdx.x;   // float4 index
    float4 v = ((const float4*)x)[i];
    float4 h, l;
    h.x = cvt_tf32(v.x); l.x = cvt_tf32(v.x - h.x);
    h.y = cvt_tf32(v.y); l.y = cvt_tf32(v.y - h.y);
    h.z = cvt_tf32(v.z); l.z = cvt_tf32(v.z - h.z);
    h.w = cvt_tf32(v.w); l.w = cvt_tf32(v.w - h.w);
    ((float4*)g_xhi)[i] = h;
    ((float4*)g_xlo)[i] = l;
}

__global__ __launch_bounds__(256) void k_wconv(const float* __restrict__ fc_w)
{
    int idx = blockIdx.x * 256 + threadIdx.x;           // slot index
    int lane = idx & 31;
    int t = idx >> 5;
    int j = t & 63; t >>= 6;
    int k8 = t & 31;
    int s = t >> 5;
    int n = 8 * j + (lane >> 2);
    int k0 = 8 * k8 + (lane & 3);
    const float* W = fc_w + ((size_t)s * 512 + n) * IN_;
    float w0 = W[k0], w1 = W[k0 + 4];
    float h0 = cvt_tf32(w0), h1 = cvt_tf32(w1);
    float l0 = cvt_tf32(w0 - h0), l1 = cvt_tf32(w1 - h1);
    float4 o = {h0, h1, l0, l1};
    ((float4*)g_wfrag)[idx] = o;
}

// ---------------------------------------------------------------------------
// Kernel 1: feat GEMM via mma.sync tf32 (3xTF32). Tile 128x128xK256.
// 8 warps: wm=warp&3 (m32), wn=warp>>2 (n64). Rows->g_feat / g_xsh.
// ---------------------------------------------------------------------------
#define APLN 36    // plane stride (floats); 256 planes

__global__ __launch_bounds__(256) void k_feat(
    const int* __restrict__ nbr, const int* __restrict__ tgt,
    const float* __restrict__ fc_b)
{
    __shared__ float sAf[256 * APLN];
    __shared__ int sIdx[128];

    int m0 = blockIdx.x * 128;
    int n0 = blockIdx.y * 128;
    int s  = blockIdx.z;
    int tid = threadIdx.x;
    int warp = tid >> 5, L = tid & 31;
    int wm = warp & 3, wn = warp >> 2;
    int g = L >> 2, c4 = L & 3;

    if (tid < 128) {
        int r = m0 + tid;
        sIdx[tid] = (r < RR) ? nbr[s * RR + r] : tgt[r - RR];
    }
    __syncthreads();

    float acc[2][8][4];
    #pragma unroll
    for (int mi = 0; mi < 2; ++mi)
        #pragma unroll
        for (int jl = 0; jl < 8; ++jl)
            #pragma unroll
            for (int e = 0; e < 4; ++e) acc[mi][jl][e] = 0.f;

    const float* wf = g_wfrag + (size_t)s * 32 * 64 * 32 * 4;
    int jbase = (n0 >> 3) + wn * 8;

    // staging register prefetch (chunk 0)
    float4 ah[4], al[4];
    #pragma unroll
    for (int u = 0; u < 4; ++u) {
        int idx = tid + 256 * u;
        int row = idx >> 3, kq = idx & 7;
        size_t o = (size_t)sIdx[row] * IN_ + 4 * kq;
        ah[u] = *(const float4*)(g_xhi + o);
        al[u] = *(const float4*)(g_xlo + o);
    }
    // B fragment prefetch (k8 = 0)
    float4 bp[8];
    #pragma unroll
    for (int jl = 0; jl < 8; ++jl)
        bp[jl] = *(const float4*)(wf + ((size_t)(0 * 64 + jbase + jl) * 32 + L) * 4);

    for (int ch = 0; ch < 8; ++ch) {
        __syncthreads();
        // store staged A chunk into frag-order smem
        #pragma unroll
        for (int u = 0; u < 4; ++u) {
            int idx = tid + 256 * u;
            int row = idx >> 3, kq = idx & 7;
            int q = kq >> 1;
            int mt = row >> 4;
            int r = row & 15;
            int reg = ((r >> 3) & 1) | ((kq & 1) << 1);
            int gg = r & 7;
            int p0 = ((q * 8 + mt) * 2 + 0) * 4 + reg;
            int p1 = ((q * 8 + mt) * 2 + 1) * 4 + reg;
            *(float4*)(sAf + p0 * APLN + 4 * gg) = ah[u];
            *(float4*)(sAf + p1 * APLN + 4 * gg) = al[u];
        }
        __syncthreads();
        if (ch < 7) {
            #pragma unroll
            for (int u = 0; u < 4; ++u) {
                int idx = tid + 256 * u;
                int row = idx >> 3, kq = idx & 7;
                size_t o = (size_t)sIdx[row] * IN_ + (ch + 1) * 32 + 4 * kq;
                ah[u] = *(const float4*)(g_xhi + o);
                al[u] = *(const float4*)(g_xlo + o);
            }
        }
        #pragma unroll
        for (int q = 0; q < 4; ++q) {
            float4 bc[8];
            #pragma unroll
            for (int jl = 0; jl < 8; ++jl) bc[jl] = bp[jl];
            int nk8 = ch * 4 + q + 1;
            if (nk8 < 32) {
                #pragma unroll
                for (int jl = 0; jl < 8; ++jl)
                    bp[jl] = *(const float4*)(wf + ((size_t)(nk8 * 64 + jbase + jl) * 32 + L) * 4);
            }
            // A fragments from smem
            uint afh[2][4], afl[2][4];
            #pragma unroll
            for (int mi = 0; mi < 2; ++mi) {
                int mt = 2 * wm + mi;
                int pb = ((q * 8 + mt) * 2) * 4;
                #pragma unroll
                for (int rg = 0; rg < 4; ++rg) {
                    afh[mi][rg] = __float_as_uint(sAf[(pb + rg) * APLN + L]);
                    afl[mi][rg] = __float_as_uint(sAf[(pb + 4 + rg) * APLN + L]);
                }
            }
            #pragma unroll
            for (int mi = 0; mi < 2; ++mi)
                #pragma unroll
                for (int jl = 0; jl < 8; ++jl) {
                    uint bh0 = __float_as_uint(bc[jl].x), bh1 = __float_as_uint(bc[jl].y);
                    uint bl0 = __float_as_uint(bc[jl].z), bl1 = __float_as_uint(bc[jl].w);
                    mma_tf32(acc[mi][jl], afh[mi], bh0, bh1);
                    mma_tf32(acc[mi][jl], afh[mi], bl0, bl1);
                    mma_tf32(acc[mi][jl], afl[mi], bh0, bh1);
                }
        }
    }

    // epilogue: bias + lrelu + store (c0,c1)->(r,col) (c2,c3)->(r+8,col)
    #pragma unroll
    for (int mi = 0; mi < 2; ++mi) {
        int rbase = 32 * wm + 16 * mi + g;
        #pragma unroll
        for (int jl = 0; jl < 8; ++jl) {
            int col = 64 * wn + 8 * jl + 2 * c4;
            float b0v = fc_b[s * 512 + n0 + col];
            float b1v = fc_b[s * 512 + n0 + col + 1];
            float2 v0 = {lrelu(acc[mi][jl][0] + b0v), lrelu(acc[mi][jl][1] + b1v)};
            float2 v1 = {lrelu(acc[mi][jl][2] + b0v), lrelu(acc[mi][jl][3] + b1v)};
            if (m0 < RR) {
                int r = m0 + rbase;
                *(float2*)(g_feat + ((size_t)s * RR + r) * Dd + n0 + col) = v0;
                *(float2*)(g_feat + ((size_t)s * RR + r + 8) * Dd + n0 + col) = v1;
            } else {
                int h = n0 >> 7;
                int b = m0 - RR + rbase;
                *(float2*)(g_xsh + ((size_t)(s * HNh + h) * Bb + b) * Hh + col) = v0;
                *(float2*)(g_xsh + ((size_t)(s * HNh + h) * Bb + b + 8) * Hh + col) = v1;
            }
        }
    }
}

// ---------------------------------------------------------------------------
// shared FFMA2 64x128x128 micro-kernel (unchanged from R6)
// ---------------------------------------------------------------------------
#define SW_STR 132
#define T_STR 132
#define SM_QKV 19008
#define SM_ATTN 23872

__device__ __forceinline__ void gemm128_f2(
    const float* __restrict__ sIn, const float* __restrict__ Wg,
    float* __restrict__ sWbuf, ull acc2[4][4],
    int tid, int tx, int ty)
{
    int kcp = (tid & 3) << 2;
    int nA = tid >> 2, nB = nA + 64;
    #pragma unroll
    for (int ri = 0; ri < 4; ++ri)
        #pragma unroll
        for (int j = 0; j < 4; ++j) acc2[ri][j] = 0ull;

    float4 p0 = *(const float4*)(Wg + nA * Hh + kcp);
    float4 p1 = *(const float4*)(Wg + nB * Hh + kcp);
    for (int c = 0; c < 8; ++c) {
        __syncthreads();
        sWbuf[(kcp + 0) * T_STR + nA] = p0.x; sWbuf[(kcp + 1) * T_STR + nA] = p0.y;
        sWbuf[(kcp + 2) * T_STR + nA] = p0.z; sWbuf[(kcp + 3) * T_STR + nA] = p0.w;
        sWbuf[(kcp + 0) * T_STR + nB] = p1.x; sWbuf[(kcp + 1) * T_STR + nB] = p1.y;
        sWbuf[(kcp + 2) * T_STR + nB] = p1.z; sWbuf[(kcp + 3) * T_STR + nB] = p1.w;
        __syncthreads();
        if (c < 7) {
            int k0n = (c + 1) * 16 + kcp;
            p0 = *(const float4*)(Wg + nA * Hh + k0n);
            p1 = *(const float4*)(Wg + nB * Hh + k0n);
        }
        int k0 = c * 16;
        #pragma unroll
        for (int kk = 0; kk < 16; ++kk) {
            ull a2[4], w2[4];
            #pragma unroll
            for (int ri = 0; ri < 4; ++ri)
                a2[ri] = pack2b(sIn[(ty * 4 + ri) * T_STR + k0 + kk]);
            #pragma unroll
            for (int j = 0; j < 4; ++j)
                w2[j] = *(const ull*)(sWbuf + kk * T_STR + tx * 8 + 2 * j);
            #pragma unroll
            for (int ri = 0; ri < 4; ++ri)
                #pragma unroll
                for (int j = 0; j < 4; ++j)
                    ffma2(acc2[ri][j], a2[ri], w2[j]);
        }
    }
}

// ---------------------------------------------------------------------------
// Kernel 2: qkv chain (unchanged)
// ---------------------------------------------------------------------------
__global__ __launch_bounds__(256, 2) void k_qkv(
    const float* __restrict__ q_w, const float* __restrict__ q_b,
    const float* __restrict__ a2w, const float* __restrict__ a2b,
    const float* __restrict__ aW)
{
    extern __shared__ __align__(16) float sm[];
    float* sA = sm;
    float* sQ = sm + 8448;
    float* sW = sm + 16896;

    int sh = blockIdx.y;
    int s = sh >> 2, h = sh & 3;
    int km = (s >= 2) ? 1 : 0;
    int b0 = blockIdx.x * 64;
    int tid = threadIdx.x;
    int tx = tid & 15, ty = tid >> 4;

    int who = (s * HNh + h) * Hh;
    int aho = (km * HNh + h) * Hh;
    const float* Wq = q_w + (size_t)who * Hh;
    const float* W2 = a2w + (size_t)aho * Hh;
    const float* Ww = aW + (size_t)aho * Hh;

    #pragma unroll
    for (int i = 0; i < 8; ++i) {
        int lid = tid + i * 256;
        int row = lid >> 5, c4 = (lid & 31) << 2;
        float4 v = *(const float4*)(g_xsh + ((size_t)(s * HNh + h) * Bb + b0 + row) * Hh + c4);
        *(float4*)(sA + row * T_STR + c4) = v;
    }

    ull acc2[4][4];

    gemm128_f2(sA, Wq, sW, acc2, tid, tx, ty);
    {
        float4 b0v = *(const float4*)(q_b + who + tx * 8);
        float4 b1v = *(const float4*)(q_b + who + tx * 8 + 4);
        float bb[8] = {b0v.x, b0v.y, b0v.z, b0v.w, b1v.x, b1v.y, b1v.z, b1v.w};
        #pragma unroll
        for (int ri = 0; ri < 4; ++ri) {
            float vv[8];
            #pragma unroll
            for (int j = 0; j < 4; ++j) {
                float2 t = unpack2(acc2[ri][j]);
                vv[2 * j] = t.x + bb[2 * j];
                vv[2 * j + 1] = t.y + bb[2 * j + 1];
            }
            float4 v0 = {vv[0], vv[1], vv[2], vv[3]};
            float4 v1 = {vv[4], vv[5], vv[6], vv[7]};
            *(float4*)(sQ + (ty * 4 + ri) * T_STR + tx * 8) = v0;
            *(float4*)(sQ + (ty * 4 + ri) * T_STR + tx * 8 + 4) = v1;
        }
    }

    gemm128_f2(sQ, W2, sW, acc2, tid, tx, ty);
    __syncthreads();
    {
        float4 b0v = *(const float4*)(a2b + aho + tx * 8);
        float4 b1v = *(const float4*)(a2b + aho + tx * 8 + 4);
        float bb[8] = {b0v.x, b0v.y, b0v.z, b0v.w, b1v.x, b1v.y, b1v.z, b1v.w};
        #pragma unroll
        for (int ri = 0; ri < 4; ++ri) {
            float vv[8];
            #pragma unroll
            for (int j = 0; j < 4; ++j) {
                float2 t = unpack2(acc2[ri][j]);
                vv[2 * j] = lrelu(t.x + bb[2 * j]);
                vv[2 * j + 1] = lrelu(t.y + bb[2 * j + 1]);
            }
            float4 v0 = {vv[0], vv[1], vv[2], vv[3]};
            float4 v1 = {vv[4], vv[5], vv[6], vv[7]};
            *(float4*)(sA + (ty * 4 + ri) * T_STR + tx * 8) = v0;
            *(float4*)(sA + (ty * 4 + ri) * T_STR + tx * 8 + 4) = v1;
        }
    }

    gemm128_f2(sA, Ww, sW, acc2, tid, tx, ty);
    #pragma unroll
    for (int ri = 0; ri < 4; ++ri) {
        int b = b0 + ty * 4 + ri;
        float* dst = g_wh2 + ((size_t)(s * HNh + h) * Bb + b) * Hh + tx * 8;
        float vv[8];
        #pragma unroll
        for (int j = 0; j < 4; ++j) {
            float2 t = unpack2(acc2[ri][j]);
            vv[2 * j] = t.x; vv[2 * j + 1] = t.y;
        }
        float4 v0 = {vv[0], vv[1], vv[2], vv[3]};
        float4 v1 = {vv[4], vv[5], vv[6], vv[7]};
        *(float4*)(dst) = v0;
        *(float4*)(dst + 4) = v1;
    }
}

// ---------------------------------------------------------------------------
// Kernel 3: fused attention (unchanged from R6)
// ---------------------------------------------------------------------------
__global__ __launch_bounds__(256, 2) void k_attn(
    const float* __restrict__ k_w, const float* __restrict__ k_b,
    const float* __restrict__ v_w, const float* __restrict__ v_b,
    const float* __restrict__ a1w, const float* __restrict__ a1b)
{
    extern __shared__ __align__(16) float sm[];
    float* sF   = sm;
    float* sKH  = sm + 8448;
    float* sWk  = sm + 16896;
    float* sWv  = sm + 19008;
    float* sW2  = sm + 21120;
    float* sHp  = sm + 21632;
    float* sAtt = sm + 23744;
    float* sE   = sm + 23808;

    int sh = blockIdx.y;
    int s = sh >> 2, h = sh & 3;
    int km = (s >= 2) ? 1 : 0;
    int r0 = blockIdx.x * 64;
    int b0 = r0 >> 4;
    int tid = threadIdx.x;
    int tx = tid & 15, ty = tid >> 4;

    #pragma unroll
    for (int i = 0; i < 8; ++i) {
        int lid = tid + i * 256;
        int row = lid >> 5, c4 = (lid & 31) << 2;
        float4 v = *(const float4*)(g_feat + ((size_t)s * RR + r0 + row) * Dd + h * Hh + c4);
        *(float4*)(sF + row * T_STR + c4) = v;
    }
    #pragma unroll
    for (int i = 0; i < 2; ++i) {
        int lid = tid + i * 256;
        int bg = lid >> 7, o = lid & 127;
        sW2[lid] = g_wh2[((s * HNh + h) * Bb + b0 + bg) * Hh + o];
    }

    int who = (s * HNh + h) * Hh;
    int aho = (km * HNh + h) * Hh;
    const float* Wk = k_w + (size_t)who * Hh;
    const float* Wv = v_w + (size_t)who * Hh;
    const float* Wa = a1w + (size_t)aho * Hh;

    int kcp = (tid & 3) << 2;
    int nA = tid >> 2, nB = nA + 64;

    ull ak2[4][4], av2[4][4];
    #pragma unroll
    for (int ri = 0; ri < 4; ++ri)
        #pragma unroll
        for (int j = 0; j < 4; ++j) { ak2[ri][j] = 0ull; av2[ri][j] = 0ull; }

    float4 pk0 = *(const float4*)(Wk + nA * Hh + kcp);
    float4 pk1 = *(const float4*)(Wk + nB * Hh + kcp);
    float4 pv0 = *(const float4*)(Wv + nA * Hh + kcp);
    float4 pv1 = *(const float4*)(Wv + nB * Hh + kcp);

    for (int c = 0; c < 8; ++c) {
        __syncthreads();
        sWk[(kcp + 0) * T_STR + nA] = pk0.x; sWk[(kcp + 1) * T_STR + nA] = pk0.y;
        sWk[(kcp + 2) * T_STR + nA] = pk0.z; sWk[(kcp + 3) * T_STR + nA] = pk0.w;
        sWk[(kcp + 0) * T_STR + nB] = pk1.x; sWk[(kcp + 1) * T_STR + nB] = pk1.y;
        sWk[(kcp + 2) * T_STR + nB] = pk1.z; sWk[(kcp + 3) * T_STR + nB] = pk1.w;
        sWv[(kcp + 0) * T_STR + nA] = pv0.x; sWv[(kcp + 1) * T_STR + nA] = pv0.y;
        sWv[(kcp + 2) * T_STR + nA] = pv0.z; sWv[(kcp + 3) * T_STR + nA] = pv0.w;
        sWv[(kcp + 0) * T_STR + nB] = pv1.x; sWv[(kcp + 1) * T_STR + nB] = pv1.y;
        sWv[(kcp + 2) * T_STR + nB] = pv1.z; sWv[(kcp + 3) * T_STR + nB] = pv1.w;
        __syncthreads();
        if (c < 7) {
            int k0n = (c + 1) * 16 + kcp;
            pk0 = *(const float4*)(Wk + nA * Hh + k0n);
            pk1 = *(const float4*)(Wk + nB * Hh + k0n);
            pv0 = *(const float4*)(Wv + nA * Hh + k0n);
            pv1 = *(const float4*)(Wv + nB * Hh + k0n);
        }
        int k0 = c * 16;
        #pragma unroll
        for (int kk = 0; kk < 16; ++kk) {
            ull a2[4], wk2[4], wv2[4];
            #pragma unroll
            for (int ri = 0; ri < 4; ++ri)
                a2[ri] = pack2b(sF[(ty * 4 + ri) * T_STR + k0 + kk]);
            #pragma unroll
            for (int j = 0; j < 4; ++j) {
                wk2[j] = *(const ull*)(sWk + kk * T_STR + tx * 8 + 2 * j);
                wv2[j] = *(const ull*)(sWv + kk * T_STR + tx * 8 + 2 * j);
            }
            #pragma unroll
            for (int ri = 0; ri < 4; ++ri)
                #pragma unroll
                for (int j = 0; j < 4; ++j) {
                    ffma2(ak2[ri][j], a2[ri], wk2[j]);
                    ffma2(av2[ri][j], a2[ri], wv2[j]);
                }
        }
    }

    float av[4][8];
    {
        float4 b0v = *(const float4*)(k_b + who + tx * 8);
        float4 b1v = *(const float4*)(k_b + who + tx * 8 + 4);
        float bb[8] = {b0v.x, b0v.y, b0v.z, b0v.w, b1v.x, b1v.y, b1v.z, b1v.w};
        #pragma unroll
        for (int ri = 0; ri < 4; ++ri) {
            float vv[8];
            #pragma unroll
            for (int j = 0; j < 4; ++j) {
                float2 t = unpack2(ak2[ri][j]);
                vv[2 * j] = t.x + bb[2 * j];
                vv[2 * j + 1] = t.y + bb[2 * j + 1];
            }
            float4 v0 = {vv[0], vv[1], vv[2], vv[3]};
            float4 v1 = {vv[4], vv[5], vv[6], vv[7]};
            *(float4*)(sKH + (ty * 4 + ri) * T_STR + tx * 8) = v0;
            *(float4*)(sKH + (ty * 4 + ri) * T_STR + tx * 8 + 4) = v1;
        }
        float4 c0v = *(const float4*)(v_b + who + tx * 8);
        float4 c1v = *(const float4*)(v_b + who + tx * 8 + 4);
        float cc[8] = {c0v.x, c0v.y, c0v.z, c0v.w, c1v.x, c1v.y, c1v.z, c1v.w};
        #pragma unroll
        for (int ri = 0; ri < 4; ++ri)
            #pragma unroll
            for (int j = 0; j < 4; ++j) {
                float2 t = unpack2(av2[ri][j]);
                av[ri][2 * j] = t.x + cc[2 * j];
                av[ri][2 * j + 1] = t.y + cc[2 * j + 1];
            }
    }

    ull ac32[4][4];
    #pragma unroll
    for (int ri = 0; ri < 4; ++ri)
        #pragma unroll
        for (int j = 0; j < 4; ++j) ac32[ri][j] = 0ull;

    pk0 = *(const float4*)(Wa + nA * Hh + kcp);
    pk1 = *(const float4*)(Wa + nB * Hh + kcp);
    for (int c = 0; c < 8; ++c) {
        __syncthreads();
        sWk[(kcp + 0) * T_STR + nA] = pk0.x; sWk[(kcp + 1) * T_STR + nA] = pk0.y;
        sWk[(kcp + 2) * T_STR + nA] = pk0.z; sWk[(kcp + 3) * T_STR + nA] = pk0.w;
        sWk[(kcp + 0) * T_STR + nB] = pk1.x; sWk[(kcp + 1) * T_STR + nB] = pk1.y;
        sWk[(kcp + 2) * T_STR + nB] = pk1.z; sWk[(kcp + 3) * T_STR + nB] = pk1.w;
        __syncthreads();
        if (c < 7) {
            int k0n = (c + 1) * 16 + kcp;
            pk0 = *(const float4*)(Wa + nA * Hh + k0n);
            pk1 = *(const float4*)(Wa + nB * Hh + k0n);
        }
        int k0 = c * 16;
        #pragma unroll
        for (int kk = 0; kk < 16; ++kk) {
            ull a2[4], w2[4];
            #pragma unroll
            for (int ri = 0; ri < 4; ++ri)
                a2[ri] = pack2b(sKH[(ty * 4 + ri) * T_STR + k0 + kk]);
            #pragma unroll
            for (int j = 0; j < 4; ++j)
                w2[j] = *(const ull*)(sWk + kk * T_STR + tx * 8 + 2 * j);
            #pragma unroll
            for (int ri = 0; ri < 4; ++ri)
                #pragma unroll
                for (int j = 0; j < 4; ++j)
                    ffma2(ac32[ri][j], a2[ri], w2[j]);
        }
    }

    {
        float4 b0v = *(const float4*)(a1b + aho + tx * 8);
        float4 b1v = *(const float4*)(a1b + aho + tx * 8 + 4);
        float bb[8] = {b0v.x, b0v.y, b0v.z, b0v.w, b1v.x, b1v.y, b1v.z, b1v.w};
        int bg = ty >> 2;
        #pragma unroll
        for (int ri = 0; ri < 4; ++ri) {
            float p = 0.f;
            #pragma unroll
            for (int j = 0; j < 4; ++j) {
                float2 t = unpack2(ac32[ri][j]);
                p += lrelu(t.x + bb[2 * j]) * sW2[bg * 128 + tx * 8 + 2 * j];
                p += lrelu(t.y + bb[2 * j + 1]) * sW2[bg * 128 + tx * 8 + 2 * j + 1];
            }
            sHp[(ty * 4 + ri) * 16 + tx] = p;
        }
    }
    __syncthreads();
    if (tid < 64) {
        float a = 0.f;
        #pragma unroll
        for (int j = 0; j < 16; ++j) a += sHp[tid * 16 + j];
        sAtt[tid] = a;
    }
    __syncthreads();
    if (tid < 4) {
        float mx = -1e30f;
        #pragma unroll
        for (int m = 0; m < Mm; ++m) mx = fmaxf(mx, sAtt[tid * 16 + m]);
        float sum = 0.f, ee[Mm];
        #pragma unroll
        for (int m = 0; m < Mm; ++m) { ee[m] = expf(sAtt[tid * 16 + m] - mx); sum += ee[m]; }
        float inv = 1.f / sum;
        #pragma unroll
        for (int m = 0; m < Mm; ++m) sE[tid * 16 + m] = ee[m] * inv;
    }
    __syncthreads();

    {
        int bg = ty >> 2;
        float hp[8];
        #pragma unroll
        for (int ci = 0; ci < 8; ++ci) hp[ci] = 0.f;
        #pragma unroll
        for (int ri = 0; ri < 4; ++ri) {
            int m = (ty * 4 + ri) & 15;
            float e = sE[bg * 16 + m];
            #pragma unroll
            for (int ci = 0; ci < 8; ++ci)
                hp[ci] += lrelu(av[ri][ci] * e);
        }
        #pragma unroll
        for (int ci = 0; ci < 8; ++ci)
            sHp[ty * T_STR + tx * 8 + ci] = hp[ci];
    }
    __syncthreads();
    #pragma unroll
    for (int i = 0; i < 2; ++i) {
        int lid = tid + i * 256;
        int bg = lid >> 7, o = lid & 127;
        float hsum = sHp[(bg * 4 + 0) * T_STR + o] + sHp[(bg * 4 + 1) * T_STR + o]
                   + sHp[(bg * 4 + 2) * T_STR + o] + sHp[(bg * 4 + 3) * T_STR + o];
        float xs = g_xsh[((s * HNh + h) * Bb + b0 + bg) * Hh + o];
        g_out[((size_t)s * Bb + b0 + bg) * Dd + h * Hh + o] = 0.5f * (xs + hsum);
    }
}

// ---------------------------------------------------------------------------
// Semantic attention (unchanged)
// ---------------------------------------------------------------------------
#define SZ_STR 20

__global__ __launch_bounds__(256) void k_sem_score(
    const float* __restrict__ zbase,
    const float* __restrict__ p1w, const float* __restrict__ p1b,
    const float* __restrict__ p2w,
    float* __restrict__ sc,
    int mode)
{
    __shared__ __align__(16) float sZ[64 * SZ_STR];
    __shared__ __align__(16) float sW[16 * SW_STR];
    __shared__ float sPart[64 * 16];

    int gy = blockIdx.y;
    int b0 = blockIdx.x * 64;
    int tid = threadIdx.x;
    int tx = tid & 15, ty = tid >> 4;

    int wsel, outbase;
    const float* zrow0;
    size_t zstride;
    if (mode == 0) {
        int s = gy;
        wsel = (s >= 2) ? 1 : 0;
        zrow0 = zbase + ((size_t)s * Bb + b0) * Dd;
        zstride = Dd;
        outbase = s * Bb + b0;
    } else {
        int k2 = gy;
        wsel = 0;
        zrow0 = zbase + ((size_t)b0 * 2 + k2) * Dd;
        zstride = 2 * Dd;
        outbase = k2 * Bb + b0;
    }
    const float* Wp = p1w + (size_t)wsel * Hh * Dd;
    const float* bp = p1b + wsel * Hh;
    const float* p2 = p2w + wsel * Hh;

    int kcp = (tid & 3) << 2;
    int rZ = tid >> 2;
    int nA = tid >> 2, nB = nA + 64;

    ull acc2[4][4];
    #pragma unroll
    for (int ri = 0; ri < 4; ++ri)
        #pragma unroll
        for (int j = 0; j < 4; ++j) acc2[ri][j] = 0ull;

    float4 pz = *(const float4*)(zrow0 + (size_t)rZ * zstride + kcp);
    float4 pw0 = *(const float4*)(Wp + (size_t)nA * Dd + kcp);
    float4 pw1 = *(const float4*)(Wp + (size_t)nB * Dd + kcp);

    for (int c = 0; c < 32; ++c) {
        __syncthreads();
        *(float4*)(sZ + rZ * SZ_STR + kcp) = pz;
        sW[(kcp + 0) * SW_STR + nA] = pw0.x; sW[(kcp + 1) * SW_STR + nA] = pw0.y;
        sW[(kcp + 2) * SW_STR + nA] = pw0.z; sW[(kcp + 3) * SW_STR + nA] = pw0.w;
        sW[(kcp + 0) * SW_STR + nB] = pw1.x; sW[(kcp + 1) * SW_STR + nB] = pw1.y;
        sW[(kcp + 2) * SW_STR + nB] = pw1.z; sW[(kcp + 3) * SW_STR + nB] = pw1.w;
        __syncthreads();
        if (c < 31) {
            int k0n = (c + 1) * 16 + kcp;
            pz = *(const float4*)(zrow0 + (size_t)rZ * zstride + k0n);
            pw0 = *(const float4*)(Wp + (size_t)nA * Dd + k0n);
            pw1 = *(const float4*)(Wp + (size_t)nB * Dd + k0n);
        }
        #pragma unroll
        for (int kk = 0; kk < 16; ++kk) {
            ull a2[4], w2[4];
            #pragma unroll
            for (int ri = 0; ri < 4; ++ri)
                a2[ri] = pack2b(sZ[(ty * 4 + ri) * SZ_STR + kk]);
            #pragma unroll
            for (int j = 0; j < 4; ++j)
                w2[j] = *(const ull*)(sW + kk * SW_STR + tx * 8 + 2 * j);
            #pragma unroll
            for (int ri = 0; ri < 4; ++ri)
                #pragma unroll
                for (int j = 0; j < 4; ++j)
                    ffma2(acc2[ri][j], a2[ri], w2[j]);
        }
    }
    {
        float bb[8], pp[8];
        #pragma unroll
        for (int ci = 0; ci < 8; ++ci) {
            bb[ci] = bp[tx * 8 + ci];
            pp[ci] = p2[tx * 8 + ci];
        }
        #pragma unroll
        for (int ri = 0; ri < 4; ++ri) {
            float p = 0.f;
            #pragma unroll
            for (int j = 0; j < 4; ++j) {
                float2 t = unpack2(acc2[ri][j]);
                p += tanhf(t.x + bb[2 * j]) * pp[2 * j];
                p += tanhf(t.y + bb[2 * j + 1]) * pp[2 * j + 1];
            }
            sPart[(ty * 4 + ri) * 16 + tx] = p;
        }
    }
    __syncthreads();
    if (tid < 64) {
        float a = 0.f;
        #pragma unroll
        for (int j = 0; j < 16; ++j) a += sPart[tid * 16 + j];
        sc[outbase + tid] = a;
    }
}

__global__ __launch_bounds__(256) void k_sem_comb1()
{
    int b = blockIdx.x;
    int tid = threadIdx.x;
    float s0 = g_sc1[0 * Bb + b], s1 = g_sc1[1 * Bb + b];
    float s2 = g_sc1[2 * Bb + b], s3 = g_sc1[3 * Bb + b], s4 = g_sc1[4 * Bb + b];
    float mx0 = fmaxf(s0, s1);
    float e0 = expf(s0 - mx0), e1 = expf(s1 - mx0);
    float i0 = 1.f / (e0 + e1);
    float b00 = e0 * i0, b01 = e1 * i0;
    float mx1 = fmaxf(fmaxf(s2, s3), s4);
    float f0 = expf(s2 - mx1), f1 = expf(s3 - mx1), f2 = expf(s4 - mx1);
    float i1 = 1.f / (f0 + f1 + f2);
    float b10 = f0 * i1, b11 = f1 * i1, b12 = f2 * i1;
    for (int d = tid; d < Dd; d += 256) {
        float z0 = b00 * g_out[(0 * Bb + b) * Dd + d] + b01 * g_out[(1 * Bb + b) * Dd + d];
        float z1 = b10 * g_out[(2 * Bb + b) * Dd + d] + b11 * g_out[(3 * Bb + b) * Dd + d]
                 + b12 * g_out[(4 * Bb + b) * Dd + d];
        g_mp[(b * 2 + 0) * Dd + d] = z0;
        g_mp[(b * 2 + 1) * Dd + d] = z1;
    }
}

__global__ __launch_bounds__(256) void k_sem_comb2(float* __restrict__ out)
{
    int b = blockIdx.x;
    int tid = threadIdx.x;
    float s0 = g_sc2[b], s1 = g_sc2[Bb + b];
    float mx = fmaxf(s0, s1);
    float e0 = expf(s0 - mx), e1 = expf(s1 - mx);
    float inv = 1.f / (e0 + e1);
    float be0 = e0 * inv, be1 = e1 * inv;
    for (int d = tid; d < Dd; d += 256)
        out[(size_t)b * Dd + d] = be0 * g_mp[(b * 2 + 0) * Dd + d]
                                + be1 * g_mp[(b * 2 + 1) * Dd + d];
}

// ---------------------------------------------------------------------------
extern "C" void kernel_launch(void* const* d_in, const int* in_sizes, int n_in,
                              void* d_out, int out_size)
{
    const float* x    = (const float*)d_in[0];
    const int*   tgt  = (const int*)d_in[1];
    const int*   nbr  = (const int*)d_in[2];
    const float* fc_w = (const float*)d_in[3];
    const float* fc_b = (const float*)d_in[4];
    const float* q_w  = (const float*)d_in[5];
    const float* q_b  = (const float*)d_in[6];
    const float* k_w  = (const float*)d_in[7];
    const float* k_b  = (const float*)d_in[8];
    const float* v_w  = (const float*)d_in[9];
    const float* v_b  = (const float*)d_in[10];
    const float* aW   = (const float*)d_in[11];
    const float* a1w  = (const float*)d_in[12];
    const float* a1b  = (const float*)d_in[13];
    const float* a2w  = (const float*)d_in[14];
    const float* a2b  = (const float*)d_in[15];
    const float* ip1w = (const float*)d_in[16];
    const float* ip1b = (const float*)d_in[17];
    const float* ip2w = (const float*)d_in[18];
    const float* bp1w = (const float*)d_in[19];
    const float* bp1b = (const float*)d_in[20];
    const float* bp2w = (const float*)d_in[21];
    float* out = (float*)d_out;

    (void)in_sizes; (void)n_in; (void)out_size;

    static int configured = 0;
    if (!configured) {
        cudaFuncSetAttribute(k_attn, cudaFuncAttributeMaxDynamicSharedMemorySize,
                             SM_ATTN * 4);
        cudaFuncSetAttribute(k_qkv, cudaFuncAttributeMaxDynamicSharedMemorySize,
                             SM_QKV * 4);
        configured = 1;
    }

    float* d_gout;  cudaGetSymbolAddress((void**)&d_gout, g_out);
    float* d_gmp;   cudaGetSymbolAddress((void**)&d_gmp, g_mp);
    float* d_sc1;   cudaGetSymbolAddress((void**)&d_sc1, g_sc1);
    float* d_sc2;   cudaGetSymbolAddress((void**)&d_sc2, g_sc2);

    k_xconv<<<(Ntot * IN_ / 4) / 256, 256>>>(x);
    k_wconv<<<(Ss * 32 * 64 * 32) / 256, 256>>>(fc_w);
    k_feat<<<dim3(RTOT / 128, 4, Ss), 256>>>(nbr, tgt, fc_b);
    k_qkv<<<dim3(Bb / 64, Ss * HNh), 256, SM_QKV * 4>>>(q_w, q_b, a2w, a2b, aW);
    k_attn<<<dim3(RR / 64, Ss * HNh), 256, SM_ATTN * 4>>>(k_w, k_b, v_w, v_b, a1w, a1b);
    k_sem_score<<<dim3(Bb / 64, Ss), 256>>>(d_gout, ip1w, ip1b, ip2w, d_sc1, 0);
    k_sem_comb1<<<Bb, 256>>>();
    k_sem_score<<<dim3(Bb / 64, 2), 256>>>(d_gmp, bp1w, bp1b, bp2w, d_sc2, 1);
    k_sem_comb2<<<Bb, 256>>>(out);
}

// round 10
// speedup vs baseline: 3.8844x; 1.1822x over previous
#include <cuda_runtime.h>
#include <math.h>

#define Ntot 20000
#define IN_  256
#define Hh   128
#define HNh  4
#define Ss   5
#define Bb   1024
#define Mm   16
#define Dd   512
#define RR   16384
#define RTOT (RR + Bb)
#define LALPHA 0.2f

typedef unsigned long long ull;
typedef unsigned int uint;

__device__ __forceinline__ float lrelu(float z) { return z >= 0.f ? z : LALPHA * z; }

__device__ __forceinline__ ull pack2b(float a) {
    ull r;
    asm("mov.b64 %0, {%1, %1};" : "=l"(r) : "f"(a));
    return r;
}
__device__ __forceinline__ void ffma2(ull& d, ull a, ull b) {
    asm("fma.rn.f32x2 %0, %1, %2, %0;" : "+l"(d) : "l"(a), "l"(b));
}
__device__ __forceinline__ float2 unpack2(ull v) {
    float2 r;
    asm("mov.b64 {%0, %1}, %2;" : "=f"(r.x), "=f"(r.y) : "l"(v));
    return r;
}
__device__ __forceinline__ float cvt_tf32(float x) {
    uint r;
    asm("cvt.rna.tf32.f32 %0, %1;" : "=r"(r) : "f"(x));
    return __uint_as_float(r);
}
__device__ __forceinline__ void mma_tf32(float c[4], const uint a[4], uint b0, uint b1) {
    asm("mma.sync.aligned.m16n8k8.row.col.f32.tf32.tf32.f32 "
        "{%0,%1,%2,%3}, {%4,%5,%6,%7}, {%8,%9}, {%0,%1,%2,%3};"
        : "+f"(c[0]), "+f"(c[1]), "+f"(c[2]), "+f"(c[3])
        : "r"(a[0]), "r"(a[1]), "r"(a[2]), "r"(a[3]), "r"(b0), "r"(b1));
}

// scratch
__device__ float g_xsh[Ss * HNh * Bb * Hh];
__device__ float g_wh2[Ss * HNh * Bb * Hh];
__device__ float g_out[Ss * Bb * Dd];
__device__ float g_feat[(size_t)Ss * RR * Dd];
__device__ float g_mp[Bb * 2 * Dd];
__device__ float g_sc1[Ss * Bb];
__device__ float g_sc2[2 * Bb];
__device__ float g_xhi[(size_t)Ntot * IN_];
__device__ float g_xlo[(size_t)Ntot * IN_];
__device__ float g_wfrag[Ss * 32 * 64 * 32 * 4];   // [s][k8][j][lane][4]={b0h,b1h,b0l,b1l}
__device__ float g_wc1[Ss * HNh * Hh * Hh];        // combined a1w@k_w
__device__ float g_bc1[Ss * HNh * Hh];             // combined a1w@k_b + a1b
__device__ float g_wc2[Ss * HNh * Hh * Hh];        // combined a2w@q_w
__device__ float g_bc2[Ss * HNh * Hh];             // combined a2w@q_b + a2b

// ---------------------------------------------------------------------------
// Pre-kernels: tf32 hi/lo decomposition (for k_feat)
// ---------------------------------------------------------------------------
__global__ __launch_bounds__(256) void k_xconv(const float* __restrict__ x)
{
    size_t i = (size_t)blockIdx.x * 256 + threadIdx.x;
    float4 v = ((const float4*)x)[i];
    float4 h, l;
    h.x = cvt_tf32(v.x); l.x = cvt_tf32(v.x - h.x);
    h.y = cvt_tf32(v.y); l.y = cvt_tf32(v.y - h.y);
    h.z = cvt_tf32(v.z); l.z = cvt_tf32(v.z - h.z);
    h.w = cvt_tf32(v.w); l.w = cvt_tf32(v.w - h.w);
    ((float4*)g_xhi)[i] = h;
    ((float4*)g_xlo)[i] = l;
}

__global__ __launch_bounds__(256) void k_wconv(const float* __restrict__ fc_w)
{
    int idx = blockIdx.x * 256 + threadIdx.x;
    int lane = idx & 31;
    int t = idx >> 5;
    int j = t & 63; t >>= 6;
    int k8 = t & 31;
    int s = t >> 5;
    int n = 8 * j + (lane >> 2);
    int k0 = 8 * k8 + (lane & 3);
    const float* W = fc_w + ((size_t)s * 512 + n) * IN_;
    float w0 = W[k0], w1 = W[k0 + 4];
    float h0 = cvt_tf32(w0), h1 = cvt_tf32(w1);
    float l0 = cvt_tf32(w0 - h0), l1 = cvt_tf32(w1 - h1);
    float4 o = {h0, h1, l0, l1};
    ((float4*)g_wfrag)[idx] = o;
}

// ---------------------------------------------------------------------------
// Pre-kernel: combined weights. C[o][i] = sum_j A[o][j] * B[j][i]
// bc[o] = sum_j A[o][j] * Bb[j] + Ab[o]
// A indexed [km][h], B/Bb indexed [s][h]. One block per (s,h).
// ---------------------------------------------------------------------------
__global__ __launch_bounds__(256) void k_comb(
    const float* __restrict__ Aw, const float* __restrict__ Ab,
    const float* __restrict__ Bw, const float* __restrict__ Bbias,
    float* __restrict__ Wc, float* __restrict__ bc)
{
    __shared__ float sB[32 * 132];
    int sh = blockIdx.x;
    int s = sh >> 2, h = sh & 3;
    int km = (s >= 2) ? 1 : 0;
    const float* A = Aw + (size_t)(km * HNh + h) * Hh * Hh;
    const float* B = Bw + (size_t)(s * HNh + h) * Hh * Hh;
    float* C = Wc + (size_t)(s * HNh + h) * Hh * Hh;
    int tid = threadIdx.x;
    int o = tid >> 1, half = tid & 1;

    float acc[64];
    #pragma unroll
    for (int i = 0; i < 64; ++i) acc[i] = 0.f;

    for (int c = 0; c < 4; ++c) {
        __syncthreads();
        #pragma unroll
        for (int u = 0; u < 4; ++u) {
            int idx = tid + 256 * u;
            int row = idx >> 5, c4 = (idx & 31) << 2;
            *(float4*)(sB + row * 132 + c4) = *(const float4*)(B + (c * 32 + row) * Hh + c4);
        }
        __syncthreads();
        for (int j = 0; j < 32; ++j) {
            float a = A[o * Hh + c * 32 + j];
            const float* br = sB + j * 132 + half * 64;
            #pragma unroll
            for (int i = 0; i < 64; ++i)
                acc[i] += a * br[i];
        }
    }
    #pragma unroll
    for (int i = 0; i < 64; ++i)
        C[o * Hh + half * 64 + i] = acc[i];

    if (half == 0) {
        const float* bbv = Bbias + (s * HNh + h) * Hh;
        float bsum = Ab[(km * HNh + h) * Hh + o];
        for (int j = 0; j < Hh; ++j)
            bsum += A[o * Hh + j] * bbv[j];
        bc[(s * HNh + h) * Hh + o] = bsum;
    }
}

// ---------------------------------------------------------------------------
// Kernel 1: feat GEMM via mma.sync tf32 (3xTF32). (unchanged from R7)
// ---------------------------------------------------------------------------
#define APLN 36

__global__ __launch_bounds__(256) void k_feat(
    const int* __restrict__ nbr, const int* __restrict__ tgt,
    const float* __restrict__ fc_b)
{
    __shared__ float sAf[256 * APLN];
    __shared__ int sIdx[128];

    int m0 = blockIdx.x * 128;
    int n0 = blockIdx.y * 128;
    int s  = blockIdx.z;
    int tid = threadIdx.x;
    int warp = tid >> 5, L = tid & 31;
    int wm = warp & 3, wn = warp >> 2;
    int g = L >> 2, c4 = L & 3;

    if (tid < 128) {
        int r = m0 + tid;
        sIdx[tid] = (r < RR) ? nbr[s * RR + r] : tgt[r - RR];
    }
    __syncthreads();

    float acc[2][8][4];
    #pragma unroll
    for (int mi = 0; mi < 2; ++mi)
        #pragma unroll
        for (int jl = 0; jl < 8; ++jl)
            #pragma unroll
            for (int e = 0; e < 4; ++e) acc[mi][jl][e] = 0.f;

    const float* wf = g_wfrag + (size_t)s * 32 * 64 * 32 * 4;
    int jbase = (n0 >> 3) + wn * 8;

    float4 ah[4], al[4];
    #pragma unroll
    for (int u = 0; u < 4; ++u) {
        int idx = tid + 256 * u;
        int row = idx >> 3, kq = idx & 7;
        size_t o = (size_t)sIdx[row] * IN_ + 4 * kq;
        ah[u] = *(const float4*)(g_xhi + o);
        al[u] = *(const float4*)(g_xlo + o);
    }
    float4 bp[8];
    #pragma unroll
    for (int jl = 0; jl < 8; ++jl)
        bp[jl] = *(const float4*)(wf + ((size_t)(0 * 64 + jbase + jl) * 32 + L) * 4);

    for (int ch = 0; ch < 8; ++ch) {
        __syncthreads();
        #pragma unroll
        for (int u = 0; u < 4; ++u) {
            int idx = tid + 256 * u;
            int row = idx >> 3, kq = idx & 7;
            int q = kq >> 1;
            int mt = row >> 4;
            int r = row & 15;
            int reg = ((r >> 3) & 1) | ((kq & 1) << 1);
            int gg = r & 7;
            int p0 = ((q * 8 + mt) * 2 + 0) * 4 + reg;
            int p1 = ((q * 8 + mt) * 2 + 1) * 4 + reg;
            *(float4*)(sAf + p0 * APLN + 4 * gg) = ah[u];
            *(float4*)(sAf + p1 * APLN + 4 * gg) = al[u];
        }
        __syncthreads();
        if (ch < 7) {
            #pragma unroll
            for (int u = 0; u < 4; ++u) {
                int idx = tid + 256 * u;
                int row = idx >> 3, kq = idx & 7;
                size_t o = (size_t)sIdx[row] * IN_ + (ch + 1) * 32 + 4 * kq;
                ah[u] = *(const float4*)(g_xhi + o);
                al[u] = *(const float4*)(g_xlo + o);
            }
        }
        #pragma unroll
        for (int q = 0; q < 4; ++q) {
            float4 bc[8];
            #pragma unroll
            for (int jl = 0; jl < 8; ++jl) bc[jl] = bp[jl];
            int nk8 = ch * 4 + q + 1;
            if (nk8 < 32) {
                #pragma unroll
                for (int jl = 0; jl < 8; ++jl)
                    bp[jl] = *(const float4*)(wf + ((size_t)(nk8 * 64 + jbase + jl) * 32 + L) * 4);
            }
            uint afh[2][4], afl[2][4];
            #pragma unroll
            for (int mi = 0; mi < 2; ++mi) {
                int mt = 2 * wm + mi;
                int pb = ((q * 8 + mt) * 2) * 4;
                #pragma unroll
                for (int rg = 0; rg < 4; ++rg) {
                    afh[mi][rg] = __float_as_uint(sAf[(pb + rg) * APLN + L]);
                    afl[mi][rg] = __float_as_uint(sAf[(pb + 4 + rg) * APLN + L]);
                }
            }
            #pragma unroll
            for (int mi = 0; mi < 2; ++mi)
                #pragma unroll
                for (int jl = 0; jl < 8; ++jl) {
                    uint bh0 = __float_as_uint(bc[jl].x), bh1 = __float_as_uint(bc[jl].y);
                    uint bl0 = __float_as_uint(bc[jl].z), bl1 = __float_as_uint(bc[jl].w);
                    mma_tf32(acc[mi][jl], afh[mi], bh0, bh1);
                    mma_tf32(acc[mi][jl], afh[mi], bl0, bl1);
                    mma_tf32(acc[mi][jl], afl[mi], bh0, bh1);
                }
        }
    }

    #pragma unroll
    for (int mi = 0; mi < 2; ++mi) {
        int rbase = 32 * wm + 16 * mi + g;
        #pragma unroll
        for (int jl = 0; jl < 8; ++jl) {
            int col = 64 * wn + 8 * jl + 2 * c4;
            float b0v = fc_b[s * 512 + n0 + col];
            float b1v = fc_b[s * 512 + n0 + col + 1];
            float2 v0 = {lrelu(acc[mi][jl][0] + b0v), lrelu(acc[mi][jl][1] + b1v)};
            float2 v1 = {lrelu(acc[mi][jl][2] + b0v), lrelu(acc[mi][jl][3] + b1v)};
            if (m0 < RR) {
                int r = m0 + rbase;
                *(float2*)(g_feat + ((size_t)s * RR + r) * Dd + n0 + col) = v0;
                *(float2*)(g_feat + ((size_t)s * RR + r + 8) * Dd + n0 + col) = v1;
            } else {
                int h = n0 >> 7;
                int b = m0 - RR + rbase;
                *(float2*)(g_xsh + ((size_t)(s * HNh + h) * Bb + b) * Hh + col) = v0;
                *(float2*)(g_xsh + ((size_t)(s * HNh + h) * Bb + b + 8) * Hh + col) = v1;
            }
        }
    }
}

// ---------------------------------------------------------------------------
// shared FFMA2 64x128x128 micro-kernel
// ---------------------------------------------------------------------------
#define SW_STR 132
#define T_STR 132
#define SM_QKV 19008
#define SM_ATTN 15424

__device__ __forceinline__ void gemm128_f2(
    const float* __restrict__ sIn, const float* __restrict__ Wg,
    float* __restrict__ sWbuf, ull acc2[4][4],
    int tid, int tx, int ty)
{
    int kcp = (tid & 3) << 2;
    int nA = tid >> 2, nB = nA + 64;
    #pragma unroll
    for (int ri = 0; ri < 4; ++ri)
        #pragma unroll
        for (int j = 0; j < 4; ++j) acc2[ri][j] = 0ull;

    float4 p0 = *(const float4*)(Wg + nA * Hh + kcp);
    float4 p1 = *(const float4*)(Wg + nB * Hh + kcp);
    for (int c = 0; c < 8; ++c) {
        __syncthreads();
        sWbuf[(kcp + 0) * T_STR + nA] = p0.x; sWbuf[(kcp + 1) * T_STR + nA] = p0.y;
        sWbuf[(kcp + 2) * T_STR + nA] = p0.z; sWbuf[(kcp + 3) * T_STR + nA] = p0.w;
        sWbuf[(kcp + 0) * T_STR + nB] = p1.x; sWbuf[(kcp + 1) * T_STR + nB] = p1.y;
        sWbuf[(kcp + 2) * T_STR + nB] = p1.z; sWbuf[(kcp + 3) * T_STR + nB] = p1.w;
        __syncthreads();
        if (c < 7) {
            int k0n = (c + 1) * 16 + kcp;
            p0 = *(const float4*)(Wg + nA * Hh + k0n);
            p1 = *(const float4*)(Wg + nB * Hh + k0n);
        }
        int k0 = c * 16;
        #pragma unroll
        for (int kk = 0; kk < 16; ++kk) {
            ull a2[4], w2[4];
            #pragma unroll
            for (int ri = 0; ri < 4; ++ri)
                a2[ri] = pack2b(sIn[(ty * 4 + ri) * T_STR + k0 + kk]);
            #pragma unroll
            for (int j = 0; j < 4; ++j)
                w2[j] = *(const ull*)(sWbuf + kk * T_STR + tx * 8 + 2 * j);
            #pragma unroll
            for (int ri = 0; ri < 4; ++ri)
                #pragma unroll
                for (int j = 0; j < 4; ++j)
                    ffma2(acc2[ri][j], a2[ri], w2[j]);
        }
    }
}

// ---------------------------------------------------------------------------
// Kernel 2: qkv chain — now 2 GEMMs: h2 = lrelu(xsh@Wc2^T+bc2); wh2 = h2@aW^T
// ---------------------------------------------------------------------------
__global__ __launch_bounds__(256, 2) void k_qkv(
    const float* __restrict__ wc2, const float* __restrict__ bc2,
    const float* __restrict__ aW)
{
    extern __shared__ __align__(16) float sm[];
    float* sA = sm;
    float* sQ = sm + 8448;
    float* sW = sm + 16896;

    int sh = blockIdx.y;
    int s = sh >> 2, h = sh & 3;
    int km = (s >= 2) ? 1 : 0;
    int b0 = blockIdx.x * 64;
    int tid = threadIdx.x;
    int tx = tid & 15, ty = tid >> 4;

    int who = (s * HNh + h) * Hh;
    int aho = (km * HNh + h) * Hh;
    const float* Wc = wc2 + (size_t)who * Hh;
    const float* Ww = aW + (size_t)aho * Hh;

    #pragma unroll
    for (int i = 0; i < 8; ++i) {
        int lid = tid + i * 256;
        int row = lid >> 5, c4 = (lid & 31) << 2;
        float4 v = *(const float4*)(g_xsh + ((size_t)(s * HNh + h) * Bb + b0 + row) * Hh + c4);
        *(float4*)(sA + row * T_STR + c4) = v;
    }

    ull acc2[4][4];

    // GEMM1: h2 = lrelu(xsh @ Wc2^T + bc2) -> sQ
    gemm128_f2(sA, Wc, sW, acc2, tid, tx, ty);
    {
        float4 b0v = *(const float4*)(bc2 + who + tx * 8);
        float4 b1v = *(const float4*)(bc2 + who + tx * 8 + 4);
        float bb[8] = {b0v.x, b0v.y, b0v.z, b0v.w, b1v.x, b1v.y, b1v.z, b1v.w};
        #pragma unroll
        for (int ri = 0; ri < 4; ++ri) {
            float vv[8];
            #pragma unroll
            for (int j = 0; j < 4; ++j) {
                float2 t = unpack2(acc2[ri][j]);
                vv[2 * j] = lrelu(t.x + bb[2 * j]);
                vv[2 * j + 1] = lrelu(t.y + bb[2 * j + 1]);
            }
            float4 v0 = {vv[0], vv[1], vv[2], vv[3]};
            float4 v1 = {vv[4], vv[5], vv[6], vv[7]};
            *(float4*)(sQ + (ty * 4 + ri) * T_STR + tx * 8) = v0;
            *(float4*)(sQ + (ty * 4 + ri) * T_STR + tx * 8 + 4) = v1;
        }
    }

    // GEMM2: wh2 = h2 @ aW^T -> g_wh2
    gemm128_f2(sQ, Ww, sW, acc2, tid, tx, ty);
    #pragma unroll
    for (int ri = 0; ri < 4; ++ri) {
        int b = b0 + ty * 4 + ri;
        float* dst = g_wh2 + ((size_t)(s * HNh + h) * Bb + b) * Hh + tx * 8;
        float vv[8];
        #pragma unroll
        for (int j = 0; j < 4; ++j) {
            float2 t = unpack2(acc2[ri][j]);
            vv[2 * j] = t.x; vv[2 * j + 1] = t.y;
        }
        float4 v0 = {vv[0], vv[1], vv[2], vv[3]};
        float4 v1 = {vv[4], vv[5], vv[6], vv[7]};
        *(float4*)(dst) = v0;
        *(float4*)(dst + 4) = v1;
    }
}

// ---------------------------------------------------------------------------
// Kernel 3: fused attention — SINGLE merged pass:
//   h1acc = feat @ Wc1^T (combined kh->h1), vhacc = feat @ v_w^T
// then att = sum lrelu(h1acc+bc1)*wh2, softmax, h = sum lrelu(vh*e)
// smem floats: sF 8448 | sWk 2112 | sWv 2112 | sW2 512 | sHp 2112 | sAtt 64 | sE 64 = 15424
// ---------------------------------------------------------------------------
__global__ __launch_bounds__(256, 2) void k_attn(
    const float* __restrict__ wc1, const float* __restrict__ bc1,
    const float* __restrict__ v_w, const float* __restrict__ v_b)
{
    extern __shared__ __align__(16) float sm[];
    float* sF   = sm;
    float* sWk  = sm + 8448;
    float* sWv  = sm + 10560;
    float* sW2  = sm + 12672;
    float* sHp  = sm + 13184;
    float* sAtt = sm + 15296;
    float* sE   = sm + 15360;

    int sh = blockIdx.y;
    int s = sh >> 2, h = sh & 3;
    int r0 = blockIdx.x * 64;
    int b0 = r0 >> 4;
    int tid = threadIdx.x;
    int tx = tid & 15, ty = tid >> 4;

    #pragma unroll
    for (int i = 0; i < 8; ++i) {
        int lid = tid + i * 256;
        int row = lid >> 5, c4 = (lid & 31) << 2;
        float4 v = *(const float4*)(g_feat + ((size_t)s * RR + r0 + row) * Dd + h * Hh + c4);
        *(float4*)(sF + row * T_STR + c4) = v;
    }
    #pragma unroll
    for (int i = 0; i < 2; ++i) {
        int lid = tid + i * 256;
        int bg = lid >> 7, o = lid & 127;
        sW2[lid] = g_wh2[((s * HNh + h) * Bb + b0 + bg) * Hh + o];
    }

    int who = (s * HNh + h) * Hh;
    const float* Wc = wc1 + (size_t)who * Hh;
    const float* Wv = v_w + (size_t)who * Hh;

    int kcp = (tid & 3) << 2;
    int nA = tid >> 2, nB = nA + 64;

    ull ak2[4][4], av2[4][4];
    #pragma unroll
    for (int ri = 0; ri < 4; ++ri)
        #pragma unroll
        for (int j = 0; j < 4; ++j) { ak2[ri][j] = 0ull; av2[ri][j] = 0ull; }

    float4 pk0 = *(const float4*)(Wc + nA * Hh + kcp);
    float4 pk1 = *(const float4*)(Wc + nB * Hh + kcp);
    float4 pv0 = *(const float4*)(Wv + nA * Hh + kcp);
    float4 pv1 = *(const float4*)(Wv + nB * Hh + kcp);

    // single merged pass: h1acc + vhacc
    for (int c = 0; c < 8; ++c) {
        __syncthreads();
        sWk[(kcp + 0) * T_STR + nA] = pk0.x; sWk[(kcp + 1) * T_STR + nA] = pk0.y;
        sWk[(kcp + 2) * T_STR + nA] = pk0.z; sWk[(kcp + 3) * T_STR + nA] = pk0.w;
        sWk[(kcp + 0) * T_STR + nB] = pk1.x; sWk[(kcp + 1) * T_STR + nB] = pk1.y;
        sWk[(kcp + 2) * T_STR + nB] = pk1.z; sWk[(kcp + 3) * T_STR + nB] = pk1.w;
        sWv[(kcp + 0) * T_STR + nA] = pv0.x; sWv[(kcp + 1) * T_STR + nA] = pv0.y;
        sWv[(kcp + 2) * T_STR + nA] = pv0.z; sWv[(kcp + 3) * T_STR + nA] = pv0.w;
        sWv[(kcp + 0) * T_STR + nB] = pv1.x; sWv[(kcp + 1) * T_STR + nB] = pv1.y;
        sWv[(kcp + 2) * T_STR + nB] = pv1.z; sWv[(kcp + 3) * T_STR + nB] = pv1.w;
        __syncthreads();
        if (c < 7) {
            int k0n = (c + 1) * 16 + kcp;
            pk0 = *(const float4*)(Wc + nA * Hh + k0n);
            pk1 = *(const float4*)(Wc + nB * Hh + k0n);
            pv0 = *(const float4*)(Wv + nA * Hh + k0n);
            pv1 = *(const float4*)(Wv + nB * Hh + k0n);
        }
        int k0 = c * 16;
        #pragma unroll
        for (int kk = 0; kk < 16; ++kk) {
            ull a2[4], wk2[4], wv2[4];
            #pragma unroll
            for (int ri = 0; ri < 4; ++ri)
                a2[ri] = pack2b(sF[(ty * 4 + ri) * T_STR + k0 + kk]);
            #pragma unroll
            for (int j = 0; j < 4; ++j) {
                wk2[j] = *(const ull*)(sWk + kk * T_STR + tx * 8 + 2 * j);
                wv2[j] = *(const ull*)(sWv + kk * T_STR + tx * 8 + 2 * j);
            }
            #pragma unroll
            for (int ri = 0; ri < 4; ++ri)
                #pragma unroll
                for (int j = 0; j < 4; ++j) {
                    ffma2(ak2[ri][j], a2[ri], wk2[j]);
                    ffma2(av2[ri][j], a2[ri], wv2[j]);
                }
        }
    }

    // vh = vhacc + v_b (registers)
    float av[4][8];
    {
        float4 c0v = *(const float4*)(v_b + who + tx * 8);
        float4 c1v = *(const float4*)(v_b + who + tx * 8 + 4);
        float cc[8] = {c0v.x, c0v.y, c0v.z, c0v.w, c1v.x, c1v.y, c1v.z, c1v.w};
        #pragma unroll
        for (int ri = 0; ri < 4; ++ri)
            #pragma unroll
            for (int j = 0; j < 4; ++j) {
                float2 t = unpack2(av2[ri][j]);
                av[ri][2 * j] = t.x + cc[2 * j];
                av[ri][2 * j + 1] = t.y + cc[2 * j + 1];
            }
    }

    // att partials: p = sum lrelu(h1acc + bc1) * wh2
    {
        float4 b0v = *(const float4*)(bc1 + who + tx * 8);
        float4 b1v = *(const float4*)(bc1 + who + tx * 8 + 4);
        float bb[8] = {b0v.x, b0v.y, b0v.z, b0v.w, b1v.x, b1v.y, b1v.z, b1v.w};
        int bg = ty >> 2;
        #pragma unroll
        for (int ri = 0; ri < 4; ++ri) {
            float p = 0.f;
            #pragma unroll
            for (int j = 0; j < 4; ++j) {
                float2 t = unpack2(ak2[ri][j]);
                p += lrelu(t.x + bb[2 * j]) * sW2[bg * 128 + tx * 8 + 2 * j];
                p += lrelu(t.y + bb[2 * j + 1]) * sW2[bg * 128 + tx * 8 + 2 * j + 1];
            }
            sHp[(ty * 4 + ri) * 16 + tx] = p;
        }
    }
    __syncthreads();
    if (tid < 64) {
        float a = 0.f;
        #pragma unroll
        for (int j = 0; j < 16; ++j) a += sHp[tid * 16 + j];
        sAtt[tid] = a;
    }
    __syncthreads();
    if (tid < 4) {
        float mx = -1e30f;
        #pragma unroll
        for (int m = 0; m < Mm; ++m) mx = fmaxf(mx, sAtt[tid * 16 + m]);
        float sum = 0.f, ee[Mm];
        #pragma unroll
        for (int m = 0; m < Mm; ++m) { ee[m] = expf(sAtt[tid * 16 + m] - mx); sum += ee[m]; }
        float inv = 1.f / sum;
        #pragma unroll
        for (int m = 0; m < Mm; ++m) sE[tid * 16 + m] = ee[m] * inv;
    }
    __syncthreads();

    {
        int bg = ty >> 2;
        float hp[8];
        #pragma unroll
        for (int ci = 0; ci < 8; ++ci) hp[ci] = 0.f;
        #pragma unroll
        for (int ri = 0; ri < 4; ++ri) {
            int m = (ty * 4 + ri) & 15;
            float e = sE[bg * 16 + m];
            #pragma unroll
            for (int ci = 0; ci < 8; ++ci)
                hp[ci] += lrelu(av[ri][ci] * e);
        }
        #pragma unroll
        for (int ci = 0; ci < 8; ++ci)
            sHp[ty * T_STR + tx * 8 + ci] = hp[ci];
    }
    __syncthreads();
    #pragma unroll
    for (int i = 0; i < 2; ++i) {
        int lid = tid + i * 256;
        int bg = lid >> 7, o = lid & 127;
        float hsum = sHp[(bg * 4 + 0) * T_STR + o] + sHp[(bg * 4 + 1) * T_STR + o]
                   + sHp[(bg * 4 + 2) * T_STR + o] + sHp[(bg * 4 + 3) * T_STR + o];
        float xs = g_xsh[((s * HNh + h) * Bb + b0 + bg) * Hh + o];
        g_out[((size_t)s * Bb + b0 + bg) * Dd + h * Hh + o] = 0.5f * (xs + hsum);
    }
}

// ---------------------------------------------------------------------------
// Semantic attention (unchanged)
// ---------------------------------------------------------------------------
#define SZ_STR 20

__global__ __launch_bounds__(256) void k_sem_score(
    const float* __restrict__ zbase,
    const float* __restrict__ p1w, const float* __restrict__ p1b,
    const float* __restrict__ p2w,
    float* __restrict__ sc,
    int mode)
{
    __shared__ __align__(16) float sZ[64 * SZ_STR];
    __shared__ __align__(16) float sW[16 * SW_STR];
    __shared__ float sPart[64 * 16];

    int gy = blockIdx.y;
    int b0 = blockIdx.x * 64;
    int tid = threadIdx.x;
    int tx = tid & 15, ty = tid >> 4;

    int wsel, outbase;
    const float* zrow0;
    size_t zstride;
    if (mode == 0) {
        int s = gy;
        wsel = (s >= 2) ? 1 : 0;
        zrow0 = zbase + ((size_t)s * Bb + b0) * Dd;
        zstride = Dd;
        outbase = s * Bb + b0;
    } else {
        int k2 = gy;
        wsel = 0;
        zrow0 = zbase + ((size_t)b0 * 2 + k2) * Dd;
        zstride = 2 * Dd;
        outbase = k2 * Bb + b0;
    }
    const float* Wp = p1w + (size_t)wsel * Hh * Dd;
    const float* bp = p1b + wsel * Hh;
    const float* p2 = p2w + wsel * Hh;

    int kcp = (tid & 3) << 2;
    int rZ = tid >> 2;
    int nA = tid >> 2, nB = nA + 64;

    ull acc2[4][4];
    #pragma unroll
    for (int ri = 0; ri < 4; ++ri)
        #pragma unroll
        for (int j = 0; j < 4; ++j) acc2[ri][j] = 0ull;

    float4 pz = *(const float4*)(zrow0 + (size_t)rZ * zstride + kcp);
    float4 pw0 = *(const float4*)(Wp + (size_t)nA * Dd + kcp);
    float4 pw1 = *(const float4*)(Wp + (size_t)nB * Dd + kcp);

    for (int c = 0; c < 32; ++c) {
        __syncthreads();
        *(float4*)(sZ + rZ * SZ_STR + kcp) = pz;
        sW[(kcp + 0) * SW_STR + nA] = pw0.x; sW[(kcp + 1) * SW_STR + nA] = pw0.y;
        sW[(kcp + 2) * SW_STR + nA] = pw0.z; sW[(kcp + 3) * SW_STR + nA] = pw0.w;
        sW[(kcp + 0) * SW_STR + nB] = pw1.x; sW[(kcp + 1) * SW_STR + nB] = pw1.y;
        sW[(kcp + 2) * SW_STR + nB] = pw1.z; sW[(kcp + 3) * SW_STR + nB] = pw1.w;
        __syncthreads();
        if (c < 31) {
            int k0n = (c + 1) * 16 + kcp;
            pz = *(const float4*)(zrow0 + (size_t)rZ * zstride + k0n);
            pw0 = *(const float4*)(Wp + (size_t)nA * Dd + k0n);
            pw1 = *(const float4*)(Wp + (size_t)nB * Dd + k0n);
        }
        #pragma unroll
        for (int kk = 0; kk < 16; ++kk) {
            ull a2[4], w2[4];
            #pragma unroll
            for (int ri = 0; ri < 4; ++ri)
                a2[ri] = pack2b(sZ[(ty * 4 + ri) * SZ_STR + kk]);
            #pragma unroll
            for (int j = 0; j < 4; ++j)
                w2[j] = *(const ull*)(sW + kk * SW_STR + tx * 8 + 2 * j);
            #pragma unroll
            for (int ri = 0; ri < 4; ++ri)
                #pragma unroll
                for (int j = 0; j < 4; ++j)
                    ffma2(acc2[ri][j], a2[ri], w2[j]);
        }
    }
    {
        float bb[8], pp[8];
        #pragma unroll
        for (int ci = 0; ci < 8; ++ci) {
            bb[ci] = bp[tx * 8 + ci];
            pp[ci] = p2[tx * 8 + ci];
        }
        #pragma unroll
        for (int ri = 0; ri < 4; ++ri) {
            float p = 0.f;
            #pragma unroll
            for (int j = 0; j < 4; ++j) {
                float2 t = unpack2(acc2[ri][j]);
                p += tanhf(t.x + bb[2 * j]) * pp[2 * j];
                p += tanhf(t.y + bb[2 * j + 1]) * pp[2 * j + 1];
            }
            sPart[(ty * 4 + ri) * 16 + tx] = p;
        }
    }
    __syncthreads();
    if (tid < 64) {
        float a = 0.f;
        #pragma unroll
        for (int j = 0; j < 16; ++j) a += sPart[tid * 16 + j];
        sc[outbase + tid] = a;
    }
}

__global__ __launch_bounds__(256) void k_sem_comb1()
{
    int b = blockIdx.x;
    int tid = threadIdx.x;
    float s0 = g_sc1[0 * Bb + b], s1 = g_sc1[1 * Bb + b];
    float s2 = g_sc1[2 * Bb + b], s3 = g_sc1[3 * Bb + b], s4 = g_sc1[4 * Bb + b];
    float mx0 = fmaxf(s0, s1);
    float e0 = expf(s0 - mx0), e1 = expf(s1 - mx0);
    float i0 = 1.f / (e0 + e1);
    float b00 = e0 * i0, b01 = e1 * i0;
    float mx1 = fmaxf(fmaxf(s2, s3), s4);
    float f0 = expf(s2 - mx1), f1 = expf(s3 - mx1), f2 = expf(s4 - mx1);
    float i1 = 1.f / (f0 + f1 + f2);
    float b10 = f0 * i1, b11 = f1 * i1, b12 = f2 * i1;
    for (int d = tid; d < Dd; d += 256) {
        float z0 = b00 * g_out[(0 * Bb + b) * Dd + d] + b01 * g_out[(1 * Bb + b) * Dd + d];
        float z1 = b10 * g_out[(2 * Bb + b) * Dd + d] + b11 * g_out[(3 * Bb + b) * Dd + d]
                 + b12 * g_out[(4 * Bb + b) * Dd + d];
        g_mp[(b * 2 + 0) * Dd + d] = z0;
        g_mp[(b * 2 + 1) * Dd + d] = z1;
    }
}

__global__ __launch_bounds__(256) void k_sem_comb2(float* __restrict__ out)
{
    int b = blockIdx.x;
    int tid = threadIdx.x;
    float s0 = g_sc2[b], s1 = g_sc2[Bb + b];
    float mx = fmaxf(s0, s1);
    float e0 = expf(s0 - mx), e1 = expf(s1 - mx);
    float inv = 1.f / (e0 + e1);
    float be0 = e0 * inv, be1 = e1 * inv;
    for (int d = tid; d < Dd; d += 256)
        out[(size_t)b * Dd + d] = be0 * g_mp[(b * 2 + 0) * Dd + d]
                                + be1 * g_mp[(b * 2 + 1) * Dd + d];
}

// ---------------------------------------------------------------------------
extern "C" void kernel_launch(void* const* d_in, const int* in_sizes, int n_in,
                              void* d_out, int out_size)
{
    const float* x    = (const float*)d_in[0];
    const int*   tgt  = (const int*)d_in[1];
    const int*   nbr  = (const int*)d_in[2];
    const float* fc_w = (const float*)d_in[3];
    const float* fc_b = (const float*)d_in[4];
    const float* q_w  = (const float*)d_in[5];
    const float* q_b  = (const float*)d_in[6];
    const float* k_w  = (const float*)d_in[7];
    const float* k_b  = (const float*)d_in[8];
    const float* v_w  = (const float*)d_in[9];
    const float* v_b  = (const float*)d_in[10];
    const float* aW   = (const float*)d_in[11];
    const float* a1w  = (const float*)d_in[12];
    const float* a1b  = (const float*)d_in[13];
    const float* a2w  = (const float*)d_in[14];
    const float* a2b  = (const float*)d_in[15];
    const float* ip1w = (const float*)d_in[16];
    const float* ip1b = (const float*)d_in[17];
    const float* ip2w = (const float*)d_in[18];
    const float* bp1w = (const float*)d_in[19];
    const float* bp1b = (const float*)d_in[20];
    const float* bp2w = (const float*)d_in[21];
    float* out = (float*)d_out;

    (void)in_sizes; (void)n_in; (void)out_size;

    static int configured = 0;
    if (!configured) {
        cudaFuncSetAttribute(k_attn, cudaFuncAttributeMaxDynamicSharedMemorySize,
                             SM_ATTN * 4);
        cudaFuncSetAttribute(k_qkv, cudaFuncAttributeMaxDynamicSharedMemorySize,
                             SM_QKV * 4);
        configured = 1;
    }

    float* d_gout;  cudaGetSymbolAddress((void**)&d_gout, g_out);
    float* d_gmp;   cudaGetSymbolAddress((void**)&d_gmp, g_mp);
    float* d_sc1;   cudaGetSymbolAddress((void**)&d_sc1, g_sc1);
    float* d_sc2;   cudaGetSymbolAddress((void**)&d_sc2, g_sc2);
    float* d_wc1;   cudaGetSymbolAddress((void**)&d_wc1, g_wc1);
    float* d_bc1;   cudaGetSymbolAddress((void**)&d_bc1, g_bc1);
    float* d_wc2;   cudaGetSymbolAddress((void**)&d_wc2, g_wc2);
    float* d_bc2;   cudaGetSymbolAddress((void**)&d_bc2, g_bc2);

    k_xconv<<<(Ntot * IN_ / 4) / 256, 256>>>(x);
    k_wconv<<<(Ss * 32 * 64 * 32) / 256, 256>>>(fc_w);
    k_comb<<<Ss * HNh, 256>>>(a1w, a1b, k_w, k_b, d_wc1, d_bc1);
    k_comb<<<Ss * HNh, 256>>>(a2w, a2b, q_w, q_b, d_wc2, d_bc2);
    k_feat<<<dim3(RTOT / 128, 4, Ss), 256>>>(nbr, tgt, fc_b);
    k_qkv<<<dim3(Bb / 64, Ss * HNh), 256, SM_QKV * 4>>>(d_wc2, d_bc2, aW);
    k_attn<<<dim3(RR / 64, Ss * HNh), 256, SM_ATTN * 4>>>(d_wc1, d_bc1, v_w, v_b);
    k_sem_score<<<dim3(Bb / 64, Ss), 256>>>(d_gout, ip1w, ip1b, ip2w, d_sc1, 0);
    k_sem_comb1<<<Bb, 256>>>();
    k_sem_score<<<dim3(Bb / 64, 2), 256>>>(d_gmp, bp1w, bp1b, bp2w, d_sc2, 1);
    k_sem_comb2<<<Bb, 256>>>(out);
}

// round 12
// speedup vs baseline: 4.1975x; 1.0806x over previous
#include <cuda_runtime.h>
#include <math.h>

#define Ntot 20000
#define IN_  256
#define Hh   128
#define HNh  4
#define Ss   5
#define Bb   1024
#define Mm   16
#define Dd   512
#define RR   16384
#define RTOT (RR + Bb)
#define LALPHA 0.2f

typedef unsigned long long ull;
typedef unsigned int uint;

__device__ __forceinline__ float lrelu(float z) { return z >= 0.f ? z : LALPHA * z; }

__device__ __forceinline__ ull pack2b(float a) {
    ull r;
    asm("mov.b64 %0, {%1, %1};" : "=l"(r) : "f"(a));
    return r;
}
__device__ __forceinline__ void ffma2(ull& d, ull a, ull b) {
    asm("fma.rn.f32x2 %0, %1, %2, %0;" : "+l"(d) : "l"(a), "l"(b));
}
__device__ __forceinline__ float2 unpack2(ull v) {
    float2 r;
    asm("mov.b64 {%0, %1}, %2;" : "=f"(r.x), "=f"(r.y) : "l"(v));
    return r;
}
__device__ __forceinline__ float cvt_tf32(float x) {
    uint r;
    asm("cvt.rna.tf32.f32 %0, %1;" : "=r"(r) : "f"(x));
    return __uint_as_float(r);
}
__device__ __forceinline__ void mma_tf32(float c[4], const uint a[4], uint b0, uint b1) {
    asm("mma.sync.aligned.m16n8k8.row.col.f32.tf32.tf32.f32 "
        "{%0,%1,%2,%3}, {%4,%5,%6,%7}, {%8,%9}, {%0,%1,%2,%3};"
        : "+f"(c[0]), "+f"(c[1]), "+f"(c[2]), "+f"(c[3])
        : "r"(a[0]), "r"(a[1]), "r"(a[2]), "r"(a[3]), "r"(b0), "r"(b1));
}

// scratch
__device__ float g_xsh[Ss * HNh * Bb * Hh];
__device__ float g_wh2[Ss * HNh * Bb * Hh];
__device__ float g_out[Ss * Bb * Dd];
__device__ float g_feat[(size_t)Ss * RR * Dd];
__device__ float g_mp[Bb * 2 * Dd];
__device__ float g_sc1[Ss * Bb];
__device__ float g_sc2[2 * Bb];
__device__ float g_xhi[(size_t)Ntot * IN_];
__device__ float g_xlo[(size_t)Ntot * IN_];
__device__ float g_wfrag[Ss * 32 * 64 * 32 * 4];   // [s][k8][j][lane][4]={b0h,b1h,b0l,b1l}
__device__ float g_wc1[Ss * HNh * Hh * Hh];        // combined a1w@k_w
__device__ float g_bc1[Ss * HNh * Hh];             // combined a1w@k_b + a1b
__device__ float g_wc2[Ss * HNh * Hh * Hh];        // combined a2w@q_w
__device__ float g_bc2[Ss * HNh * Hh];             // combined a2w@q_b + a2b

// ---------------------------------------------------------------------------
// Pre-kernels: tf32 hi/lo decomposition (for k_feat)
// ---------------------------------------------------------------------------
__global__ __launch_bounds__(256) void k_xconv(const float* __restrict__ x)
{
    size_t i = (size_t)blockIdx.x * 256 + threadIdx.x;
    float4 v = ((const float4*)x)[i];
    float4 h, l;
    h.x = cvt_tf32(v.x); l.x = cvt_tf32(v.x - h.x);
    h.y = cvt_tf32(v.y); l.y = cvt_tf32(v.y - h.y);
    h.z = cvt_tf32(v.z); l.z = cvt_tf32(v.z - h.z);
    h.w = cvt_tf32(v.w); l.w = cvt_tf32(v.w - h.w);
    ((float4*)g_xhi)[i] = h;
    ((float4*)g_xlo)[i] = l;
}

__global__ __launch_bounds__(256) void k_wconv(const float* __restrict__ fc_w)
{
    int idx = blockIdx.x * 256 + threadIdx.x;
    int lane = idx & 31;
    int t = idx >> 5;
    int j = t & 63; t >>= 6;
    int k8 = t & 31;
    int s = t >> 5;
    int n = 8 * j + (lane >> 2);
    int k0 = 8 * k8 + (lane & 3);
    const float* W = fc_w + ((size_t)s * 512 + n) * IN_;
    float w0 = W[k0], w1 = W[k0 + 4];
    float h0 = cvt_tf32(w0), h1 = cvt_tf32(w1);
    float l0 = cvt_tf32(w0 - h0), l1 = cvt_tf32(w1 - h1);
    float4 o = {h0, h1, l0, l1};
    ((float4*)g_wfrag)[idx] = o;
}

// ---------------------------------------------------------------------------
// Pre-kernel: combined weights — parallel version.
// grid (half, sh, cid): 2 x 20 x 2 = 80 blocks.
// C[o][i] = sum_j A[o][j] * B[j][i];  bcv[o] = sum_j A[o][j]*Bvb[j] + Ab[o]
// ---------------------------------------------------------------------------
#define SM_COMB 26496   // floats: sB 16896 | sA 8448 | sBb 128 | sPb 1024

__global__ __launch_bounds__(256) void k_comb(
    const float* __restrict__ A1w, const float* __restrict__ A1b,
    const float* __restrict__ B1w, const float* __restrict__ B1b,
    const float* __restrict__ A2w, const float* __restrict__ A2b,
    const float* __restrict__ B2w, const float* __restrict__ B2b)
{
    extern __shared__ __align__(16) float cs[];
    float* sB  = cs;            // 128 x 132
    float* sA  = cs + 16896;    // 64 x 132
    float* sBv = cs + 25344;    // 128
    float* sPb = cs + 25472;    // 64 x 16

    int half = blockIdx.x;
    int sh   = blockIdx.y;
    int cid  = blockIdx.z;
    int s = sh >> 2, h = sh & 3;
    int km = (s >= 2) ? 1 : 0;

    const float* Aw  = cid ? A2w : A1w;
    const float* Abv = cid ? A2b : A1b;
    const float* Bw  = cid ? B2w : B1w;
    const float* Bvb = cid ? B2b : B1b;
    float* Wc  = cid ? g_wc2 : g_wc1;
    float* bcv = cid ? g_bc2 : g_bc1;

    const float* A = Aw + (size_t)(km * HNh + h) * Hh * Hh;
    const float* B = Bw + (size_t)(s * HNh + h) * Hh * Hh;
    float* C = Wc + (size_t)(s * HNh + h) * Hh * Hh;

    int tid = threadIdx.x;
    int tx = tid & 15, ty = tid >> 4;

    // stage B fully (128x128)
    #pragma unroll
    for (int u = 0; u < 16; ++u) {
        int idx = tid + 256 * u;
        int row = idx >> 5, c4 = (idx & 31) << 2;
        *(float4*)(sB + row * 132 + c4) = *(const float4*)(B + (size_t)row * Hh + c4);
    }
    // stage A half (64x128)
    #pragma unroll
    for (int u = 0; u < 8; ++u) {
        int idx = tid + 256 * u;
        int row = idx >> 5, c4 = (idx & 31) << 2;
        *(float4*)(sA + row * 132 + c4) =
            *(const float4*)(A + (size_t)(half * 64 + row) * Hh + c4);
    }
    if (tid < 128) sBv[tid] = Bvb[(s * HNh + h) * Hh + tid];
    __syncthreads();

    float acc[4][8];
    #pragma unroll
    for (int ri = 0; ri < 4; ++ri)
        #pragma unroll
        for (int ci = 0; ci < 8; ++ci) acc[ri][ci] = 0.f;

    for (int j = 0; j < Hh; ++j) {
        float a[4];
        #pragma unroll
        for (int ri = 0; ri < 4; ++ri) a[ri] = sA[(ty * 4 + ri) * 132 + j];
        float4 w0 = *(const float4*)(sB + j * 132 + tx * 8);
        float4 w1 = *(const float4*)(sB + j * 132 + tx * 8 + 4);
        float w[8] = {w0.x, w0.y, w0.z, w0.w, w1.x, w1.y, w1.z, w1.w};
        #pragma unroll
        for (int ri = 0; ri < 4; ++ri)
            #pragma unroll
            for (int ci = 0; ci < 8; ++ci)
                acc[ri][ci] += a[ri] * w[ci];
    }
    #pragma unroll
    for (int ri = 0; ri < 4; ++ri) {
        float4 v0 = {acc[ri][0], acc[ri][1], acc[ri][2], acc[ri][3]};
        float4 v1 = {acc[ri][4], acc[ri][5], acc[ri][6], acc[ri][7]};
        float* dst = C + (size_t)(half * 64 + ty * 4 + ri) * Hh + tx * 8;
        *(float4*)(dst) = v0;
        *(float4*)(dst + 4) = v1;
    }
    // bias partials
    #pragma unroll
    for (int ri = 0; ri < 4; ++ri) {
        float p = 0.f;
        #pragma unroll
        for (int jj = 0; jj < 8; ++jj)
            p += sA[(ty * 4 + ri) * 132 + tx * 8 + jj] * sBv[tx * 8 + jj];
        sPb[(ty * 4 + ri) * 16 + tx] = p;
    }
    __syncthreads();
    if (tid < 64) {
        float bsum = Abv[(km * HNh + h) * Hh + half * 64 + tid];
        #pragma unroll
        for (int j = 0; j < 16; ++j) bsum += sPb[tid * 16 + j];
        bcv[(s * HNh + h) * Hh + half * 64 + tid] = bsum;
    }
}

// ---------------------------------------------------------------------------
// Kernel 1: feat GEMM via mma.sync tf32 (3xTF32). (unchanged)
// ---------------------------------------------------------------------------
#define APLN 36

__global__ __launch_bounds__(256) void k_feat(
    const int* __restrict__ nbr, const int* __restrict__ tgt,
    const float* __restrict__ fc_b)
{
    __shared__ float sAf[256 * APLN];
    __shared__ int sIdx[128];

    int m0 = blockIdx.x * 128;
    int n0 = blockIdx.y * 128;
    int s  = blockIdx.z;
    int tid = threadIdx.x;
    int warp = tid >> 5, L = tid & 31;
    int wm = warp & 3, wn = warp >> 2;
    int g = L >> 2, c4 = L & 3;

    if (tid < 128) {
        int r = m0 + tid;
        sIdx[tid] = (r < RR) ? nbr[s * RR + r] : tgt[r - RR];
    }
    __syncthreads();

    float acc[2][8][4];
    #pragma unroll
    for (int mi = 0; mi < 2; ++mi)
        #pragma unroll
        for (int jl = 0; jl < 8; ++jl)
            #pragma unroll
            for (int e = 0; e < 4; ++e) acc[mi][jl][e] = 0.f;

    const float* wf = g_wfrag + (size_t)s * 32 * 64 * 32 * 4;
    int jbase = (n0 >> 3) + wn * 8;

    float4 ah[4], al[4];
    #pragma unroll
    for (int u = 0; u < 4; ++u) {
        int idx = tid + 256 * u;
        int row = idx >> 3, kq = idx & 7;
        size_t o = (size_t)sIdx[row] * IN_ + 4 * kq;
        ah[u] = *(const float4*)(g_xhi + o);
        al[u] = *(const float4*)(g_xlo + o);
    }
    float4 bp[8];
    #pragma unroll
    for (int jl = 0; jl < 8; ++jl)
        bp[jl] = *(const float4*)(wf + ((size_t)(0 * 64 + jbase + jl) * 32 + L) * 4);

    for (int ch = 0; ch < 8; ++ch) {
        __syncthreads();
        #pragma unroll
        for (int u = 0; u < 4; ++u) {
            int idx = tid + 256 * u;
            int row = idx >> 3, kq = idx & 7;
            int q = kq >> 1;
            int mt = row >> 4;
            int r = row & 15;
            int reg = ((r >> 3) & 1) | ((kq & 1) << 1);
            int gg = r & 7;
            int p0 = ((q * 8 + mt) * 2 + 0) * 4 + reg;
            int p1 = ((q * 8 + mt) * 2 + 1) * 4 + reg;
            *(float4*)(sAf + p0 * APLN + 4 * gg) = ah[u];
            *(float4*)(sAf + p1 * APLN + 4 * gg) = al[u];
        }
        __syncthreads();
        if (ch < 7) {
            #pragma unroll
            for (int u = 0; u < 4; ++u) {
                int idx = tid + 256 * u;
                int row = idx >> 3, kq = idx & 7;
                size_t o = (size_t)sIdx[row] * IN_ + (ch + 1) * 32 + 4 * kq;
                ah[u] = *(const float4*)(g_xhi + o);
                al[u] = *(const float4*)(g_xlo + o);
            }
        }
        #pragma unroll
        for (int q = 0; q < 4; ++q) {
            float4 bc[8];
            #pragma unroll
            for (int jl = 0; jl < 8; ++jl) bc[jl] = bp[jl];
            int nk8 = ch * 4 + q + 1;
            if (nk8 < 32) {
                #pragma unroll
                for (int jl = 0; jl < 8; ++jl)
                    bp[jl] = *(const float4*)(wf + ((size_t)(nk8 * 64 + jbase + jl) * 32 + L) * 4);
            }
            uint afh[2][4], afl[2][4];
            #pragma unroll
            for (int mi = 0; mi < 2; ++mi) {
                int mt = 2 * wm + mi;
                int pb = ((q * 8 + mt) * 2) * 4;
                #pragma unroll
                for (int rg = 0; rg < 4; ++rg) {
                    afh[mi][rg] = __float_as_uint(sAf[(pb + rg) * APLN + L]);
                    afl[mi][rg] = __float_as_uint(sAf[(pb + 4 + rg) * APLN + L]);
                }
            }
            #pragma unroll
            for (int mi = 0; mi < 2; ++mi)
                #pragma unroll
                for (int jl = 0; jl < 8; ++jl) {
                    uint bh0 = __float_as_uint(bc[jl].x), bh1 = __float_as_uint(bc[jl].y);
                    uint bl0 = __float_as_uint(bc[jl].z), bl1 = __float_as_uint(bc[jl].w);
                    mma_tf32(acc[mi][jl], afh[mi], bh0, bh1);
                    mma_tf32(acc[mi][jl], afh[mi], bl0, bl1);
                    mma_tf32(acc[mi][jl], afl[mi], bh0, bh1);
                }
        }
    }

    #pragma unroll
    for (int mi = 0; mi < 2; ++mi) {
        int rbase = 32 * wm + 16 * mi + g;
        #pragma unroll
        for (int jl = 0; jl < 8; ++jl) {
            int col = 64 * wn + 8 * jl + 2 * c4;
            float b0v = fc_b[s * 512 + n0 + col];
            float b1v = fc_b[s * 512 + n0 + col + 1];
            float2 v0 = {lrelu(acc[mi][jl][0] + b0v), lrelu(acc[mi][jl][1] + b1v)};
            float2 v1 = {lrelu(acc[mi][jl][2] + b0v), lrelu(acc[mi][jl][3] + b1v)};
            if (m0 < RR) {
                int r = m0 + rbase;
                *(float2*)(g_feat + ((size_t)s * RR + r) * Dd + n0 + col) = v0;
                *(float2*)(g_feat + ((size_t)s * RR + r + 8) * Dd + n0 + col) = v1;
            } else {
                int h = n0 >> 7;
                int b = m0 - RR + rbase;
                *(float2*)(g_xsh + ((size_t)(s * HNh + h) * Bb + b) * Hh + col) = v0;
                *(float2*)(g_xsh + ((size_t)(s * HNh + h) * Bb + b + 8) * Hh + col) = v1;
            }
        }
    }
}

// ---------------------------------------------------------------------------
// shared FFMA2 64x128x128 micro-kernel
// ---------------------------------------------------------------------------
#define SW_STR 132
#define T_STR 132
#define SM_QKV 19008
#define SM_ATTN 15424

__device__ __forceinline__ void gemm128_f2(
    const float* __restrict__ sIn, const float* __restrict__ Wg,
    float* __restrict__ sWbuf, ull acc2[4][4],
    int tid, int tx, int ty)
{
    int kcp = (tid & 3) << 2;
    int nA = tid >> 2, nB = nA + 64;
    #pragma unroll
    for (int ri = 0; ri < 4; ++ri)
        #pragma unroll
        for (int j = 0; j < 4; ++j) acc2[ri][j] = 0ull;

    float4 p0 = *(const float4*)(Wg + nA * Hh + kcp);
    float4 p1 = *(const float4*)(Wg + nB * Hh + kcp);
    for (int c = 0; c < 8; ++c) {
        __syncthreads();
        sWbuf[(kcp + 0) * T_STR + nA] = p0.x; sWbuf[(kcp + 1) * T_STR + nA] = p0.y;
        sWbuf[(kcp + 2) * T_STR + nA] = p0.z; sWbuf[(kcp + 3) * T_STR + nA] = p0.w;
        sWbuf[(kcp + 0) * T_STR + nB] = p1.x; sWbuf[(kcp + 1) * T_STR + nB] = p1.y;
        sWbuf[(kcp + 2) * T_STR + nB] = p1.z; sWbuf[(kcp + 3) * T_STR + nB] = p1.w;
        __syncthreads();
        if (c < 7) {
            int k0n = (c + 1) * 16 + kcp;
            p0 = *(const float4*)(Wg + nA * Hh + k0n);
            p1 = *(const float4*)(Wg + nB * Hh + k0n);
        }
        int k0 = c * 16;
        #pragma unroll
        for (int kk = 0; kk < 16; ++kk) {
            ull a2[4], w2[4];
            #pragma unroll
            for (int ri = 0; ri < 4; ++ri)
                a2[ri] = pack2b(sIn[(ty * 4 + ri) * T_STR + k0 + kk]);
            #pragma unroll
            for (int j = 0; j < 4; ++j)
                w2[j] = *(const ull*)(sWbuf + kk * T_STR + tx * 8 + 2 * j);
            #pragma unroll
            for (int ri = 0; ri < 4; ++ri)
                #pragma unroll
                for (int j = 0; j < 4; ++j)
                    ffma2(acc2[ri][j], a2[ri], w2[j]);
        }
    }
}

// ---------------------------------------------------------------------------
// Kernel 2: qkv chain — 2 GEMMs: h2 = lrelu(xsh@Wc2^T+bc2); wh2 = h2@aW^T
// ---------------------------------------------------------------------------
__global__ __launch_bounds__(256, 2) void k_qkv(
    const float* __restrict__ wc2, const float* __restrict__ bc2,
    const float* __restrict__ aW)
{
    extern __shared__ __align__(16) float sm[];
    float* sA = sm;
    float* sQ = sm + 8448;
    float* sW = sm + 16896;

    int sh = blockIdx.y;
    int s = sh >> 2, h = sh & 3;
    int km = (s >= 2) ? 1 : 0;
    int b0 = blockIdx.x * 64;
    int tid = threadIdx.x;
    int tx = tid & 15, ty = tid >> 4;

    int who = (s * HNh + h) * Hh;
    int aho = (km * HNh + h) * Hh;
    const float* Wc = wc2 + (size_t)who * Hh;
    const float* Ww = aW + (size_t)aho * Hh;

    #pragma unroll
    for (int i = 0; i < 8; ++i) {
        int lid = tid + i * 256;
        int row = lid >> 5, c4 = (lid & 31) << 2;
        float4 v = *(const float4*)(g_xsh + ((size_t)(s * HNh + h) * Bb + b0 + row) * Hh + c4);
        *(float4*)(sA + row * T_STR + c4) = v;
    }

    ull acc2[4][4];

    gemm128_f2(sA, Wc, sW, acc2, tid, tx, ty);
    {
        float4 b0v = *(const float4*)(bc2 + who + tx * 8);
        float4 b1v = *(const float4*)(bc2 + who + tx * 8 + 4);
        float bb[8] = {b0v.x, b0v.y, b0v.z, b0v.w, b1v.x, b1v.y, b1v.z, b1v.w};
        #pragma unroll
        for (int ri = 0; ri < 4; ++ri) {
            float vv[8];
            #pragma unroll
            for (int j = 0; j < 4; ++j) {
                float2 t = unpack2(acc2[ri][j]);
                vv[2 * j] = lrelu(t.x + bb[2 * j]);
                vv[2 * j + 1] = lrelu(t.y + bb[2 * j + 1]);
            }
            float4 v0 = {vv[0], vv[1], vv[2], vv[3]};
            float4 v1 = {vv[4], vv[5], vv[6], vv[7]};
            *(float4*)(sQ + (ty * 4 + ri) * T_STR + tx * 8) = v0;
            *(float4*)(sQ + (ty * 4 + ri) * T_STR + tx * 8 + 4) = v1;
        }
    }

    gemm128_f2(sQ, Ww, sW, acc2, tid, tx, ty);
    #pragma unroll
    for (int ri = 0; ri < 4; ++ri) {
        int b = b0 + ty * 4 + ri;
        float* dst = g_wh2 + ((size_t)(s * HNh + h) * Bb + b) * Hh + tx * 8;
        float vv[8];
        #pragma unroll
        for (int j = 0; j < 4; ++j) {
            float2 t = unpack2(acc2[ri][j]);
            vv[2 * j] = t.x; vv[2 * j + 1] = t.y;
        }
        float4 v0 = {vv[0], vv[1], vv[2], vv[3]};
        float4 v1 = {vv[4], vv[5], vv[6], vv[7]};
        *(float4*)(dst) = v0;
        *(float4*)(dst + 4) = v1;
    }
}

// ---------------------------------------------------------------------------
// Kernel 3: fused attention — single merged pass (unchanged from R10)
// ---------------------------------------------------------------------------
__global__ __launch_bounds__(256, 2) void k_attn(
    const float* __restrict__ wc1, const float* __restrict__ bc1,
    const float* __restrict__ v_w, const float* __restrict__ v_b)
{
    extern __shared__ __align__(16) float sm[];
    float* sF   = sm;
    float* sWk  = sm + 8448;
    float* sWv  = sm + 10560;
    float* sW2  = sm + 12672;
    float* sHp  = sm + 13184;
    float* sAtt = sm + 15296;
    float* sE   = sm + 15360;

    int sh = blockIdx.y;
    int s = sh >> 2, h = sh & 3;
    int r0 = blockIdx.x * 64;
    int b0 = r0 >> 4;
    int tid = threadIdx.x;
    int tx = tid & 15, ty = tid >> 4;

    #pragma unroll
    for (int i = 0; i < 8; ++i) {
        int lid = tid + i * 256;
        int row = lid >> 5, c4 = (lid & 31) << 2;
        float4 v = *(const float4*)(g_feat + ((size_t)s * RR + r0 + row) * Dd + h * Hh + c4);
        *(float4*)(sF + row * T_STR + c4) = v;
    }
    #pragma unroll
    for (int i = 0; i < 2; ++i) {
        int lid = tid + i * 256;
        int bg = lid >> 7, o = lid & 127;
        sW2[lid] = g_wh2[((s * HNh + h) * Bb + b0 + bg) * Hh + o];
    }

    int who = (s * HNh + h) * Hh;
    const float* Wc = wc1 + (size_t)who * Hh;
    const float* Wv = v_w + (size_t)who * Hh;

    int kcp = (tid & 3) << 2;
    int nA = tid >> 2, nB = nA + 64;

    ull ak2[4][4], av2[4][4];
    #pragma unroll
    for (int ri = 0; ri < 4; ++ri)
        #pragma unroll
        for (int j = 0; j < 4; ++j) { ak2[ri][j] = 0ull; av2[ri][j] = 0ull; }

    float4 pk0 = *(const float4*)(Wc + nA * Hh + kcp);
    float4 pk1 = *(const float4*)(Wc + nB * Hh + kcp);
    float4 pv0 = *(const float4*)(Wv + nA * Hh + kcp);
    float4 pv1 = *(const float4*)(Wv + nB * Hh + kcp);

    for (int c = 0; c < 8; ++c) {
        __syncthreads();
        sWk[(kcp + 0) * T_STR + nA] = pk0.x; sWk[(kcp + 1) * T_STR + nA] = pk0.y;
        sWk[(kcp + 2) * T_STR + nA] = pk0.z; sWk[(kcp + 3) * T_STR + nA] = pk0.w;
        sWk[(kcp + 0) * T_STR + nB] = pk1.x; sWk[(kcp + 1) * T_STR + nB] = pk1.y;
        sWk[(kcp + 2) * T_STR + nB] = pk1.z; sWk[(kcp + 3) * T_STR + nB] = pk1.w;
        sWv[(kcp + 0) * T_STR + nA] = pv0.x; sWv[(kcp + 1) * T_STR + nA] = pv0.y;
        sWv[(kcp + 2) * T_STR + nA] = pv0.z; sWv[(kcp + 3) * T_STR + nA] = pv0.w;
        sWv[(kcp + 0) * T_STR + nB] = pv1.x; sWv[(kcp + 1) * T_STR + nB] = pv1.y;
        sWv[(kcp + 2) * T_STR + nB] = pv1.z; sWv[(kcp + 3) * T_STR + nB] = pv1.w;
        __syncthreads();
        if (c < 7) {
            int k0n = (c + 1) * 16 + kcp;
            pk0 = *(const float4*)(Wc + nA * Hh + k0n);
            pk1 = *(const float4*)(Wc + nB * Hh + k0n);
            pv0 = *(const float4*)(Wv + nA * Hh + k0n);
            pv1 = *(const float4*)(Wv + nB * Hh + k0n);
        }
        int k0 = c * 16;
        #pragma unroll
        for (int kk = 0; kk < 16; ++kk) {
            ull a2[4], wk2[4], wv2[4];
            #pragma unroll
            for (int ri = 0; ri < 4; ++ri)
                a2[ri] = pack2b(sF[(ty * 4 + ri) * T_STR + k0 + kk]);
            #pragma unroll
            for (int j = 0; j < 4; ++j) {
                wk2[j] = *(const ull*)(sWk + kk * T_STR + tx * 8 + 2 * j);
                wv2[j] = *(const ull*)(sWv + kk * T_STR + tx * 8 + 2 * j);
            }
            #pragma unroll
            for (int ri = 0; ri < 4; ++ri)
                #pragma unroll
                for (int j = 0; j < 4; ++j) {
                    ffma2(ak2[ri][j], a2[ri], wk2[j]);
                    ffma2(av2[ri][j], a2[ri], wv2[j]);
                }
        }
    }

    float av[4][8];
    {
        float4 c0v = *(const float4*)(v_b + who + tx * 8);
        float4 c1v = *(const float4*)(v_b + who + tx * 8 + 4);
        float cc[8] = {c0v.x, c0v.y, c0v.z, c0v.w, c1v.x, c1v.y, c1v.z, c1v.w};
        #pragma unroll
        for (int ri = 0; ri < 4; ++ri)
            #pragma unroll
            for (int j = 0; j < 4; ++j) {
                float2 t = unpack2(av2[ri][j]);
                av[ri][2 * j] = t.x + cc[2 * j];
                av[ri][2 * j + 1] = t.y + cc[2 * j + 1];
            }
    }

    {
        float4 b0v = *(const float4*)(bc1 + who + tx * 8);
        float4 b1v = *(const float4*)(bc1 + who + tx * 8 + 4);
        float bb[8] = {b0v.x, b0v.y, b0v.z, b0v.w, b1v.x, b1v.y, b1v.z, b1v.w};
        int bg = ty >> 2;
        #pragma unroll
        for (int ri = 0; ri < 4; ++ri) {
            float p = 0.f;
            #pragma unroll
            for (int j = 0; j < 4; ++j) {
                float2 t = unpack2(ak2[ri][j]);
                p += lrelu(t.x + bb[2 * j]) * sW2[bg * 128 + tx * 8 + 2 * j];
                p += lrelu(t.y + bb[2 * j + 1]) * sW2[bg * 128 + tx * 8 + 2 * j + 1];
            }
            sHp[(ty * 4 + ri) * 16 + tx] = p;
        }
    }
    __syncthreads();
    if (tid < 64) {
        float a = 0.f;
        #pragma unroll
        for (int j = 0; j < 16; ++j) a += sHp[tid * 16 + j];
        sAtt[tid] = a;
    }
    __syncthreads();
    if (tid < 4) {
        float mx = -1e30f;
        #pragma unroll
        for (int m = 0; m < Mm; ++m) mx = fmaxf(mx, sAtt[tid * 16 + m]);
        float sum = 0.f, ee[Mm];
        #pragma unroll
        for (int m = 0; m < Mm; ++m) { ee[m] = expf(sAtt[tid * 16 + m] - mx); sum += ee[m]; }
        float inv = 1.f / sum;
        #pragma unroll
        for (int m = 0; m < Mm; ++m) sE[tid * 16 + m] = ee[m] * inv;
    }
    __syncthreads();

    {
        int bg = ty >> 2;
        float hp[8];
        #pragma unroll
        for (int ci = 0; ci < 8; ++ci) hp[ci] = 0.f;
        #pragma unroll
        for (int ri = 0; ri < 4; ++ri) {
            int m = (ty * 4 + ri) & 15;
            float e = sE[bg * 16 + m];
            #pragma unroll
            for (int ci = 0; ci < 8; ++ci)
                hp[ci] += lrelu(av[ri][ci] * e);
        }
        #pragma unroll
        for (int ci = 0; ci < 8; ++ci)
            sHp[ty * T_STR + tx * 8 + ci] = hp[ci];
    }
    __syncthreads();
    #pragma unroll
    for (int i = 0; i < 2; ++i) {
        int lid = tid + i * 256;
        int bg = lid >> 7, o = lid & 127;
        float hsum = sHp[(bg * 4 + 0) * T_STR + o] + sHp[(bg * 4 + 1) * T_STR + o]
                   + sHp[(bg * 4 + 2) * T_STR + o] + sHp[(bg * 4 + 3) * T_STR + o];
        float xs = g_xsh[((s * HNh + h) * Bb + b0 + bg) * Hh + o];
        g_out[((size_t)s * Bb + b0 + bg) * Dd + h * Hh + o] = 0.5f * (xs + hsum);
    }
}

// ---------------------------------------------------------------------------
// Semantic attention (unchanged)
// ---------------------------------------------------------------------------
#define SZ_STR 20

__global__ __launch_bounds__(256) void k_sem_score(
    const float* __restrict__ zbase,
    const float* __restrict__ p1w, const float* __restrict__ p1b,
    const float* __restrict__ p2w,
    float* __restrict__ sc,
    int mode)
{
    __shared__ __align__(16) float sZ[64 * SZ_STR];
    __shared__ __align__(16) float sW[16 * SW_STR];
    __shared__ float sPart[64 * 16];

    int gy = blockIdx.y;
    int b0 = blockIdx.x * 64;
    int tid = threadIdx.x;
    int tx = tid & 15, ty = tid >> 4;

    int wsel, outbase;
    const float* zrow0;
    size_t zstride;
    if (mode == 0) {
        int s = gy;
        wsel = (s >= 2) ? 1 : 0;
        zrow0 = zbase + ((size_t)s * Bb + b0) * Dd;
        zstride = Dd;
        outbase = s * Bb + b0;
    } else {
        int k2 = gy;
        wsel = 0;
        zrow0 = zbase + ((size_t)b0 * 2 + k2) * Dd;
        zstride = 2 * Dd;
        outbase = k2 * Bb + b0;
    }
    const float* Wp = p1w + (size_t)wsel * Hh * Dd;
    const float* bp = p1b + wsel * Hh;
    const float* p2 = p2w + wsel * Hh;

    int kcp = (tid & 3) << 2;
    int rZ = tid >> 2;
    int nA = tid >> 2, nB = nA + 64;

    ull acc2[4][4];
    #pragma unroll
    for (int ri = 0; ri < 4; ++ri)
        #pragma unroll
        for (int j = 0; j < 4; ++j) acc2[ri][j] = 0ull;

    float4 pz = *(const float4*)(zrow0 + (size_t)rZ * zstride + kcp);
    float4 pw0 = *(const float4*)(Wp + (size_t)nA * Dd + kcp);
    float4 pw1 = *(const float4*)(Wp + (size_t)nB * Dd + kcp);

    for (int c = 0; c < 32; ++c) {
        __syncthreads();
        *(float4*)(sZ + rZ * SZ_STR + kcp) = pz;
        sW[(kcp + 0) * SW_STR + nA] = pw0.x; sW[(kcp + 1) * SW_STR + nA] = pw0.y;
        sW[(kcp + 2) * SW_STR + nA] = pw0.z; sW[(kcp + 3) * SW_STR + nA] = pw0.w;
        sW[(kcp + 0) * SW_STR + nB] = pw1.x; sW[(kcp + 1) * SW_STR + nB] = pw1.y;
        sW[(kcp + 2) * SW_STR + nB] = pw1.z; sW[(kcp + 3) * SW_STR + nB] = pw1.w;
        __syncthreads();
        if (c < 31) {
            int k0n = (c + 1) * 16 + kcp;
            pz = *(const float4*)(zrow0 + (size_t)rZ * zstride + k0n);
            pw0 = *(const float4*)(Wp + (size_t)nA * Dd + k0n);
            pw1 = *(const float4*)(Wp + (size_t)nB * Dd + k0n);
        }
        #pragma unroll
        for (int kk = 0; kk < 16; ++kk) {
            ull a2[4], w2[4];
            #pragma unroll
            for (int ri = 0; ri < 4; ++ri)
                a2[ri] = pack2b(sZ[(ty * 4 + ri) * SZ_STR + kk]);
            #pragma unroll
            for (int j = 0; j < 4; ++j)
                w2[j] = *(const ull*)(sW + kk * SW_STR + tx * 8 + 2 * j);
            #pragma unroll
            for (int ri = 0; ri < 4; ++ri)
                #pragma unroll
                for (int j = 0; j < 4; ++j)
                    ffma2(acc2[ri][j], a2[ri], w2[j]);
        }
    }
    {
        float bb[8], pp[8];
        #pragma unroll
        for (int ci = 0; ci < 8; ++ci) {
            bb[ci] = bp[tx * 8 + ci];
            pp[ci] = p2[tx * 8 + ci];
        }
        #pragma unroll
        for (int ri = 0; ri < 4; ++ri) {
            float p = 0.f;
            #pragma unroll
            for (int j = 0; j < 4; ++j) {
                float2 t = unpack2(acc2[ri][j]);
                p += tanhf(t.x + bb[2 * j]) * pp[2 * j];
                p += tanhf(t.y + bb[2 * j + 1]) * pp[2 * j + 1];
            }
            sPart[(ty * 4 + ri) * 16 + tx] = p;
        }
    }
    __syncthreads();
    if (tid < 64) {
        float a = 0.f;
        #pragma unroll
        for (int j = 0; j < 16; ++j) a += sPart[tid * 16 + j];
        sc[outbase + tid] = a;
    }
}

__global__ __launch_bounds__(256) void k_sem_comb1()
{
    int b = blockIdx.x;
    int tid = threadIdx.x;
    float s0 = g_sc1[0 * Bb + b], s1 = g_sc1[1 * Bb + b];
    float s2 = g_sc1[2 * Bb + b], s3 = g_sc1[3 * Bb + b], s4 = g_sc1[4 * Bb + b];
    float mx0 = fmaxf(s0, s1);
    float e0 = expf(s0 - mx0), e1 = expf(s1 - mx0);
    float i0 = 1.f / (e0 + e1);
    float b00 = e0 * i0, b01 = e1 * i0;
    float mx1 = fmaxf(fmaxf(s2, s3), s4);
    float f0 = expf(s2 - mx1), f1 = expf(s3 - mx1), f2 = expf(s4 - mx1);
    float i1 = 1.f / (f0 + f1 + f2);
    float b10 = f0 * i1, b11 = f1 * i1, b12 = f2 * i1;
    for (int d = tid; d < Dd; d += 256) {
        float z0 = b00 * g_out[(0 * Bb + b) * Dd + d] + b01 * g_out[(1 * Bb + b) * Dd + d];
        float z1 = b10 * g_out[(2 * Bb + b) * Dd + d] + b11 * g_out[(3 * Bb + b) * Dd + d]
                 + b12 * g_out[(4 * Bb + b) * Dd + d];
        g_mp[(b * 2 + 0) * Dd + d] = z0;
        g_mp[(b * 2 + 1) * Dd + d] = z1;
    }
}

__global__ __launch_bounds__(256) void k_sem_comb2(float* __restrict__ out)
{
    int b = blockIdx.x;
    int tid = threadIdx.x;
    float s0 = g_sc2[b], s1 = g_sc2[Bb + b];
    float mx = fmaxf(s0, s1);
    float e0 = expf(s0 - mx), e1 = expf(s1 - mx);
    float inv = 1.f / (e0 + e1);
    float be0 = e0 * inv, be1 = e1 * inv;
    for (int d = tid; d < Dd; d += 256)
        out[(size_t)b * Dd + d] = be0 * g_mp[(b * 2 + 0) * Dd + d]
                                + be1 * g_mp[(b * 2 + 1) * Dd + d];
}

// ---------------------------------------------------------------------------
extern "C" void kernel_launch(void* const* d_in, const int* in_sizes, int n_in,
                              void* d_out, int out_size)
{
    const float* x    = (const float*)d_in[0];
    const int*   tgt  = (const int*)d_in[1];
    const int*   nbr  = (const int*)d_in[2];
    const float* fc_w = (const float*)d_in[3];
    const float* fc_b = (const float*)d_in[4];
    const float* q_w  = (const float*)d_in[5];
    const float* q_b  = (const float*)d_in[6];
    const float* k_w  = (const float*)d_in[7];
    const float* k_b  = (const float*)d_in[8];
    const float* v_w  = (const float*)d_in[9];
    const float* v_b  = (const float*)d_in[10];
    const float* aW   = (const float*)d_in[11];
    const float* a1w  = (const float*)d_in[12];
    const float* a1b  = (const float*)d_in[13];
    const float* a2w  = (const float*)d_in[14];
    const float* a2b  = (const float*)d_in[15];
    const float* ip1w = (const float*)d_in[16];
    const float* ip1b = (const float*)d_in[17];
    const float* ip2w = (const float*)d_in[18];
    const float* bp1w = (const float*)d_in[19];
    const float* bp1b = (const float*)d_in[20];
    const float* bp2w = (const float*)d_in[21];
    float* out = (float*)d_out;

    (void)in_sizes; (void)n_in; (void)out_size;

    static int configured = 0;
    if (!configured) {
        cudaFuncSetAttribute(k_attn, cudaFuncAttributeMaxDynamicSharedMemorySize,
                             SM_ATTN * 4);
        cudaFuncSetAttribute(k_qkv, cudaFuncAttributeMaxDynamicSharedMemorySize,
                             SM_QKV * 4);
        cudaFuncSetAttribute(k_comb, cudaFuncAttributeMaxDynamicSharedMemorySize,
                             SM_COMB * 4);
        configured = 1;
    }

    float* d_gout;  cudaGetSymbolAddress((void**)&d_gout, g_out);
    float* d_gmp;   cudaGetSymbolAddress((void**)&d_gmp, g_mp);
    float* d_sc1;   cudaGetSymbolAddress((void**)&d_sc1, g_sc1);
    float* d_sc2;   cudaGetSymbolAddress((void**)&d_sc2, g_sc2);
    float* d_wc1;   cudaGetSymbolAddress((void**)&d_wc1, g_wc1);
    float* d_bc1;   cudaGetSymbolAddress((void**)&d_bc1, g_bc1);
    float* d_wc2;   cudaGetSymbolAddress((void**)&d_wc2, g_wc2);
    float* d_bc2;   cudaGetSymbolAddress((void**)&d_bc2, g_bc2);

    k_xconv<<<(Ntot * IN_ / 4) / 256, 256>>>(x);
    k_wconv<<<(Ss * 32 * 64 * 32) / 256, 256>>>(fc_w);
    k_comb<<<dim3(2, 20, 2), 256, SM_COMB * 4>>>(a1w, a1b, k_w, k_b,
                                                 a2w, a2b, q_w, q_b);
    k_feat<<<dim3(RTOT / 128, 4, Ss), 256>>>(nbr, tgt, fc_b);
    k_qkv<<<dim3(Bb / 64, Ss * HNh), 256, SM_QKV * 4>>>(d_wc2, d_bc2, aW);
    k_attn<<<dim3(RR / 64, Ss * HNh), 256, SM_ATTN * 4>>>(d_wc1, d_bc1, v_w, v_b);
    k_sem_score<<<dim3(Bb / 64, Ss), 256>>>(d_gout, ip1w, ip1b, ip2w, d_sc1, 0);
    k_sem_comb1<<<Bb, 256>>>();
    k_sem_score<<<dim3(Bb / 64, 2), 256>>>(d_gmp, bp1w, bp1b, bp2w, d_sc2, 1);
    k_sem_comb2<<<Bb, 256>>>(out);
}

// round 15
// speedup vs baseline: 4.5073x; 1.0738x over previous
#include <cuda_runtime.h>
#include <math.h>

#define Ntot 20000
#define IN_  256
#define Hh   128
#define HNh  4
#define Ss   5
#define Bb   1024
#define Mm   16
#define Dd   512
#define RR   16384
#define RTOT (RR + Bb)
#define LALPHA 0.2f

typedef unsigned long long ull;
typedef unsigned int uint;

__device__ __forceinline__ float lrelu(float z) { return z >= 0.f ? z : LALPHA * z; }

__device__ __forceinline__ ull pack2b(float a) {
    ull r;
    asm("mov.b64 %0, {%1, %1};" : "=l"(r) : "f"(a));
    return r;
}
__device__ __forceinline__ void ffma2(ull& d, ull a, ull b) {
    asm("fma.rn.f32x2 %0, %1, %2, %0;" : "+l"(d) : "l"(a), "l"(b));
}
__device__ __forceinline__ float2 unpack2(ull v) {
    float2 r;
    asm("mov.b64 {%0, %1}, %2;" : "=f"(r.x), "=f"(r.y) : "l"(v));
    return r;
}
__device__ __forceinline__ float cvt_tf32(float x) {
    uint r;
    asm("cvt.rna.tf32.f32 %0, %1;" : "=r"(r) : "f"(x));
    return __uint_as_float(r);
}
__device__ __forceinline__ void mma_tf32(float c[4], const uint a[4], uint b0, uint b1) {
    asm("mma.sync.aligned.m16n8k8.row.col.f32.tf32.tf32.f32 "
        "{%0,%1,%2,%3}, {%4,%5,%6,%7}, {%8,%9}, {%0,%1,%2,%3};"
        : "+f"(c[0]), "+f"(c[1]), "+f"(c[2]), "+f"(c[3])
        : "r"(a[0]), "r"(a[1]), "r"(a[2]), "r"(a[3]), "r"(b0), "r"(b1));
}
__device__ __forceinline__ uint smem_u32(const void* p) {
    uint a;
    asm("{ .reg .u64 t; cvta.to.shared.u64 t, %1; cvt.u32.u64 %0, t; }" : "=r"(a) : "l"(p));
    return a;
}
__device__ __forceinline__ void cp_async16(uint dst, const void* src) {
    asm volatile("cp.async.ca.shared.global [%0], [%1], 16;" :: "r"(dst), "l"(src));
}
#define CP_COMMIT() asm volatile("cp.async.commit_group;")
#define CP_WAIT1()  asm volatile("cp.async.wait_group 1;")
#define CP_WAIT0()  asm volatile("cp.async.wait_group 0;")

// scratch
__device__ float g_xsh[Ss * HNh * Bb * Hh];
__device__ float g_wh2[Ss * HNh * Bb * Hh];
__device__ float g_out[Ss * Bb * Dd];
__device__ float g_feat[(size_t)Ss * RR * Dd];
__device__ float g_mp[Bb * 2 * Dd];
__device__ float g_sc1[Ss * Bb];
__device__ float g_sc2[2 * Bb];
__device__ float g_xhi[(size_t)Ntot * IN_];
__device__ float g_xlo[(size_t)Ntot * IN_];
__device__ float g_wfrag[Ss * 32 * 64 * 32 * 4];
__device__ float g_wc1[Ss * HNh * Hh * Hh];
__device__ float g_bc1[Ss * HNh * Hh];
__device__ float g_wc2[Ss * HNh * Hh * Hh];
__device__ float g_bc2[Ss * HNh * Hh];

// ---------------------------------------------------------------------------
// Pre-kernels: tf32 hi/lo decomposition
// ---------------------------------------------------------------------------
__global__ __launch_bounds__(256) void k_xconv(const float* __restrict__ x)
{
    size_t i = (size_t)blockIdx.x * 256 + threadIdx.x;
    float4 v = ((const float4*)x)[i];
    float4 h, l;
    h.x = cvt_tf32(v.x); l.x = cvt_tf32(v.x - h.x);
    h.y = cvt_tf32(v.y); l.y = cvt_tf32(v.y - h.y);
    h.z = cvt_tf32(v.z); l.z = cvt_tf32(v.z - h.z);
    h.w = cvt_tf32(v.w); l.w = cvt_tf32(v.w - h.w);
    ((float4*)g_xhi)[i] = h;
    ((float4*)g_xlo)[i] = l;
}

__global__ __launch_bounds__(256) void k_wconv(const float* __restrict__ fc_w)
{
    int idx = blockIdx.x * 256 + threadIdx.x;
    int lane = idx & 31;
    int t = idx >> 5;
    int j = t & 63; t >>= 6;
    int k8 = t & 31;
    int s = t >> 5;
    int n = 8 * j + (lane >> 2);
    int k0 = 8 * k8 + (lane & 3);
    const float* W = fc_w + ((size_t)s * 512 + n) * IN_;
    float w0 = W[k0], w1 = W[k0 + 4];
    float h0 = cvt_tf32(w0), h1 = cvt_tf32(w1);
    float l0 = cvt_tf32(w0 - h0), l1 = cvt_tf32(w1 - h1);
    float4 o = {h0, h1, l0, l1};
    ((float4*)g_wfrag)[idx] = o;
}

// ---------------------------------------------------------------------------
// Pre-kernel: combined weights (parallel, from R12)
// ---------------------------------------------------------------------------
#define SM_COMB 26496

__global__ __launch_bounds__(256) void k_comb(
    const float* __restrict__ A1w, const float* __restrict__ A1b,
    const float* __restrict__ B1w, const float* __restrict__ B1b,
    const float* __restrict__ A2w, const float* __restrict__ A2b,
    const float* __restrict__ B2w, const float* __restrict__ B2b)
{
    extern __shared__ __align__(16) float cs[];
    float* sB  = cs;
    float* sA  = cs + 16896;
    float* sBv = cs + 25344;
    float* sPb = cs + 25472;

    int half = blockIdx.x;
    int sh   = blockIdx.y;
    int cid  = blockIdx.z;
    int s = sh >> 2, h = sh & 3;
    int km = (s >= 2) ? 1 : 0;

    const float* Aw  = cid ? A2w : A1w;
    const float* Abv = cid ? A2b : A1b;
    const float* Bw  = cid ? B2w : B1w;
    const float* Bvb = cid ? B2b : B1b;
    float* Wc  = cid ? g_wc2 : g_wc1;
    float* bcv = cid ? g_bc2 : g_bc1;

    const float* A = Aw + (size_t)(km * HNh + h) * Hh * Hh;
    const float* B = Bw + (size_t)(s * HNh + h) * Hh * Hh;
    float* C = Wc + (size_t)(s * HNh + h) * Hh * Hh;

    int tid = threadIdx.x;
    int tx = tid & 15, ty = tid >> 4;

    #pragma unroll
    for (int u = 0; u < 16; ++u) {
        int idx = tid + 256 * u;
        int row = idx >> 5, c4 = (idx & 31) << 2;
        *(float4*)(sB + row * 132 + c4) = *(const float4*)(B + (size_t)row * Hh + c4);
    }
    #pragma unroll
    for (int u = 0; u < 8; ++u) {
        int idx = tid + 256 * u;
        int row = idx >> 5, c4 = (idx & 31) << 2;
        *(float4*)(sA + row * 132 + c4) =
            *(const float4*)(A + (size_t)(half * 64 + row) * Hh + c4);
    }
    if (tid < 128) sBv[tid] = Bvb[(s * HNh + h) * Hh + tid];
    __syncthreads();

    float acc[4][8];
    #pragma unroll
    for (int ri = 0; ri < 4; ++ri)
        #pragma unroll
        for (int ci = 0; ci < 8; ++ci) acc[ri][ci] = 0.f;

    for (int j = 0; j < Hh; ++j) {
        float a[4];
        #pragma unroll
        for (int ri = 0; ri < 4; ++ri) a[ri] = sA[(ty * 4 + ri) * 132 + j];
        float4 w0 = *(const float4*)(sB + j * 132 + tx * 8);
        float4 w1 = *(const float4*)(sB + j * 132 + tx * 8 + 4);
        float w[8] = {w0.x, w0.y, w0.z, w0.w, w1.x, w1.y, w1.z, w1.w};
        #pragma unroll
        for (int ri = 0; ri < 4; ++ri)
            #pragma unroll
            for (int ci = 0; ci < 8; ++ci)
                acc[ri][ci] += a[ri] * w[ci];
    }
    #pragma unroll
    for (int ri = 0; ri < 4; ++ri) {
        float4 v0 = {acc[ri][0], acc[ri][1], acc[ri][2], acc[ri][3]};
        float4 v1 = {acc[ri][4], acc[ri][5], acc[ri][6], acc[ri][7]};
        float* dst = C + (size_t)(half * 64 + ty * 4 + ri) * Hh + tx * 8;
        *(float4*)(dst) = v0;
        *(float4*)(dst + 4) = v1;
    }
    #pragma unroll
    for (int ri = 0; ri < 4; ++ri) {
        float p = 0.f;
        #pragma unroll
        for (int jj = 0; jj < 8; ++jj)
            p += sA[(ty * 4 + ri) * 132 + tx * 8 + jj] * sBv[tx * 8 + jj];
        sPb[(ty * 4 + ri) * 16 + tx] = p;
    }
    __syncthreads();
    if (tid < 64) {
        float bsum = Abv[(km * HNh + h) * Hh + half * 64 + tid];
        #pragma unroll
        for (int j = 0; j < 16; ++j) bsum += sPb[tid * 16 + j];
        bcv[(s * HNh + h) * Hh + half * 64 + tid] = bsum;
    }
}

// ---------------------------------------------------------------------------
// Kernel 1: feat GEMM via mma.sync tf32 (3xTF32), cp.async double-buffered A,
// direct B loads, 2 blocks/SM.
// dyn smem: 2 x 256*APLN floats = 73728 B
// ---------------------------------------------------------------------------
#define APLN 36
#define SMF_BYTES (2 * 256 * APLN * 4)

__global__ __launch_bounds__(256, 2) void k_feat(
    const int* __restrict__ nbr, const int* __restrict__ tgt,
    const float* __restrict__ fc_b)
{
    extern __shared__ __align__(16) float sAf[];   // [2][256*APLN]
    __shared__ int sIdx[128];

    int m0 = blockIdx.x * 128;
    int n0 = blockIdx.y * 128;
    int s  = blockIdx.z;
    int tid = threadIdx.x;
    int warp = tid >> 5, L = tid & 31;
    int wm = warp & 3, wn = warp >> 2;
    int g = L >> 2, c4 = L & 3;

    if (tid < 128) {
        int r = m0 + tid;
        sIdx[tid] = (r < RR) ? nbr[s * RR + r] : tgt[r - RR];
    }
    __syncthreads();

    uint sbase = smem_u32(sAf);

    // per-thread staging slot addresses (constant across chunks)
    int srow[4], skq[4];
    uint dsthi[4], dstlo[4];
    #pragma unroll
    for (int u = 0; u < 4; ++u) {
        int idx = tid + 256 * u;
        int row = idx >> 3, kq = idx & 7;
        srow[u] = row; skq[u] = kq;
        int q = kq >> 1;
        int mt = row >> 4;
        int r = row & 15;
        int reg = ((r >> 3) & 1) | ((kq & 1) << 1);
        int gg = r & 7;
        int p0 = ((q * 8 + mt) * 2 + 0) * 4 + reg;
        int p1 = ((q * 8 + mt) * 2 + 1) * 4 + reg;
        dsthi[u] = (uint)((p0 * APLN + 4 * gg) * 4);
        dstlo[u] = (uint)((p1 * APLN + 4 * gg) * 4);
    }

    float acc[2][8][4];
    #pragma unroll
    for (int mi = 0; mi < 2; ++mi)
        #pragma unroll
        for (int jl = 0; jl < 8; ++jl)
            #pragma unroll
            for (int e = 0; e < 4; ++e) acc[mi][jl][e] = 0.f;

    const float* wf = g_wfrag + (size_t)s * 32 * 64 * 32 * 4;
    int jbase = (n0 >> 3) + wn * 8;

    // stage chunk 0 -> buffer 0
    {
        uint boff = 0;
        #pragma unroll
        for (int u = 0; u < 4; ++u) {
            size_t o = (size_t)sIdx[srow[u]] * IN_ + 4 * skq[u];
            cp_async16(sbase + boff + dsthi[u], g_xhi + o);
            cp_async16(sbase + boff + dstlo[u], g_xlo + o);
        }
        CP_COMMIT();
    }

    for (int ch = 0; ch < 8; ++ch) {
        __syncthreads();   // all warps done computing on the buffer we stage into
        if (ch < 7) {
            uint boff = ((ch + 1) & 1) ? (uint)(256 * APLN * 4) : 0u;
            int kadd = (ch + 1) * 32;
            #pragma unroll
            for (int u = 0; u < 4; ++u) {
                size_t o = (size_t)sIdx[srow[u]] * IN_ + kadd + 4 * skq[u];
                cp_async16(sbase + boff + dsthi[u], g_xhi + o);
                cp_async16(sbase + boff + dstlo[u], g_xlo + o);
            }
            CP_COMMIT();
            CP_WAIT1();    // chunk ch complete (chunk ch+1 may still fly)
        } else {
            CP_WAIT0();    // last chunk complete
        }
        __syncthreads();   // chunk ch visible to all warps

        const float* buf = sAf + ((ch & 1) ? 256 * APLN : 0);
        #pragma unroll
        for (int q = 0; q < 4; ++q) {
            int k8 = ch * 4 + q;
            float4 bc[8];
            #pragma unroll
            for (int jl = 0; jl < 8; ++jl)
                bc[jl] = *(const float4*)(wf + ((size_t)(k8 * 64 + jbase + jl) * 32 + L) * 4);
            uint afh[2][4], afl[2][4];
            #pragma unroll
            for (int mi = 0; mi < 2; ++mi) {
                int mt = 2 * wm + mi;
                int pb = ((q * 8 + mt) * 2) * 4;
                #pragma unroll
                for (int rg = 0; rg < 4; ++rg) {
                    afh[mi][rg] = __float_as_uint(buf[(pb + rg) * APLN + L]);
                    afl[mi][rg] = __float_as_uint(buf[(pb + 4 + rg) * APLN + L]);
                }
            }
            #pragma unroll
            for (int mi = 0; mi < 2; ++mi)
                #pragma unroll
                for (int jl = 0; jl < 8; ++jl) {
                    uint bh0 = __float_as_uint(bc[jl].x), bh1 = __float_as_uint(bc[jl].y);
                    uint bl0 = __float_as_uint(bc[jl].z), bl1 = __float_as_uint(bc[jl].w);
                    mma_tf32(acc[mi][jl], afh[mi], bh0, bh1);
                    mma_tf32(acc[mi][jl], afh[mi], bl0, bl1);
                    mma_tf32(acc[mi][jl], afl[mi], bh0, bh1);
                }
        }
    }

    #pragma unroll
    for (int mi = 0; mi < 2; ++mi) {
        int rbase = 32 * wm + 16 * mi + g;
        #pragma unroll
        for (int jl = 0; jl < 8; ++jl) {
            int col = 64 * wn + 8 * jl + 2 * c4;
            float b0v = fc_b[s * 512 + n0 + col];
            float b1v = fc_b[s * 512 + n0 + col + 1];
            float2 v0 = {lrelu(acc[mi][jl][0] + b0v), lrelu(acc[mi][jl][1] + b1v)};
            float2 v1 = {lrelu(acc[mi][jl][2] + b0v), lrelu(acc[mi][jl][3] + b1v)};
            if (m0 < RR) {
                int r = m0 + rbase;
                *(float2*)(g_feat + ((size_t)s * RR + r) * Dd + n0 + col) = v0;
                *(float2*)(g_feat + ((size_t)s * RR + r + 8) * Dd + n0 + col) = v1;
            } else {
                int h = n0 >> 7;
                int b = m0 - RR + rbase;
                *(float2*)(g_xsh + ((size_t)(s * HNh + h) * Bb + b) * Hh + col) = v0;
                *(float2*)(g_xsh + ((size_t)(s * HNh + h) * Bb + b + 8) * Hh + col) = v1;
            }
        }
    }
}

// ---------------------------------------------------------------------------
// shared FFMA2 64x128x128 micro-kernel
// ---------------------------------------------------------------------------
#define SW_STR 132
#define T_STR 132
#define SM_QKV 19008
#define SM_ATTN 15424

__device__ __forceinline__ void gemm128_f2(
    const float* __restrict__ sIn, const float* __restrict__ Wg,
    float* __restrict__ sWbuf, ull acc2[4][4],
    int tid, int tx, int ty)
{
    int kcp = (tid & 3) << 2;
    int nA = tid >> 2, nB = nA + 64;
    #pragma unroll
    for (int ri = 0; ri < 4; ++ri)
        #pragma unroll
        for (int j = 0; j < 4; ++j) acc2[ri][j] = 0ull;

    float4 p0 = *(const float4*)(Wg + nA * Hh + kcp);
    float4 p1 = *(const float4*)(Wg + nB * Hh + kcp);
    for (int c = 0; c < 8; ++c) {
        __syncthreads();
        sWbuf[(kcp + 0) * T_STR + nA] = p0.x; sWbuf[(kcp + 1) * T_STR + nA] = p0.y;
        sWbuf[(kcp + 2) * T_STR + nA] = p0.z; sWbuf[(kcp + 3) * T_STR + nA] = p0.w;
        sWbuf[(kcp + 0) * T_STR + nB] = p1.x; sWbuf[(kcp + 1) * T_STR + nB] = p1.y;
        sWbuf[(kcp + 2) * T_STR + nB] = p1.z; sWbuf[(kcp + 3) * T_STR + nB] = p1.w;
        __syncthreads();
        if (c < 7) {
            int k0n = (c + 1) * 16 + kcp;
            p0 = *(const float4*)(Wg + nA * Hh + k0n);
            p1 = *(const float4*)(Wg + nB * Hh + k0n);
        }
        int k0 = c * 16;
        #pragma unroll
        for (int kk = 0; kk < 16; ++kk) {
            ull a2[4], w2[4];
            #pragma unroll
            for (int ri = 0; ri < 4; ++ri)
                a2[ri] = pack2b(sIn[(ty * 4 + ri) * T_STR + k0 + kk]);
            #pragma unroll
            for (int j = 0; j < 4; ++j)
                w2[j] = *(const ull*)(sWbuf + kk * T_STR + tx * 8 + 2 * j);
            #pragma unroll
            for (int ri = 0; ri < 4; ++ri)
                #pragma unroll
                for (int j = 0; j < 4; ++j)
                    ffma2(acc2[ri][j], a2[ri], w2[j]);
        }
    }
}

// ---------------------------------------------------------------------------
// Kernel 2: qkv chain (unchanged)
// ---------------------------------------------------------------------------
__global__ __launch_bounds__(256, 2) void k_qkv(
    const float* __restrict__ wc2, const float* __restrict__ bc2,
    const float* __restrict__ aW)
{
    extern __shared__ __align__(16) float sm[];
    float* sA = sm;
    float* sQ = sm + 8448;
    float* sW = sm + 16896;

    int sh = blockIdx.y;
    int s = sh >> 2, h = sh & 3;
    int km = (s >= 2) ? 1 : 0;
    int b0 = blockIdx.x * 64;
    int tid = threadIdx.x;
    int tx = tid & 15, ty = tid >> 4;

    int who = (s * HNh + h) * Hh;
    int aho = (km * HNh + h) * Hh;
    const float* Wc = wc2 + (size_t)who * Hh;
    const float* Ww = aW + (size_t)aho * Hh;

    #pragma unroll
    for (int i = 0; i < 8; ++i) {
        int lid = tid + i * 256;
        int row = lid >> 5, c4 = (lid & 31) << 2;
        float4 v = *(const float4*)(g_xsh + ((size_t)(s * HNh + h) * Bb + b0 + row) * Hh + c4);
        *(float4*)(sA + row * T_STR + c4) = v;
    }

    ull acc2[4][4];

    gemm128_f2(sA, Wc, sW, acc2, tid, tx, ty);
    {
        float4 b0v = *(const float4*)(bc2 + who + tx * 8);
        float4 b1v = *(const float4*)(bc2 + who + tx * 8 + 4);
        float bb[8] = {b0v.x, b0v.y, b0v.z, b0v.w, b1v.x, b1v.y, b1v.z, b1v.w};
        #pragma unroll
        for (int ri = 0; ri < 4; ++ri) {
            float vv[8];
            #pragma unroll
            for (int j = 0; j < 4; ++j) {
                float2 t = unpack2(acc2[ri][j]);
                vv[2 * j] = lrelu(t.x + bb[2 * j]);
                vv[2 * j + 1] = lrelu(t.y + bb[2 * j + 1]);
            }
            float4 v0 = {vv[0], vv[1], vv[2], vv[3]};
            float4 v1 = {vv[4], vv[5], vv[6], vv[7]};
            *(float4*)(sQ + (ty * 4 + ri) * T_STR + tx * 8) = v0;
            *(float4*)(sQ + (ty * 4 + ri) * T_STR + tx * 8 + 4) = v1;
        }
    }

    gemm128_f2(sQ, Ww, sW, acc2, tid, tx, ty);
    #pragma unroll
    for (int ri = 0; ri < 4; ++ri) {
        int b = b0 + ty * 4 + ri;
        float* dst = g_wh2 + ((size_t)(s * HNh + h) * Bb + b) * Hh + tx * 8;
        float vv[8];
        #pragma unroll
        for (int j = 0; j < 4; ++j) {
            float2 t = unpack2(acc2[ri][j]);
            vv[2 * j] = t.x; vv[2 * j + 1] = t.y;
        }
        float4 v0 = {vv[0], vv[1], vv[2], vv[3]};
        float4 v1 = {vv[4], vv[5], vv[6], vv[7]};
        *(float4*)(dst) = v0;
        *(float4*)(dst + 4) = v1;
    }
}

// ---------------------------------------------------------------------------
// Kernel 3: fused attention — single merged pass (unchanged)
// ---------------------------------------------------------------------------
__global__ __launch_bounds__(256, 2) void k_attn(
    const float* __restrict__ wc1, const float* __restrict__ bc1,
    const float* __restrict__ v_w, const float* __restrict__ v_b)
{
    extern __shared__ __align__(16) float sm[];
    float* sF   = sm;
    float* sWk  = sm + 8448;
    float* sWv  = sm + 10560;
    float* sW2  = sm + 12672;
    float* sHp  = sm + 13184;
    float* sAtt = sm + 15296;
    float* sE   = sm + 15360;

    int sh = blockIdx.y;
    int s = sh >> 2, h = sh & 3;
    int r0 = blockIdx.x * 64;
    int b0 = r0 >> 4;
    int tid = threadIdx.x;
    int tx = tid & 15, ty = tid >> 4;

    #pragma unroll
    for (int i = 0; i < 8; ++i) {
        int lid = tid + i * 256;
        int row = lid >> 5, c4 = (lid & 31) << 2;
        float4 v = *(const float4*)(g_feat + ((size_t)s * RR + r0 + row) * Dd + h * Hh + c4);
        *(float4*)(sF + row * T_STR + c4) = v;
    }
    #pragma unroll
    for (int i = 0; i < 2; ++i) {
        int lid = tid + i * 256;
        int bg = lid >> 7, o = lid & 127;
        sW2[lid] = g_wh2[((s * HNh + h) * Bb + b0 + bg) * Hh + o];
    }

    int who = (s * HNh + h) * Hh;
    const float* Wc = wc1 + (size_t)who * Hh;
    const float* Wv = v_w + (size_t)who * Hh;

    int kcp = (tid & 3) << 2;
    int nA = tid >> 2, nB = nA + 64;

    ull ak2[4][4], av2[4][4];
    #pragma unroll
    for (int ri = 0; ri < 4; ++ri)
        #pragma unroll
        for (int j = 0; j < 4; ++j) { ak2[ri][j] = 0ull; av2[ri][j] = 0ull; }

    float4 pk0 = *(const float4*)(Wc + nA * Hh + kcp);
    float4 pk1 = *(const float4*)(Wc + nB * Hh + kcp);
    float4 pv0 = *(const float4*)(Wv + nA * Hh + kcp);
    float4 pv1 = *(const float4*)(Wv + nB * Hh + kcp);

    for (int c = 0; c < 8; ++c) {
        __syncthreads();
        sWk[(kcp + 0) * T_STR + nA] = pk0.x; sWk[(kcp + 1) * T_STR + nA] = pk0.y;
        sWk[(kcp + 2) * T_STR + nA] = pk0.z; sWk[(kcp + 3) * T_STR + nA] = pk0.w;
        sWk[(kcp + 0) * T_STR + nB] = pk1.x; sWk[(kcp + 1) * T_STR + nB] = pk1.y;
        sWk[(kcp + 2) * T_STR + nB] = pk1.z; sWk[(kcp + 3) * T_STR + nB] = pk1.w;
        sWv[(kcp + 0) * T_STR + nA] = pv0.x; sWv[(kcp + 1) * T_STR + nA] = pv0.y;
        sWv[(kcp + 2) * T_STR + nA] = pv0.z; sWv[(kcp + 3) * T_STR + nA] = pv0.w;
        sWv[(kcp + 0) * T_STR + nB] = pv1.x; sWv[(kcp + 1) * T_STR + nB] = pv1.y;
        sWv[(kcp + 2) * T_STR + nB] = pv1.z; sWv[(kcp + 3) * T_STR + nB] = pv1.w;
        __syncthreads();
        if (c < 7) {
            int k0n = (c + 1) * 16 + kcp;
            pk0 = *(const float4*)(Wc + nA * Hh + k0n);
            pk1 = *(const float4*)(Wc + nB * Hh + k0n);
            pv0 = *(const float4*)(Wv + nA * Hh + k0n);
            pv1 = *(const float4*)(Wv + nB * Hh + k0n);
        }
        int k0 = c * 16;
        #pragma unroll
        for (int kk = 0; kk < 16; ++kk) {
            ull a2[4], wk2[4], wv2[4];
            #pragma unroll
            for (int ri = 0; ri < 4; ++ri)
                a2[ri] = pack2b(sF[(ty * 4 + ri) * T_STR + k0 + kk]);
            #pragma unroll
            for (int j = 0; j < 4; ++j) {
                wk2[j] = *(const ull*)(sWk + kk * T_STR + tx * 8 + 2 * j);
                wv2[j] = *(const ull*)(sWv + kk * T_STR + tx * 8 + 2 * j);
            }
            #pragma unroll
            for (int ri = 0; ri < 4; ++ri)
                #pragma unroll
                for (int j = 0; j < 4; ++j) {
                    ffma2(ak2[ri][j], a2[ri], wk2[j]);
                    ffma2(av2[ri][j], a2[ri], wv2[j]);
                }
        }
    }

    float av[4][8];
    {
        float4 c0v = *(const float4*)(v_b + who + tx * 8);
        float4 c1v = *(const float4*)(v_b + who + tx * 8 + 4);
        float cc[8] = {c0v.x, c0v.y, c0v.z, c0v.w, c1v.x, c1v.y, c1v.z, c1v.w};
        #pragma unroll
        for (int ri = 0; ri < 4; ++ri)
            #pragma unroll
            for (int j = 0; j < 4; ++j) {
                float2 t = unpack2(av2[ri][j]);
                av[ri][2 * j] = t.x + cc[2 * j];
                av[ri][2 * j + 1] = t.y + cc[2 * j + 1];
            }
    }

    {
        float4 b0v = *(const float4*)(bc1 + who + tx * 8);
        float4 b1v = *(const float4*)(bc1 + who + tx * 8 + 4);
        float bb[8] = {b0v.x, b0v.y, b0v.z, b0v.w, b1v.x, b1v.y, b1v.z, b1v.w};
        int bg = ty >> 2;
        #pragma unroll
        for (int ri = 0; ri < 4; ++ri) {
            float p = 0.f;
            #pragma unroll
            for (int j = 0; j < 4; ++j) {
                float2 t = unpack2(ak2[ri][j]);
                p += lrelu(t.x + bb[2 * j]) * sW2[bg * 128 + tx * 8 + 2 * j];
                p += lrelu(t.y + bb[2 * j + 1]) * sW2[bg * 128 + tx * 8 + 2 * j + 1];
            }
            sHp[(ty * 4 + ri) * 16 + tx] = p;
        }
    }
    __syncthreads();
    if (tid < 64) {
        float a = 0.f;
        #pragma unroll
        for (int j = 0; j < 16; ++j) a += sHp[tid * 16 + j];
        sAtt[tid] = a;
    }
    __syncthreads();
    if (tid < 4) {
        float mx = -1e30f;
        #pragma unroll
        for (int m = 0; m < Mm; ++m) mx = fmaxf(mx, sAtt[tid * 16 + m]);
        float sum = 0.f, ee[Mm];
        #pragma unroll
        for (int m = 0; m < Mm; ++m) { ee[m] = expf(sAtt[tid * 16 + m] - mx); sum += ee[m]; }
        float inv = 1.f / sum;
        #pragma unroll
        for (int m = 0; m < Mm; ++m) sE[tid * 16 + m] = ee[m] * inv;
    }
    __syncthreads();

    {
        int bg = ty >> 2;
        float hp[8];
        #pragma unroll
        for (int ci = 0; ci < 8; ++ci) hp[ci] = 0.f;
        #pragma unroll
        for (int ri = 0; ri < 4; ++ri) {
            int m = (ty * 4 + ri) & 15;
            float e = sE[bg * 16 + m];
            #pragma unroll
            for (int ci = 0; ci < 8; ++ci)
                hp[ci] += lrelu(av[ri][ci] * e);
        }
        #pragma unroll
        for (int ci = 0; ci < 8; ++ci)
            sHp[ty * T_STR + tx * 8 + ci] = hp[ci];
    }
    __syncthreads();
    #pragma unroll
    for (int i = 0; i < 2; ++i) {
        int lid = tid + i * 256;
        int bg = lid >> 7, o = lid & 127;
        float hsum = sHp[(bg * 4 + 0) * T_STR + o] + sHp[(bg * 4 + 1) * T_STR + o]
                   + sHp[(bg * 4 + 2) * T_STR + o] + sHp[(bg * 4 + 3) * T_STR + o];
        float xs = g_xsh[((s * HNh + h) * Bb + b0 + bg) * Hh + o];
        g_out[((size_t)s * Bb + b0 + bg) * Dd + h * Hh + o] = 0.5f * (xs + hsum);
    }
}

// ---------------------------------------------------------------------------
// Semantic attention (unchanged)
// ---------------------------------------------------------------------------
#define SZ_STR 20

__global__ __launch_bounds__(256) void k_sem_score(
    const float* __restrict__ zbase,
    const float* __restrict__ p1w, const float* __restrict__ p1b,
    const float* __restrict__ p2w,
    float* __restrict__ sc,
    int mode)
{
    __shared__ __align__(16) float sZ[64 * SZ_STR];
    __shared__ __align__(16) float sW[16 * SW_STR];
    __shared__ float sPart[64 * 16];

    int gy = blockIdx.y;
    int b0 = blockIdx.x * 64;
    int tid = threadIdx.x;
    int tx = tid & 15, ty = tid >> 4;

    int wsel, outbase;
    const float* zrow0;
    size_t zstride;
    if (mode == 0) {
        int s = gy;
        wsel = (s >= 2) ? 1 : 0;
        zrow0 = zbase + ((size_t)s * Bb + b0) * Dd;
        zstride = Dd;
        outbase = s * Bb + b0;
    } else {
        int k2 = gy;
        wsel = 0;
        zrow0 = zbase + ((size_t)b0 * 2 + k2) * Dd;
        zstride = 2 * Dd;
        outbase = k2 * Bb + b0;
    }
    const float* Wp = p1w + (size_t)wsel * Hh * Dd;
    const float* bp = p1b + wsel * Hh;
    const float* p2 = p2w + wsel * Hh;

    int kcp = (tid & 3) << 2;
    int rZ = tid >> 2;
    int nA = tid >> 2, nB = nA + 64;

    ull acc2[4][4];
    #pragma unroll
    for (int ri = 0; ri < 4; ++ri)
        #pragma unroll
        for (int j = 0; j < 4; ++j) acc2[ri][j] = 0ull;

    float4 pz = *(const float4*)(zrow0 + (size_t)rZ * zstride + kcp);
    float4 pw0 = *(const float4*)(Wp + (size_t)nA * Dd + kcp);
    float4 pw1 = *(const float4*)(Wp + (size_t)nB * Dd + kcp);

    for (int c = 0; c < 32; ++c) {
        __syncthreads();
        *(float4*)(sZ + rZ * SZ_STR + kcp) = pz;
        sW[(kcp + 0) * SW_STR + nA] = pw0.x; sW[(kcp + 1) * SW_STR + nA] = pw0.y;
        sW[(kcp + 2) * SW_STR + nA] = pw0.z; sW[(kcp + 3) * SW_STR + nA] = pw0.w;
        sW[(kcp + 0) * SW_STR + nB] = pw1.x; sW[(kcp + 1) * SW_STR + nB] = pw1.y;
        sW[(kcp + 2) * SW_STR + nB] = pw1.z; sW[(kcp + 3) * SW_STR + nB] = pw1.w;
        __syncthreads();
        if (c < 31) {
            int k0n = (c + 1) * 16 + kcp;
            pz = *(const float4*)(zrow0 + (size_t)rZ * zstride + k0n);
            pw0 = *(const float4*)(Wp + (size_t)nA * Dd + k0n);
            pw1 = *(const float4*)(Wp + (size_t)nB * Dd + k0n);
        }
        #pragma unroll
        for (int kk = 0; kk < 16; ++kk) {
            ull a2[4], w2[4];
            #pragma unroll
            for (int ri = 0; ri < 4; ++ri)
                a2[ri] = pack2b(sZ[(ty * 4 + ri) * SZ_STR + kk]);
            #pragma unroll
            for (int j = 0; j < 4; ++j)
                w2[j] = *(const ull*)(sW + kk * SW_STR + tx * 8 + 2 * j);
            #pragma unroll
            for (int ri = 0; ri < 4; ++ri)
                #pragma unroll
                for (int j = 0; j < 4; ++j)
                    ffma2(acc2[ri][j], a2[ri], w2[j]);
        }
    }
    {
        float bb[8], pp[8];
        #pragma unroll
        for (int ci = 0; ci < 8; ++ci) {
            bb[ci] = bp[tx * 8 + ci];
            pp[ci] = p2[tx * 8 + ci];
        }
        #pragma unroll
        for (int ri = 0; ri < 4; ++ri) {
            float p = 0.f;
            #pragma unroll
            for (int j = 0; j < 4; ++j) {
                float2 t = unpack2(acc2[ri][j]);
                p += tanhf(t.x + bb[2 * j]) * pp[2 * j];
                p += tanhf(t.y + bb[2 * j + 1]) * pp[2 * j + 1];
            }
            sPart[(ty * 4 + ri) * 16 + tx] = p;
        }
    }
    __syncthreads();
    if (tid < 64) {
        float a = 0.f;
        #pragma unroll
        for (int j = 0; j < 16; ++j) a += sPart[tid * 16 + j];
        sc[outbase + tid] = a;
    }
}

__global__ __launch_bounds__(256) void k_sem_comb1()
{
    int b = blockIdx.x;
    int tid = threadIdx.x;
    float s0 = g_sc1[0 * Bb + b], s1 = g_sc1[1 * Bb + b];
    float s2 = g_sc1[2 * Bb + b], s3 = g_sc1[3 * Bb + b], s4 = g_sc1[4 * Bb + b];
    float mx0 = fmaxf(s0, s1);
    float e0 = expf(s0 - mx0), e1 = expf(s1 - mx0);
    float i0 = 1.f / (e0 + e1);
    float b00 = e0 * i0, b01 = e1 * i0;
    float mx1 = fmaxf(fmaxf(s2, s3), s4);
    float f0 = expf(s2 - mx1), f1 = expf(s3 - mx1), f2 = expf(s4 - mx1);
    float i1 = 1.f / (f0 + f1 + f2);
    float b10 = f0 * i1, b11 = f1 * i1, b12 = f2 * i1;
    for (int d = tid; d < Dd; d += 256) {
        float z0 = b00 * g_out[(0 * Bb + b) * Dd + d] + b01 * g_out[(1 * Bb + b) * Dd + d];
        float z1 = b10 * g_out[(2 * Bb + b) * Dd + d] + b11 * g_out[(3 * Bb + b) * Dd + d]
                 + b12 * g_out[(4 * Bb + b) * Dd + d];
        g_mp[(b * 2 + 0) * Dd + d] = z0;
        g_mp[(b * 2 + 1) * Dd + d] = z1;
    }
}

__global__ __launch_bounds__(256) void k_sem_comb2(float* __restrict__ out)
{
    int b = blockIdx.x;
    int tid = threadIdx.x;
    float s0 = g_sc2[b], s1 = g_sc2[Bb + b];
    float mx = fmaxf(s0, s1);
    float e0 = expf(s0 - mx), e1 = expf(s1 - mx);
    float inv = 1.f / (e0 + e1);
    float be0 = e0 * inv, be1 = e1 * inv;
    for (int d = tid; d < Dd; d += 256)
        out[(size_t)b * Dd + d] = be0 * g_mp[(b * 2 + 0) * Dd + d]
                                + be1 * g_mp[(b * 2 + 1) * Dd + d];
}

// ---------------------------------------------------------------------------
extern "C" void kernel_launch(void* const* d_in, const int* in_sizes, int n_in,
                              void* d_out, int out_size)
{
    const float* x    = (const float*)d_in[0];
    const int*   tgt  = (const int*)d_in[1];
    const int*   nbr  = (const int*)d_in[2];
    const float* fc_w = (const float*)d_in[3];
    const float* fc_b = (const float*)d_in[4];
    const float* q_w  = (const float*)d_in[5];
    const float* q_b  = (const float*)d_in[6];
    const float* k_w  = (const float*)d_in[7];
    const float* k_b  = (const float*)d_in[8];
    const float* v_w  = (const float*)d_in[9];
    const float* v_b  = (const float*)d_in[10];
    const float* aW   = (const float*)d_in[11];
    const float* a1w  = (const float*)d_in[12];
    const float* a1b  = (const float*)d_in[13];
    const float* a2w  = (const float*)d_in[14];
    const float* a2b  = (const float*)d_in[15];
    const float* ip1w = (const float*)d_in[16];
    const float* ip1b = (const float*)d_in[17];
    const float* ip2w = (const float*)d_in[18];
    const float* bp1w = (const float*)d_in[19];
    const float* bp1b = (const float*)d_in[20];
    const float* bp2w = (const float*)d_in[21];
    float* out = (float*)d_out;

    (void)in_sizes; (void)n_in; (void)out_size;

    static int configured = 0;
    if (!configured) {
        cudaFuncSetAttribute(k_attn, cudaFuncAttributeMaxDynamicSharedMemorySize,
                             SM_ATTN * 4);
        cudaFuncSetAttribute(k_qkv, cudaFuncAttributeMaxDynamicSharedMemorySize,
                             SM_QKV * 4);
        cudaFuncSetAttribute(k_comb, cudaFuncAttributeMaxDynamicSharedMemorySize,
                             SM_COMB * 4);
        cudaFuncSetAttribute(k_feat, cudaFuncAttributeMaxDynamicSharedMemorySize,
                             SMF_BYTES);
        configured = 1;
    }

    float* d_gout;  cudaGetSymbolAddress((void**)&d_gout, g_out);
    float* d_gmp;   cudaGetSymbolAddress((void**)&d_gmp, g_mp);
    float* d_sc1;   cudaGetSymbolAddress((void**)&d_sc1, g_sc1);
    float* d_sc2;   cudaGetSymbolAddress((void**)&d_sc2, g_sc2);
    float* d_wc1;   cudaGetSymbolAddress((void**)&d_wc1, g_wc1);
    float* d_bc1;   cudaGetSymbolAddress((void**)&d_bc1, g_bc1);
    float* d_wc2;   cudaGetSymbolAddress((void**)&d_wc2, g_wc2);
    float* d_bc2;   cudaGetSymbolAddress((void**)&d_bc2, g_bc2);

    k_xconv<<<(Ntot * IN_ / 4) / 256, 256>>>(x);
    k_wconv<<<(Ss * 32 * 64 * 32) / 256, 256>>>(fc_w);
    k_comb<<<dim3(2, 20, 2), 256, SM_COMB * 4>>>(a1w, a1b, k_w, k_b,
                                                 a2w, a2b, q_w, q_b);
    k_feat<<<dim3(RTOT / 128, 4, Ss), 256, SMF_BYTES>>>(nbr, tgt, fc_b);
    k_qkv<<<dim3(Bb / 64, Ss * HNh), 256, SM_QKV * 4>>>(d_wc2, d_bc2, aW);
    k_attn<<<dim3(RR / 64, Ss * HNh), 256, SM_ATTN * 4>>>(d_wc1, d_bc1, v_w, v_b);
    k_sem_score<<<dim3(Bb / 64, Ss), 256>>>(d_gout, ip1w, ip1b, ip2w, d_sc1, 0);
    k_sem_comb1<<<Bb, 256>>>();
    k_sem_score<<<dim3(Bb / 64, 2), 256>>>(d_gmp, bp1w, bp1b, bp2w, d_sc2, 1);
    k_sem_comb2<<<Bb, 256>>>(out);
}

// round 16
// speedup vs baseline: 5.9404x; 1.3179x over previous
#include <cuda_runtime.h>
#include <math.h>

#define Ntot 20000
#define IN_  256
#define Hh   128
#define HNh  4
#define Ss   5
#define Bb   1024
#define Mm   16
#define Dd   512
#define RR   16384
#define RTOT (RR + Bb)
#define LALPHA 0.2f

typedef unsigned long long ull;
typedef unsigned int uint;

__device__ __forceinline__ float lrelu(float z) { return z >= 0.f ? z : LALPHA * z; }

__device__ __forceinline__ ull pack2b(float a) {
    ull r;
    asm("mov.b64 %0, {%1, %1};" : "=l"(r) : "f"(a));
    return r;
}
__device__ __forceinline__ void ffma2(ull& d, ull a, ull b) {
    asm("fma.rn.f32x2 %0, %1, %2, %0;" : "+l"(d) : "l"(a), "l"(b));
}
__device__ __forceinline__ float2 unpack2(ull v) {
    float2 r;
    asm("mov.b64 {%0, %1}, %2;" : "=f"(r.x), "=f"(r.y) : "l"(v));
    return r;
}
__device__ __forceinline__ float cvt_tf32(float x) {
    uint r;
    asm("cvt.rna.tf32.f32 %0, %1;" : "=r"(r) : "f"(x));
    return __uint_as_float(r);
}
__device__ __forceinline__ void mma_tf32(float c[4], const uint a[4], uint b0, uint b1) {
    asm("mma.sync.aligned.m16n8k8.row.col.f32.tf32.tf32.f32 "
        "{%0,%1,%2,%3}, {%4,%5,%6,%7}, {%8,%9}, {%0,%1,%2,%3};"
        : "+f"(c[0]), "+f"(c[1]), "+f"(c[2]), "+f"(c[3])
        : "r"(a[0]), "r"(a[1]), "r"(a[2]), "r"(a[3]), "r"(b0), "r"(b1));
}
__device__ __forceinline__ uint smem_u32(const void* p) {
    uint a;
    asm("{ .reg .u64 t; cvta.to.shared.u64 t, %1; cvt.u32.u64 %0, t; }" : "=r"(a) : "l"(p));
    return a;
}
__device__ __forceinline__ void cp_async16(uint dst, const void* src) {
    asm volatile("cp.async.ca.shared.global [%0], [%1], 16;" :: "r"(dst), "l"(src));
}
#define CP_COMMIT() asm volatile("cp.async.commit_group;")
#define CP_WAIT1()  asm volatile("cp.async.wait_group 1;")
#define CP_WAIT0()  asm volatile("cp.async.wait_group 0;")

// scratch
__device__ float g_xsh[Ss * HNh * Bb * Hh];
__device__ float g_wh2[Ss * HNh * Bb * Hh];
__device__ float g_out[Ss * Bb * Dd];
__device__ float g_fhi[(size_t)Ss * RR * Dd];
__device__ float g_flo[(size_t)Ss * RR * Dd];
__device__ float g_mp[Bb * 2 * Dd];
__device__ float g_sc1[Ss * Bb];
__device__ float g_sc2[2 * Bb];
__device__ float g_xhi[(size_t)Ntot * IN_];
__device__ float g_xlo[(size_t)Ntot * IN_];
__device__ float g_wfrag[Ss * 32 * 64 * 32 * 4];
__device__ float g_wfa[20 * 2 * 16 * 16 * 32 * 4];  // [sh][gemm][k8][j][lane]x{b0h,b1h,b0l,b1l}
__device__ float g_wc1[Ss * HNh * Hh * Hh];
__device__ float g_bc1[Ss * HNh * Hh];
__device__ float g_wc2[Ss * HNh * Hh * Hh];
__device__ float g_bc2[Ss * HNh * Hh];

// ---------------------------------------------------------------------------
// Pre-kernels
// ---------------------------------------------------------------------------
__global__ __launch_bounds__(256) void k_xconv(const float* __restrict__ x)
{
    size_t i = (size_t)blockIdx.x * 256 + threadIdx.x;
    float4 v = ((const float4*)x)[i];
    float4 h, l;
    h.x = cvt_tf32(v.x); l.x = cvt_tf32(v.x - h.x);
    h.y = cvt_tf32(v.y); l.y = cvt_tf32(v.y - h.y);
    h.z = cvt_tf32(v.z); l.z = cvt_tf32(v.z - h.z);
    h.w = cvt_tf32(v.w); l.w = cvt_tf32(v.w - h.w);
    ((float4*)g_xhi)[i] = h;
    ((float4*)g_xlo)[i] = l;
}

__global__ __launch_bounds__(256) void k_wconv(const float* __restrict__ fc_w)
{
    int idx = blockIdx.x * 256 + threadIdx.x;
    int lane = idx & 31;
    int t = idx >> 5;
    int j = t & 63; t >>= 6;
    int k8 = t & 31;
    int s = t >> 5;
    int n = 8 * j + (lane >> 2);
    int k0 = 8 * k8 + (lane & 3);
    const float* W = fc_w + ((size_t)s * 512 + n) * IN_;
    float w0 = W[k0], w1 = W[k0 + 4];
    float h0 = cvt_tf32(w0), h1 = cvt_tf32(w1);
    float l0 = cvt_tf32(w0 - h0), l1 = cvt_tf32(w1 - h1);
    float4 o = {h0, h1, l0, l1};
    ((float4*)g_wfrag)[idx] = o;
}

// frag-order attention weights: gemm0 = g_wc1 (runtime), gemm1 = v_w
__global__ __launch_bounds__(256) void k_wfa(const float* __restrict__ v_w)
{
    int idx = blockIdx.x * 256 + threadIdx.x;
    int lane = idx & 31;
    int t = idx >> 5;
    int j = t & 15; t >>= 4;
    int k8 = t & 15; t >>= 4;
    int gemm = t & 1;
    int sh = t >> 1;
    int s = sh >> 2, h = sh & 3;
    int n = 8 * j + (lane >> 2);
    int k0 = 8 * k8 + (lane & 3);
    const float* W = gemm ? (v_w + (size_t)(s * HNh + h) * Hh * Hh)
                          : (g_wc1 + (size_t)(s * HNh + h) * Hh * Hh);
    float w0 = W[n * Hh + k0], w1 = W[n * Hh + k0 + 4];
    float h0 = cvt_tf32(w0), h1 = cvt_tf32(w1);
    float l0 = cvt_tf32(w0 - h0), l1 = cvt_tf32(w1 - h1);
    float4 o = {h0, h1, l0, l1};
    ((float4*)g_wfa)[idx] = o;
}

// ---------------------------------------------------------------------------
// Pre-kernel: combined weights (parallel, unchanged from R12)
// ---------------------------------------------------------------------------
#define SM_COMB 26496

__global__ __launch_bounds__(256) void k_comb(
    const float* __restrict__ A1w, const float* __restrict__ A1b,
    const float* __restrict__ B1w, const float* __restrict__ B1b,
    const float* __restrict__ A2w, const float* __restrict__ A2b,
    const float* __restrict__ B2w, const float* __restrict__ B2b)
{
    extern __shared__ __align__(16) float cs[];
    float* sB  = cs;
    float* sA  = cs + 16896;
    float* sBv = cs + 25344;
    float* sPb = cs + 25472;

    int half = blockIdx.x;
    int sh   = blockIdx.y;
    int cid  = blockIdx.z;
    int s = sh >> 2, h = sh & 3;
    int km = (s >= 2) ? 1 : 0;

    const float* Aw  = cid ? A2w : A1w;
    const float* Abv = cid ? A2b : A1b;
    const float* Bw  = cid ? B2w : B1w;
    const float* Bvb = cid ? B2b : B1b;
    float* Wc  = cid ? g_wc2 : g_wc1;
    float* bcv = cid ? g_bc2 : g_bc1;

    const float* A = Aw + (size_t)(km * HNh + h) * Hh * Hh;
    const float* B = Bw + (size_t)(s * HNh + h) * Hh * Hh;
    float* C = Wc + (size_t)(s * HNh + h) * Hh * Hh;

    int tid = threadIdx.x;
    int tx = tid & 15, ty = tid >> 4;

    #pragma unroll
    for (int u = 0; u < 16; ++u) {
        int idx = tid + 256 * u;
        int row = idx >> 5, c4 = (idx & 31) << 2;
        *(float4*)(sB + row * 132 + c4) = *(const float4*)(B + (size_t)row * Hh + c4);
    }
    #pragma unroll
    for (int u = 0; u < 8; ++u) {
        int idx = tid + 256 * u;
        int row = idx >> 5, c4 = (idx & 31) << 2;
        *(float4*)(sA + row * 132 + c4) =
            *(const float4*)(A + (size_t)(half * 64 + row) * Hh + c4);
    }
    if (tid < 128) sBv[tid] = Bvb[(s * HNh + h) * Hh + tid];
    __syncthreads();

    float acc[4][8];
    #pragma unroll
    for (int ri = 0; ri < 4; ++ri)
        #pragma unroll
        for (int ci = 0; ci < 8; ++ci) acc[ri][ci] = 0.f;

    for (int j = 0; j < Hh; ++j) {
        float a[4];
        #pragma unroll
        for (int ri = 0; ri < 4; ++ri) a[ri] = sA[(ty * 4 + ri) * 132 + j];
        float4 w0 = *(const float4*)(sB + j * 132 + tx * 8);
        float4 w1 = *(const float4*)(sB + j * 132 + tx * 8 + 4);
        float w[8] = {w0.x, w0.y, w0.z, w0.w, w1.x, w1.y, w1.z, w1.w};
        #pragma unroll
        for (int ri = 0; ri < 4; ++ri)
            #pragma unroll
            for (int ci = 0; ci < 8; ++ci)
                acc[ri][ci] += a[ri] * w[ci];
    }
    #pragma unroll
    for (int ri = 0; ri < 4; ++ri) {
        float4 v0 = {acc[ri][0], acc[ri][1], acc[ri][2], acc[ri][3]};
        float4 v1 = {acc[ri][4], acc[ri][5], acc[ri][6], acc[ri][7]};
        float* dst = C + (size_t)(half * 64 + ty * 4 + ri) * Hh + tx * 8;
        *(float4*)(dst) = v0;
        *(float4*)(dst + 4) = v1;
    }
    #pragma unroll
    for (int ri = 0; ri < 4; ++ri) {
        float p = 0.f;
        #pragma unroll
        for (int jj = 0; jj < 8; ++jj)
            p += sA[(ty * 4 + ri) * 132 + tx * 8 + jj] * sBv[tx * 8 + jj];
        sPb[(ty * 4 + ri) * 16 + tx] = p;
    }
    __syncthreads();
    if (tid < 64) {
        float bsum = Abv[(km * HNh + h) * Hh + half * 64 + tid];
        #pragma unroll
        for (int j = 0; j < 16; ++j) bsum += sPb[tid * 16 + j];
        bcv[(s * HNh + h) * Hh + half * 64 + tid] = bsum;
    }
}

// ---------------------------------------------------------------------------
// Kernel 1: feat GEMM (tf32 mma, cp.async) — epilogue writes hi/lo planes
// ---------------------------------------------------------------------------
#define APLN 36
#define SMF_BYTES (2 * 256 * APLN * 4)

__global__ __launch_bounds__(256, 2) void k_feat(
    const int* __restrict__ nbr, const int* __restrict__ tgt,
    const float* __restrict__ fc_b)
{
    extern __shared__ __align__(16) float sAf[];
    __shared__ int sIdx[128];

    int m0 = blockIdx.x * 128;
    int n0 = blockIdx.y * 128;
    int s  = blockIdx.z;
    int tid = threadIdx.x;
    int warp = tid >> 5, L = tid & 31;
    int wm = warp & 3, wn = warp >> 2;
    int g = L >> 2, c4 = L & 3;

    if (tid < 128) {
        int r = m0 + tid;
        sIdx[tid] = (r < RR) ? nbr[s * RR + r] : tgt[r - RR];
    }
    __syncthreads();

    uint sbase = smem_u32(sAf);

    int srow[4], skq[4];
    uint dsthi[4], dstlo[4];
    #pragma unroll
    for (int u = 0; u < 4; ++u) {
        int idx = tid + 256 * u;
        int row = idx >> 3, kq = idx & 7;
        srow[u] = row; skq[u] = kq;
        int q = kq >> 1;
        int mt = row >> 4;
        int r = row & 15;
        int reg = ((r >> 3) & 1) | ((kq & 1) << 1);
        int gg = r & 7;
        int p0 = ((q * 8 + mt) * 2 + 0) * 4 + reg;
        int p1 = ((q * 8 + mt) * 2 + 1) * 4 + reg;
        dsthi[u] = (uint)((p0 * APLN + 4 * gg) * 4);
        dstlo[u] = (uint)((p1 * APLN + 4 * gg) * 4);
    }

    float acc[2][8][4];
    #pragma unroll
    for (int mi = 0; mi < 2; ++mi)
        #pragma unroll
        for (int jl = 0; jl < 8; ++jl)
            #pragma unroll
            for (int e = 0; e < 4; ++e) acc[mi][jl][e] = 0.f;

    const float* wf = g_wfrag + (size_t)s * 32 * 64 * 32 * 4;
    int jbase = (n0 >> 3) + wn * 8;

    {
        #pragma unroll
        for (int u = 0; u < 4; ++u) {
            size_t o = (size_t)sIdx[srow[u]] * IN_ + 4 * skq[u];
            cp_async16(sbase + dsthi[u], g_xhi + o);
            cp_async16(sbase + dstlo[u], g_xlo + o);
        }
        CP_COMMIT();
    }

    for (int ch = 0; ch < 8; ++ch) {
        __syncthreads();
        if (ch < 7) {
            uint boff = ((ch + 1) & 1) ? (uint)(256 * APLN * 4) : 0u;
            int kadd = (ch + 1) * 32;
            #pragma unroll
            for (int u = 0; u < 4; ++u) {
                size_t o = (size_t)sIdx[srow[u]] * IN_ + kadd + 4 * skq[u];
                cp_async16(sbase + boff + dsthi[u], g_xhi + o);
                cp_async16(sbase + boff + dstlo[u], g_xlo + o);
            }
            CP_COMMIT();
            CP_WAIT1();
        } else {
            CP_WAIT0();
        }
        __syncthreads();

        const float* buf = sAf + ((ch & 1) ? 256 * APLN : 0);
        #pragma unroll
        for (int q = 0; q < 4; ++q) {
            int k8 = ch * 4 + q;
            float4 bc[8];
            #pragma unroll
            for (int jl = 0; jl < 8; ++jl)
                bc[jl] = *(const float4*)(wf + ((size_t)(k8 * 64 + jbase + jl) * 32 + L) * 4);
            uint afh[2][4], afl[2][4];
            #pragma unroll
            for (int mi = 0; mi < 2; ++mi) {
                int mt = 2 * wm + mi;
                int pb = ((q * 8 + mt) * 2) * 4;
                #pragma unroll
                for (int rg = 0; rg < 4; ++rg) {
                    afh[mi][rg] = __float_as_uint(buf[(pb + rg) * APLN + L]);
                    afl[mi][rg] = __float_as_uint(buf[(pb + 4 + rg) * APLN + L]);
                }
            }
            #pragma unroll
            for (int mi = 0; mi < 2; ++mi)
                #pragma unroll
                for (int jl = 0; jl < 8; ++jl) {
                    uint bh0 = __float_as_uint(bc[jl].x), bh1 = __float_as_uint(bc[jl].y);
                    uint bl0 = __float_as_uint(bc[jl].z), bl1 = __float_as_uint(bc[jl].w);
                    mma_tf32(acc[mi][jl], afh[mi], bh0, bh1);
                    mma_tf32(acc[mi][jl], afh[mi], bl0, bl1);
                    mma_tf32(acc[mi][jl], afl[mi], bh0, bh1);
                }
        }
    }

    #pragma unroll
    for (int mi = 0; mi < 2; ++mi) {
        int rbase = 32 * wm + 16 * mi + g;
        #pragma unroll
        for (int jl = 0; jl < 8; ++jl) {
            int col = 64 * wn + 8 * jl + 2 * c4;
            float b0v = fc_b[s * 512 + n0 + col];
            float b1v = fc_b[s * 512 + n0 + col + 1];
            float va = lrelu(acc[mi][jl][0] + b0v);
            float vb2 = lrelu(acc[mi][jl][1] + b1v);
            float vc = lrelu(acc[mi][jl][2] + b0v);
            float vd = lrelu(acc[mi][jl][3] + b1v);
            if (m0 < RR) {
                int r = m0 + rbase;
                size_t o0 = ((size_t)s * RR + r) * Dd + n0 + col;
                size_t o1 = ((size_t)s * RR + r + 8) * Dd + n0 + col;
                float ha = cvt_tf32(va), hb = cvt_tf32(vb2);
                float hc = cvt_tf32(vc), hd = cvt_tf32(vd);
                float2 h0 = {ha, hb}, h1 = {hc, hd};
                float2 l0 = {cvt_tf32(va - ha), cvt_tf32(vb2 - hb)};
                float2 l1 = {cvt_tf32(vc - hc), cvt_tf32(vd - hd)};
                *(float2*)(g_fhi + o0) = h0;
                *(float2*)(g_flo + o0) = l0;
                *(float2*)(g_fhi + o1) = h1;
                *(float2*)(g_flo + o1) = l1;
            } else {
                int h = n0 >> 7;
                int b = m0 - RR + rbase;
                float2 v0 = {va, vb2}, v1 = {vc, vd};
                *(float2*)(g_xsh + ((size_t)(s * HNh + h) * Bb + b) * Hh + col) = v0;
                *(float2*)(g_xsh + ((size_t)(s * HNh + h) * Bb + b + 8) * Hh + col) = v1;
            }
        }
    }
}

// ---------------------------------------------------------------------------
// shared FFMA2 64x128x128 micro-kernel (k_qkv, k_sem_score)
// ---------------------------------------------------------------------------
#define SW_STR 132
#define T_STR 132
#define SM_QKV 19008

__device__ __forceinline__ void gemm128_f2(
    const float* __restrict__ sIn, const float* __restrict__ Wg,
    float* __restrict__ sWbuf, ull acc2[4][4],
    int tid, int tx, int ty)
{
    int kcp = (tid & 3) << 2;
    int nA = tid >> 2, nB = nA + 64;
    #pragma unroll
    for (int ri = 0; ri < 4; ++ri)
        #pragma unroll
        for (int j = 0; j < 4; ++j) acc2[ri][j] = 0ull;

    float4 p0 = *(const float4*)(Wg + nA * Hh + kcp);
    float4 p1 = *(const float4*)(Wg + nB * Hh + kcp);
    for (int c = 0; c < 8; ++c) {
        __syncthreads();
        sWbuf[(kcp + 0) * T_STR + nA] = p0.x; sWbuf[(kcp + 1) * T_STR + nA] = p0.y;
        sWbuf[(kcp + 2) * T_STR + nA] = p0.z; sWbuf[(kcp + 3) * T_STR + nA] = p0.w;
        sWbuf[(kcp + 0) * T_STR + nB] = p1.x; sWbuf[(kcp + 1) * T_STR + nB] = p1.y;
        sWbuf[(kcp + 2) * T_STR + nB] = p1.z; sWbuf[(kcp + 3) * T_STR + nB] = p1.w;
        __syncthreads();
        if (c < 7) {
            int k0n = (c + 1) * 16 + kcp;
            p0 = *(const float4*)(Wg + nA * Hh + k0n);
            p1 = *(const float4*)(Wg + nB * Hh + k0n);
        }
        int k0 = c * 16;
        #pragma unroll
        for (int kk = 0; kk < 16; ++kk) {
            ull a2[4], w2[4];
            #pragma unroll
            for (int ri = 0; ri < 4; ++ri)
                a2[ri] = pack2b(sIn[(ty * 4 + ri) * T_STR + k0 + kk]);
            #pragma unroll
            for (int j = 0; j < 4; ++j)
                w2[j] = *(const ull*)(sWbuf + kk * T_STR + tx * 8 + 2 * j);
            #pragma unroll
            for (int ri = 0; ri < 4; ++ri)
                #pragma unroll
                for (int j = 0; j < 4; ++j)
                    ffma2(acc2[ri][j], a2[ri], w2[j]);
        }
    }
}

// ---------------------------------------------------------------------------
// Kernel 2: qkv chain (unchanged)
// ---------------------------------------------------------------------------
__global__ __launch_bounds__(256, 2) void k_qkv(
    const float* __restrict__ wc2, const float* __restrict__ bc2,
    const float* __restrict__ aW)
{
    extern __shared__ __align__(16) float sm[];
    float* sA = sm;
    float* sQ = sm + 8448;
    float* sW = sm + 16896;

    int sh = blockIdx.y;
    int s = sh >> 2, h = sh & 3;
    int km = (s >= 2) ? 1 : 0;
    int b0 = blockIdx.x * 64;
    int tid = threadIdx.x;
    int tx = tid & 15, ty = tid >> 4;

    int who = (s * HNh + h) * Hh;
    int aho = (km * HNh + h) * Hh;
    const float* Wc = wc2 + (size_t)who * Hh;
    const float* Ww = aW + (size_t)aho * Hh;

    #pragma unroll
    for (int i = 0; i < 8; ++i) {
        int lid = tid + i * 256;
        int row = lid >> 5, c4 = (lid & 31) << 2;
        float4 v = *(const float4*)(g_xsh + ((size_t)(s * HNh + h) * Bb + b0 + row) * Hh + c4);
        *(float4*)(sA + row * T_STR + c4) = v;
    }

    ull acc2[4][4];

    gemm128_f2(sA, Wc, sW, acc2, tid, tx, ty);
    {
        float4 b0v = *(const float4*)(bc2 + who + tx * 8);
        float4 b1v = *(const float4*)(bc2 + who + tx * 8 + 4);
        float bb[8] = {b0v.x, b0v.y, b0v.z, b0v.w, b1v.x, b1v.y, b1v.z, b1v.w};
        #pragma unroll
        for (int ri = 0; ri < 4; ++ri) {
            float vv[8];
            #pragma unroll
            for (int j = 0; j < 4; ++j) {
                float2 t = unpack2(acc2[ri][j]);
                vv[2 * j] = lrelu(t.x + bb[2 * j]);
                vv[2 * j + 1] = lrelu(t.y + bb[2 * j + 1]);
            }
            float4 v0 = {vv[0], vv[1], vv[2], vv[3]};
            float4 v1 = {vv[4], vv[5], vv[6], vv[7]};
            *(float4*)(sQ + (ty * 4 + ri) * T_STR + tx * 8) = v0;
            *(float4*)(sQ + (ty * 4 + ri) * T_STR + tx * 8 + 4) = v1;
        }
    }

    gemm128_f2(sQ, Ww, sW, acc2, tid, tx, ty);
    #pragma unroll
    for (int ri = 0; ri < 4; ++ri) {
        int b = b0 + ty * 4 + ri;
        float* dst = g_wh2 + ((size_t)(s * HNh + h) * Bb + b) * Hh + tx * 8;
        float vv[8];
        #pragma unroll
        for (int j = 0; j < 4; ++j) {
            float2 t = unpack2(acc2[ri][j]);
            vv[2 * j] = t.x; vv[2 * j + 1] = t.y;
        }
        float4 v0 = {vv[0], vv[1], vv[2], vv[3]};
        float4 v1 = {vv[4], vv[5], vv[6], vv[7]};
        *(float4*)(dst) = v0;
        *(float4*)(dst + 4) = v1;
    }
}

// ---------------------------------------------------------------------------
// Kernel 3: fused attention via tf32 mma (3xTF32), dual GEMM + reg epilogue.
// Tile M=64 (4 b-groups), N=128, K=128. 8 warps: wm=warp&1 (m32), wn=warp>>1 (n32).
// A: feat hi/lo planes, cp.async double-buffered K-chunks of 32.
// ---------------------------------------------------------------------------
#define SMA_BYTES (2 * 128 * APLN * 4)

__global__ __launch_bounds__(256, 2) void k_attn(
    const float* __restrict__ bc1, const float* __restrict__ v_b)
{
    extern __shared__ __align__(16) float sAf[];
    __shared__ float sW2[512];
    __shared__ float sBc[128];
    __shared__ float sVb[128];
    __shared__ float sAttP[256];
    __shared__ float sE[64];
    __shared__ float sH[512];

    int sh = blockIdx.y;
    int s = sh >> 2, h = sh & 3;
    int r0 = blockIdx.x * 64;
    int b0 = r0 >> 4;
    int tid = threadIdx.x;
    int warp = tid >> 5, L = tid & 31;
    int wm = warp & 1, wn = warp >> 1;
    int g = L >> 2, c4 = L & 3;
    int who = (s * HNh + h) * Hh;

    #pragma unroll
    for (int i = 0; i < 2; ++i) {
        int idx = tid + 256 * i;
        int bg = idx >> 7, o = idx & 127;
        sW2[idx] = g_wh2[((size_t)(s * HNh + h) * Bb + b0 + bg) * Hh + o];
    }
    if (tid < 128) { sBc[tid] = bc1[who + tid]; sVb[tid] = v_b[who + tid]; }

    uint sbase = smem_u32(sAf);

    // staging slots: 64 rows x 8 kq = 512 slots, 2 per thread
    int srow[2], skq[2];
    uint dsthi[2], dstlo[2];
    #pragma unroll
    for (int u = 0; u < 2; ++u) {
        int idx = tid + 256 * u;
        int row = idx >> 3, kq = idx & 7;
        srow[u] = row; skq[u] = kq;
        int q = kq >> 1;
        int mt = row >> 4;
        int rr = row & 15;
        int reg = ((rr >> 3) & 1) | ((kq & 1) << 1);
        int gg = rr & 7;
        int p0 = ((q * 4 + mt) * 2 + 0) * 4 + reg;
        int p1 = ((q * 4 + mt) * 2 + 1) * 4 + reg;
        dsthi[u] = (uint)((p0 * APLN + 4 * gg) * 4);
        dstlo[u] = (uint)((p1 * APLN + 4 * gg) * 4);
    }

    const float* Ahi = g_fhi + ((size_t)s * RR + r0) * Dd + h * Hh;
    const float* Alo = g_flo + ((size_t)s * RR + r0) * Dd + h * Hh;
    const float* wfb = g_wfa + (size_t)sh * (2 * 16 * 16 * 32 * 4);

    float ak[2][4][4], av_[2][4][4];
    #pragma unroll
    for (int mi = 0; mi < 2; ++mi)
        #pragma unroll
        for (int jl = 0; jl < 4; ++jl)
            #pragma unroll
            for (int e = 0; e < 4; ++e) { ak[mi][jl][e] = 0.f; av_[mi][jl][e] = 0.f; }

    // prologue: stage chunk 0
    {
        #pragma unroll
        for (int u = 0; u < 2; ++u) {
            size_t o = (size_t)srow[u] * Dd + 4 * skq[u];
            cp_async16(sbase + dsthi[u], Ahi + o);
            cp_async16(sbase + dstlo[u], Alo + o);
        }
        CP_COMMIT();
    }

    for (int ch = 0; ch < 4; ++ch) {
        __syncthreads();
        if (ch < 3) {
            uint boff = ((ch + 1) & 1) ? (uint)(128 * APLN * 4) : 0u;
            int kadd = (ch + 1) * 32;
            #pragma unroll
            for (int u = 0; u < 2; ++u) {
                size_t o = (size_t)srow[u] * Dd + kadd + 4 * skq[u];
                cp_async16(sbase + boff + dsthi[u], Ahi + o);
                cp_async16(sbase + boff + dstlo[u], Alo + o);
            }
            CP_COMMIT();
            CP_WAIT1();
        } else {
            CP_WAIT0();
        }
        __syncthreads();

        const float* buf = sAf + ((ch & 1) ? 128 * APLN : 0);
        #pragma unroll
        for (int q = 0; q < 4; ++q) {
            int k8 = ch * 4 + q;
            float4 bk[4], bv[4];
            #pragma unroll
            for (int jl = 0; jl < 4; ++jl) {
                int j = wn * 4 + jl;
                bk[jl] = *(const float4*)(wfb + (size_t)(((0 * 16 + k8) * 16 + j) * 32 + L) * 4);
                bv[jl] = *(const float4*)(wfb + (size_t)(((1 * 16 + k8) * 16 + j) * 32 + L) * 4);
            }
            uint afh[2][4], afl[2][4];
            #pragma unroll
            for (int mi = 0; mi < 2; ++mi) {
                int mt = 2 * wm + mi;
                int pb = ((q * 4 + mt) * 2) * 4;
                #pragma unroll
                for (int rg = 0; rg < 4; ++rg) {
                    afh[mi][rg] = __float_as_uint(buf[(pb + rg) * APLN + L]);
                    afl[mi][rg] = __float_as_uint(buf[(pb + 4 + rg) * APLN + L]);
                }
            }
            #pragma unroll
            for (int mi = 0; mi < 2; ++mi)
                #pragma unroll
                for (int jl = 0; jl < 4; ++jl) {
                    uint kh0 = __float_as_uint(bk[jl].x), kh1 = __float_as_uint(bk[jl].y);
                    uint kl0 = __float_as_uint(bk[jl].z), kl1 = __float_as_uint(bk[jl].w);
                    mma_tf32(ak[mi][jl], afh[mi], kh0, kh1);
                    mma_tf32(ak[mi][jl], afh[mi], kl0, kl1);
                    mma_tf32(ak[mi][jl], afl[mi], kh0, kh1);
                    uint vh0 = __float_as_uint(bv[jl].x), vh1 = __float_as_uint(bv[jl].y);
                    uint vl0 = __float_as_uint(bv[jl].z), vl1 = __float_as_uint(bv[jl].w);
                    mma_tf32(av_[mi][jl], afh[mi], vh0, vh1);
                    mma_tf32(av_[mi][jl], afh[mi], vl0, vl1);
                    mma_tf32(av_[mi][jl], afl[mi], vh0, vh1);
                }
        }
    }

    // epilogue 1: att partials = sum_col lrelu(h1acc + bc1) * wh2
    #pragma unroll
    for (int mi = 0; mi < 2; ++mi) {
        int mt = 2 * wm + mi;
        float pg = 0.f, pg8 = 0.f;
        #pragma unroll
        for (int jl = 0; jl < 4; ++jl) {
            int col0 = wn * 32 + jl * 8 + 2 * c4;
            float bcv0 = sBc[col0], bcv1 = sBc[col0 + 1];
            float w20 = sW2[mt * 128 + col0], w21 = sW2[mt * 128 + col0 + 1];
            pg  += lrelu(ak[mi][jl][0] + bcv0) * w20 + lrelu(ak[mi][jl][1] + bcv1) * w21;
            pg8 += lrelu(ak[mi][jl][2] + bcv0) * w20 + lrelu(ak[mi][jl][3] + bcv1) * w21;
        }
        pg  += __shfl_xor_sync(0xffffffffu, pg, 1);
        pg  += __shfl_xor_sync(0xffffffffu, pg, 2);
        pg8 += __shfl_xor_sync(0xffffffffu, pg8, 1);
        pg8 += __shfl_xor_sync(0xffffffffu, pg8, 2);
        if (c4 == 0) {
            sAttP[(mt * 16 + g) * 4 + wn] = pg;
            sAttP[(mt * 16 + g + 8) * 4 + wn] = pg8;
        }
    }
    __syncthreads();
    if (tid < 64) {
        float a = sAttP[tid * 4] + sAttP[tid * 4 + 1] + sAttP[tid * 4 + 2] + sAttP[tid * 4 + 3];
        sE[tid] = a;   // temp att
    }
    __syncthreads();
    if (tid < 4) {
        float mx = -1e30f;
        #pragma unroll
        for (int m = 0; m < Mm; ++m) mx = fmaxf(mx, sE[tid * 16 + m]);
        float ee[Mm], sum = 0.f;
        #pragma unroll
        for (int m = 0; m < Mm; ++m) { ee[m] = expf(sE[tid * 16 + m] - mx); sum += ee[m]; }
        float inv = 1.f / sum;
        #pragma unroll
        for (int m = 0; m < Mm; ++m) sAttP[tid * 16 + m] = ee[m] * inv;  // sAttP[0..63] = e
    }
    __syncthreads();

    // epilogue 2: h[bg][col] = sum_rows lrelu(vh * e)
    #pragma unroll
    for (int mi = 0; mi < 2; ++mi) {
        int mt = 2 * wm + mi;
        float eg = sAttP[mt * 16 + g];
        float eg8 = sAttP[mt * 16 + g + 8];
        float hc[8];
        #pragma unroll
        for (int jl = 0; jl < 4; ++jl) {
            int col0 = wn * 32 + jl * 8 + 2 * c4;
            float vb0 = sVb[col0], vb1 = sVb[col0 + 1];
            hc[jl * 2]     = lrelu((av_[mi][jl][0] + vb0) * eg) + lrelu((av_[mi][jl][2] + vb0) * eg8);
            hc[jl * 2 + 1] = lrelu((av_[mi][jl][1] + vb1) * eg) + lrelu((av_[mi][jl][3] + vb1) * eg8);
        }
        #pragma unroll
        for (int off = 4; off <= 16; off <<= 1)
            #pragma unroll
            for (int j8 = 0; j8 < 8; ++j8)
                hc[j8] += __shfl_xor_sync(0xffffffffu, hc[j8], off);
        if (g == 0) {
            #pragma unroll
            for (int jl = 0; jl < 4; ++jl) {
                int col0 = wn * 32 + jl * 8 + 2 * c4;
                sH[mt * 128 + col0] = hc[jl * 2];
                sH[mt * 128 + col0 + 1] = hc[jl * 2 + 1];
            }
        }
    }
    __syncthreads();
    #pragma unroll
    for (int i = 0; i < 2; ++i) {
        int idx = tid + 256 * i;
        int bg = idx >> 7, o = idx & 127;
        int b = b0 + bg;
        float xs = g_xsh[((size_t)(s * HNh + h) * Bb + b) * Hh + o];
        g_out[((size_t)s * Bb + b) * Dd + h * Hh + o] = 0.5f * (xs + sH[idx]);
    }
}

// ---------------------------------------------------------------------------
// Semantic attention (unchanged)
// ---------------------------------------------------------------------------
#define SZ_STR 20

__global__ __launch_bounds__(256) void k_sem_score(
    const float* __restrict__ zbase,
    const float* __restrict__ p1w, const float* __restrict__ p1b,
    const float* __restrict__ p2w,
    float* __restrict__ sc,
    int mode)
{
    __shared__ __align__(16) float sZ[64 * SZ_STR];
    __shared__ __align__(16) float sW[16 * SW_STR];
    __shared__ float sPart[64 * 16];

    int gy = blockIdx.y;
    int b0 = blockIdx.x * 64;
    int tid = threadIdx.x;
    int tx = tid & 15, ty = tid >> 4;

    int wsel, outbase;
    const float* zrow0;
    size_t zstride;
    if (mode == 0) {
        int s = gy;
        wsel = (s >= 2) ? 1 : 0;
        zrow0 = zbase + ((size_t)s * Bb + b0) * Dd;
        zstride = Dd;
        outbase = s * Bb + b0;
    } else {
        int k2 = gy;
        wsel = 0;
        zrow0 = zbase + ((size_t)b0 * 2 + k2) * Dd;
        zstride = 2 * Dd;
        outbase = k2 * Bb + b0;
    }
    const float* Wp = p1w + (size_t)wsel * Hh * Dd;
    const float* bp = p1b + wsel * Hh;
    const float* p2 = p2w + wsel * Hh;

    int kcp = (tid & 3) << 2;
    int rZ = tid >> 2;
    int nA = tid >> 2, nB = nA + 64;

    ull acc2[4][4];
    #pragma unroll
    for (int ri = 0; ri < 4; ++ri)
        #pragma unroll
        for (int j = 0; j < 4; ++j) acc2[ri][j] = 0ull;

    float4 pz = *(const float4*)(zrow0 + (size_t)rZ * zstride + kcp);
    float4 pw0 = *(const float4*)(Wp + (size_t)nA * Dd + kcp);
    float4 pw1 = *(const float4*)(Wp + (size_t)nB * Dd + kcp);

    for (int c = 0; c < 32; ++c) {
        __syncthreads();
        *(float4*)(sZ + rZ * SZ_STR + kcp) = pz;
        sW[(kcp + 0) * SW_STR + nA] = pw0.x; sW[(kcp + 1) * SW_STR + nA] = pw0.y;
        sW[(kcp + 2) * SW_STR + nA] = pw0.z; sW[(kcp + 3) * SW_STR + nA] = pw0.w;
        sW[(kcp + 0) * SW_STR + nB] = pw1.x; sW[(kcp + 1) * SW_STR + nB] = pw1.y;
        sW[(kcp + 2) * SW_STR + nB] = pw1.z; sW[(kcp + 3) * SW_STR + nB] = pw1.w;
        __syncthreads();
        if (c < 31) {
            int k0n = (c + 1) * 16 + kcp;
            pz = *(const float4*)(zrow0 + (size_t)rZ * zstride + k0n);
            pw0 = *(const float4*)(Wp + (size_t)nA * Dd + k0n);
            pw1 = *(const float4*)(Wp + (size_t)nB * Dd + k0n);
        }
        #pragma unroll
        for (int kk = 0; kk < 16; ++kk) {
            ull a2[4], w2[4];
            #pragma unroll
            for (int ri = 0; ri < 4; ++ri)
                a2[ri] = pack2b(sZ[(ty * 4 + ri) * SZ_STR + kk]);
            #pragma unroll
            for (int j = 0; j < 4; ++j)
                w2[j] = *(const ull*)(sW + kk * SW_STR + tx * 8 + 2 * j);
            #pragma unroll
            for (int ri = 0; ri < 4; ++ri)
                #pragma unroll
                for (int j = 0; j < 4; ++j)
                    ffma2(acc2[ri][j], a2[ri], w2[j]);
        }
    }
    {
        float bb[8], pp[8];
        #pragma unroll
        for (int ci = 0; ci < 8; ++ci) {
            bb[ci] = bp[tx * 8 + ci];
            pp[ci] = p2[tx * 8 + ci];
        }
        #pragma unroll
        for (int ri = 0; ri < 4; ++ri) {
            float p = 0.f;
            #pragma unroll
            for (int j = 0; j < 4; ++j) {
                float2 t = unpack2(acc2[ri][j]);
                p += tanhf(t.x + bb[2 * j]) * pp[2 * j];
                p += tanhf(t.y + bb[2 * j + 1]) * pp[2 * j + 1];
            }
            sPart[(ty * 4 + ri) * 16 + tx] = p;
        }
    }
    __syncthreads();
    if (tid < 64) {
        float a = 0.f;
        #pragma unroll
        for (int j = 0; j < 16; ++j) a += sPart[tid * 16 + j];
        sc[outbase + tid] = a;
    }
}

__global__ __launch_bounds__(256) void k_sem_comb1()
{
    int b = blockIdx.x;
    int tid = threadIdx.x;
    float s0 = g_sc1[0 * Bb + b], s1 = g_sc1[1 * Bb + b];
    float s2 = g_sc1[2 * Bb + b], s3 = g_sc1[3 * Bb + b], s4 = g_sc1[4 * Bb + b];
    float mx0 = fmaxf(s0, s1);
    float e0 = expf(s0 - mx0), e1 = expf(s1 - mx0);
    float i0 = 1.f / (e0 + e1);
    float b00 = e0 * i0, b01 = e1 * i0;
    float mx1 = fmaxf(fmaxf(s2, s3), s4);
    float f0 = expf(s2 - mx1), f1 = expf(s3 - mx1), f2 = expf(s4 - mx1);
    float i1 = 1.f / (f0 + f1 + f2);
    float b10 = f0 * i1, b11 = f1 * i1, b12 = f2 * i1;
    for (int d = tid; d < Dd; d += 256) {
        float z0 = b00 * g_out[(0 * Bb + b) * Dd + d] + b01 * g_out[(1 * Bb + b) * Dd + d];
        float z1 = b10 * g_out[(2 * Bb + b) * Dd + d] + b11 * g_out[(3 * Bb + b) * Dd + d]
                 + b12 * g_out[(4 * Bb + b) * Dd + d];
        g_mp[(b * 2 + 0) * Dd + d] = z0;
        g_mp[(b * 2 + 1) * Dd + d] = z1;
    }
}

__global__ __launch_bounds__(256) void k_sem_comb2(float* __restrict__ out)
{
    int b = blockIdx.x;
    int tid = threadIdx.x;
    float s0 = g_sc2[b], s1 = g_sc2[Bb + b];
    float mx = fmaxf(s0, s1);
    float e0 = expf(s0 - mx), e1 = expf(s1 - mx);
    float inv = 1.f / (e0 + e1);
    float be0 = e0 * inv, be1 = e1 * inv;
    for (int d = tid; d < Dd; d += 256)
        out[(size_t)b * Dd + d] = be0 * g_mp[(b * 2 + 0) * Dd + d]
                                + be1 * g_mp[(b * 2 + 1) * Dd + d];
}

// ---------------------------------------------------------------------------
extern "C" void kernel_launch(void* const* d_in, const int* in_sizes, int n_in,
                              void* d_out, int out_size)
{
    const float* x    = (const float*)d_in[0];
    const int*   tgt  = (const int*)d_in[1];
    const int*   nbr  = (const int*)d_in[2];
    const float* fc_w = (const float*)d_in[3];
    const float* fc_b = (const float*)d_in[4];
    const float* q_w  = (const float*)d_in[5];
    const float* q_b  = (const float*)d_in[6];
    const float* k_w  = (const float*)d_in[7];
    const float* k_b  = (const float*)d_in[8];
    const float* v_w  = (const float*)d_in[9];
    const float* v_b  = (const float*)d_in[10];
    const float* aW   = (const float*)d_in[11];
    const float* a1w  = (const float*)d_in[12];
    const float* a1b  = (const float*)d_in[13];
    const float* a2w  = (const float*)d_in[14];
    const float* a2b  = (const float*)d_in[15];
    const float* ip1w = (const float*)d_in[16];
    const float* ip1b = (const float*)d_in[17];
    const float* ip2w = (const float*)d_in[18];
    const float* bp1w = (const float*)d_in[19];
    const float* bp1b = (const float*)d_in[20];
    const float* bp2w = (const float*)d_in[21];
    float* out = (float*)d_out;

    (void)in_sizes; (void)n_in; (void)out_size;

    static int configured = 0;
    if (!configured) {
        cudaFuncSetAttribute(k_attn, cudaFuncAttributeMaxDynamicSharedMemorySize,
                             SMA_BYTES);
        cudaFuncSetAttribute(k_qkv, cudaFuncAttributeMaxDynamicSharedMemorySize,
                             SM_QKV * 4);
        cudaFuncSetAttribute(k_comb, cudaFuncAttributeMaxDynamicSharedMemorySize,
                             SM_COMB * 4);
        cudaFuncSetAttribute(k_feat, cudaFuncAttributeMaxDynamicSharedMemorySize,
                             SMF_BYTES);
        configured = 1;
    }

    float* d_gout;  cudaGetSymbolAddress((void**)&d_gout, g_out);
    float* d_gmp;   cudaGetSymbolAddress((void**)&d_gmp, g_mp);
    float* d_sc1;   cudaGetSymbolAddress((void**)&d_sc1, g_sc1);
    float* d_sc2;   cudaGetSymbolAddress((void**)&d_sc2, g_sc2);
    float* d_wc2;   cudaGetSymbolAddress((void**)&d_wc2, g_wc2);
    float* d_bc1;   cudaGetSymbolAddress((void**)&d_bc1, g_bc1);
    float* d_bc2;   cudaGetSymbolAddress((void**)&d_bc2, g_bc2);

    k_xconv<<<(Ntot * IN_ / 4) / 256, 256>>>(x);
    k_wconv<<<(Ss * 32 * 64 * 32) / 256, 256>>>(fc_w);
    k_comb<<<dim3(2, 20, 2), 256, SM_COMB * 4>>>(a1w, a1b, k_w, k_b,
                                                 a2w, a2b, q_w, q_b);
    k_wfa<<<(20 * 2 * 16 * 16 * 32) / 256, 256>>>(v_w);
    k_feat<<<dim3(RTOT / 128, 4, Ss), 256, SMF_BYTES>>>(nbr, tgt, fc_b);
    k_qkv<<<dim3(Bb / 64, Ss * HNh), 256, SM_QKV * 4>>>(d_wc2, d_bc2, aW);
    k_attn<<<dim3(RR / 64, Ss * HNh), 256, SMA_BYTES>>>(d_bc1, v_b);
    k_sem_score<<<dim3(Bb / 64, Ss), 256>>>(d_gout, ip1w, ip1b, ip2w, d_sc1, 0);
    k_sem_comb1<<<Bb, 256>>>();
    k_sem_score<<<dim3(Bb / 64, 2), 256>>>(d_gmp, bp1w, bp1b, bp2w, d_sc2, 1);
    k_sem_comb2<<<Bb, 256>>>(out);
}